// round 1
// baseline (speedup 1.0000x reference)
#include <cuda_runtime.h>
#include <math.h>

// ---------------- problem constants ----------------
constexpr int Bb   = 2;
constexpr int SEQN = 2048;
constexpr int DIM  = 512;
constexpr int NH   = 4;
constexpr int DH   = 128;
constexpr int CH   = 64;
constexpr int NC   = 32;       // SEQN / CH
constexpr int DHID = 512;      // 4 * DH
constexpr int BH   = 8;        // Bb * NH
constexpr int TOK  = Bb * SEQN;      // 4096
constexpr int RWS  = BH * SEQN;      // 16384 (all tokens x heads)
constexpr int NCHUNK = BH * NC;      // 256

// ---------------- device scratch (no allocation allowed) ----------------
__device__ float g_xs[TOK * DIM];
__device__ float g_xr[TOK * DIM];
__device__ float g_K[RWS * DH];
__device__ float g_V[RWS * DH];
__device__ float g_Q[RWS * DH];
__device__ float g_lr[TOK * NH];
__device__ float g_gate[TOK * NH];
__device__ float g_beta[Bb * NC * NH];
__device__ float g_alpha[Bb * NC * NH];
__device__ float g_Hs[RWS * DH];
__device__ float g_rsK[RWS];
__device__ float g_A1[RWS * DHID];
__device__ float g_GA[RWS * DHID];
__device__ float g_dA1[RWS * DHID];
__device__ float g_dY[RWS * DH];
__device__ float g_dH[RWS * DH];
__device__ float g_sw1[NCHUNK * DH * DHID];
__device__ float g_sw2[NCHUNK * DHID * DH];
__device__ float g_sg[NCHUNK * DH];
__device__ float g_Wp1[NCHUNK * DH * DHID];
__device__ float g_Wp2[NCHUNK * DHID * DH];
__device__ float g_Gp[NCHUNK * DH];
__device__ float g_Hq[RWS * DH];
__device__ float g_R[TOK * DIM];
__device__ float g_w1T[DHID * DH];
__device__ float g_w2T[DH * DHID];

// ---------------- math helpers ----------------
__device__ __forceinline__ float sigmf(float x) { return 1.0f / (1.0f + expf(-x)); }
__device__ __forceinline__ float gelu_f(float x) {
    return 0.5f * x * (1.0f + erff(x * 0.70710678118654752f));
}
__device__ __forceinline__ float gelup_f(float x) {
    return 0.5f * (1.0f + erff(x * 0.70710678118654752f))
         + x * 0.3989422804014327f * expf(-0.5f * x * x);
}

// ---------------- rmsnorm over DIM=512 (xs, xr) ----------------
__global__ void rmsseq_kernel(const float* __restrict__ seq,
                              const float* __restrict__ gs,
                              const float* __restrict__ gr) {
    int t = blockIdx.x;
    int tid = threadIdx.x;           // 256 threads, 2 elems each
    float x0 = seq[t * DIM + tid];
    float x1 = seq[t * DIM + tid + 256];
    float ss = x0 * x0 + x1 * x1;
    for (int o = 16; o; o >>= 1) ss += __shfl_down_sync(0xffffffffu, ss, o);
    __shared__ float sm[8];
    if ((tid & 31) == 0) sm[tid >> 5] = ss;
    __syncthreads();
    float tot = 0.f;
#pragma unroll
    for (int i = 0; i < 8; i++) tot += sm[i];
    float rs = rsqrtf(tot * (1.0f / DIM) + 1e-6f);
    g_xs[t * DIM + tid]       = x0 * rs * gs[tid];
    g_xs[t * DIM + tid + 256] = x1 * rs * gs[tid + 256];
    g_xr[t * DIM + tid]       = x0 * rs * gr[tid];
    g_xr[t * DIM + tid + 256] = x1 * rs * gr[tid + 256];
}

// ---------------- lr + gate (sigmoid of small projections) ----------------
__global__ void lrgate_kernel(const float* __restrict__ Wa, const float* __restrict__ ba,
                              const float* __restrict__ Wg) {
    int t = blockIdx.x;
    int lane = threadIdx.x & 31;
    int h = threadIdx.x >> 5;        // 128 threads = 4 warps
    float accA = 0.f, accG = 0.f;
    for (int d = lane; d < DIM; d += 32) {
        accA += g_xs[t * DIM + d] * Wa[d * NH + h];
        accG += g_xr[t * DIM + d] * Wg[d * NH + h];
    }
    for (int o = 16; o; o >>= 1) {
        accA += __shfl_down_sync(0xffffffffu, accA, o);
        accG += __shfl_down_sync(0xffffffffu, accG, o);
    }
    if (lane == 0) {
        g_lr[t * NH + h]   = sigmf(accA + ba[h]);   // MAX_LR = 1
        g_gate[t * NH + h] = sigmf(accG);
    }
}

// ---------------- pooled chunk stats -> beta, alpha ----------------
__global__ void pool_kernel(const float* __restrict__ Wm, const float* __restrict__ Wd,
                            const float* __restrict__ bd) {
    int bc = blockIdx.x;             // b*NC + c
    int b = bc / NC, c = bc % NC;
    __shared__ float pooled[DIM];
    int tid = threadIdx.x;           // 512 threads
    int t0 = b * SEQN + c * CH;
    float s = 0.f;
    for (int i = 0; i < CH; i++) s += g_xs[(t0 + i) * DIM + tid];
    pooled[tid] = s * (1.0f / CH);
    __syncthreads();
    if (tid < 128) {
        int lane = tid & 31, h = tid >> 5;
        float am = 0.f, ad = 0.f;
        for (int d = lane; d < DIM; d += 32) {
            am += pooled[d] * Wm[d * NH + h];
            ad += pooled[d] * Wd[d * NH + h];
        }
        for (int o = 16; o; o >>= 1) {
            am += __shfl_down_sync(0xffffffffu, am, o);
            ad += __shfl_down_sync(0xffffffffu, ad, o);
        }
        if (lane == 0) {
            g_beta[bc * NH + h]  = sigmf(am);
            g_alpha[bc * NH + h] = 1.0f - sigmf(ad + bd[h]);
        }
    }
}

// ---------------- rmsnorm over DH=128 for K -> Hs (store rs) ----------------
__global__ void rmshead_kernel(const float* __restrict__ memg) {
    int r = blockIdx.x;
    int d = threadIdx.x;             // 128 threads
    float x = g_K[r * DH + d];
    float ss = x * x;
    for (int o = 16; o; o >>= 1) ss += __shfl_down_sync(0xffffffffu, ss, o);
    __shared__ float sm[4];
    if ((d & 31) == 0) sm[d >> 5] = ss;
    __syncthreads();
    float tot = sm[0] + sm[1] + sm[2] + sm[3];
    float rs = rsqrtf(tot * (1.0f / DH) + 1e-6f);
    g_Hs[r * DH + d] = x * rs * memg[d];
    if (d == 0) g_rsK[r] = rs;
}

// ---------------- rmsnorm for Q with per-chunk Gp -> Hq ----------------
__global__ void hq_kernel() {
    int r = blockIdx.x;
    int d = threadIdx.x;
    int bh = r / SEQN, n = r % SEQN, c = n / CH;
    float x = g_Q[r * DH + d];
    float ss = x * x;
    for (int o = 16; o; o >>= 1) ss += __shfl_down_sync(0xffffffffu, ss, o);
    __shared__ float sm[4];
    if ((d & 31) == 0) sm[d >> 5] = ss;
    __syncthreads();
    float tot = sm[0] + sm[1] + sm[2] + sm[3];
    float rs = rsqrtf(tot * (1.0f / DH) + 1e-6f);
    g_Hq[r * DH + d] = x * rs * g_Gp[(bh * NC + c) * DH + d];
}

// ---------------- small transpose ----------------
__global__ void transpose_kernel(const float* __restrict__ in, float* __restrict__ out,
                                 int R, int C) {
    int idx = blockIdx.x * 256 + threadIdx.x;
    if (idx < R * C) {
        int r = idx / C, c = idx % C;
        out[c * R + r] = in[idx];
    }
}

// ---------------- s_g reduction ----------------
__global__ void sg_kernel() {
    int z = blockIdx.x;              // bh*NC + c
    int d = threadIdx.x;             // 128
    int row0 = z * CH;
    float acc = 0.f;
    for (int i = 0; i < CH; i++) {
        int r = row0 + i;
        acc += g_dH[r * DH + d] * g_K[r * DH + d] * g_rsK[r];
    }
    g_sg[z * DH + d] = -acc;
}

// ---------------- momentum + decay scan, writes causal w_prev ----------------
__global__ void scan_kernel(const float* __restrict__ s, const float* __restrict__ init,
                            float* __restrict__ wprev, int sz) {
    int bh = blockIdx.y;
    int e = blockIdx.x * 256 + threadIdx.x;
    if (e >= sz) return;
    int b = bh / NH, h = bh % NH;
    float m = 0.f, w = init[e];
    wprev[(bh * NC + 0) * sz + e] = w;       // chunk 0 reads init params
    for (int t = 0; t < NC; t++) {
        float beta  = g_beta[(b * NC + t) * NH + h];
        float alpha = g_alpha[(b * NC + t) * NH + h];
        m = beta * m + s[(bh * NC + t) * sz + e];
        w = alpha * w + m;
        if (t < NC - 1) wprev[(bh * NC + t + 1) * sz + e] = w;
    }
}

// ---------------- generic 64x64-tile fp32 GEMM with epilogues ----------------
// EPI: 0 plain, 1 permute-to-head-major, 2 store A1 + gelu, 3 pred->dY,
//      4 *gelu'(A1), 6 gelu only (retrieval), 7 retrieval output (gated, permuted)
template <int EPI>
__global__ void __launch_bounds__(256) gemm64(
    const float* __restrict__ A, const float* __restrict__ Bm, float* __restrict__ C,
    int M, int Nn, int K, int lda, int ldb, int ldc,
    int sA, int sB, int sC,
    const float* __restrict__ x0, const float* __restrict__ x1,
    const float* __restrict__ x2, float* __restrict__ x3) {
    int z = blockIdx.z;
    A += (long)z * sA; Bm += (long)z * sB; C += (long)z * sC;
    __shared__ float As[16][65];
    __shared__ float Bs[16][65];
    int tid = threadIdx.x;
    int tx = tid & 15, ty = tid >> 4;
    int m0 = blockIdx.y * 64, n0 = blockIdx.x * 64;
    float acc[4][4] = {};
    for (int kb = 0; kb < K; kb += 16) {
#pragma unroll
        for (int l = 0; l < 4; l++) {
            int e = tid + l * 256;
            int kk = e & 15, m = e >> 4;
            As[kk][m] = A[(m0 + m) * lda + kb + kk];
        }
#pragma unroll
        for (int l = 0; l < 4; l++) {
            int e = tid + l * 256;
            int n = e & 63, kk = e >> 6;
            Bs[kk][n] = Bm[(kb + kk) * ldb + n0 + n];
        }
        __syncthreads();
#pragma unroll
        for (int kk = 0; kk < 16; kk++) {
            float a[4], b[4];
#pragma unroll
            for (int i = 0; i < 4; i++) a[i] = As[kk][ty * 4 + i];
#pragma unroll
            for (int j = 0; j < 4; j++) b[j] = Bs[kk][tx * 4 + j];
#pragma unroll
            for (int i = 0; i < 4; i++)
#pragma unroll
                for (int j = 0; j < 4; j++) acc[i][j] += a[i] * b[j];
        }
        __syncthreads();
    }
#pragma unroll
    for (int i = 0; i < 4; i++) {
#pragma unroll
        for (int j = 0; j < 4; j++) {
            int r = m0 + ty * 4 + i, c = n0 + tx * 4 + j;
            float v = acc[i][j];
            if (EPI == 0) {
                C[r * ldc + c] = v;
            } else if (EPI == 1) {
                // projection output permuted token-major -> head-major
                int b = r / SEQN, n = r % SEQN, h = c / DH, d = c % DH;
                C[(((b * NH + h) * SEQN) + n) * DH + d] = v;
            } else if (EPI == 2) {
                x3[r * ldc + c] = v;                 // A1
                C[r * ldc + c]  = gelu_f(v);         // GA
            } else if (EPI == 3) {
                // pred = GA@W2 + K ; dY = (2*lr/DH)*(pred - V)
                float pred = v + x0[r * DH + c];
                int bh = r / SEQN, n = r % SEQN;
                int b = bh / NH, h = bh % NH;
                float lr = x2[(b * SEQN + n) * NH + h];
                C[r * DH + c] = (2.0f / DH) * lr * (pred - x1[r * DH + c]);
            } else if (EPI == 4) {
                float a1 = x0[r * ldc + c];
                C[r * ldc + c] = v * gelup_f(a1);    // dA1 = dGA * gelu'(A1)
            } else if (EPI == 6) {
                C[r * ldc + c] = gelu_f(v);
            } else if (EPI == 7) {
                // y = GAq@Wp2 + q ; gated, write combined-head layout
                float y = v + x0[z * CH * DH + r * DH + c];
                int bh = z / NC, cc = z % NC;
                int n = cc * CH + r;
                int b = bh / NH, h = bh % NH;
                float gate = x1[(b * SEQN + n) * NH + h];
                x3[(b * SEQN + n) * DIM + h * DH + c] = y * gate;
            }
        }
    }
}

// ---------------- batched C = -A^T @ B (per-chunk surprise grads), K = 64 ----------------
__global__ void __launch_bounds__(256) gemm_atb(
    const float* __restrict__ A, const float* __restrict__ Bm, float* __restrict__ C,
    int M, int Nn, int lda, int ldb, int ldc, int sA, int sB, int sC) {
    int z = blockIdx.z;
    A += (long)z * sA; Bm += (long)z * sB; C += (long)z * sC;
    __shared__ float As[16][65];
    __shared__ float Bs[16][65];
    int tid = threadIdx.x;
    int tx = tid & 15, ty = tid >> 4;
    int m0 = blockIdx.y * 64, n0 = blockIdx.x * 64;
    float acc[4][4] = {};
    for (int kb = 0; kb < CH; kb += 16) {
#pragma unroll
        for (int l = 0; l < 4; l++) {
            int e = tid + l * 256;
            int m = e & 63, kk = e >> 6;
            As[kk][m] = A[(kb + kk) * lda + m0 + m];   // A^T tile (coalesced)
        }
#pragma unroll
        for (int l = 0; l < 4; l++) {
            int e = tid + l * 256;
            int n = e & 63, kk = e >> 6;
            Bs[kk][n] = Bm[(kb + kk) * ldb + n0 + n];
        }
        __syncthreads();
#pragma unroll
        for (int kk = 0; kk < 16; kk++) {
            float a[4], b[4];
#pragma unroll
            for (int i = 0; i < 4; i++) a[i] = As[kk][ty * 4 + i];
#pragma unroll
            for (int j = 0; j < 4; j++) b[j] = Bs[kk][tx * 4 + j];
#pragma unroll
            for (int i = 0; i < 4; i++)
#pragma unroll
                for (int j = 0; j < 4; j++) acc[i][j] += a[i] * b[j];
        }
        __syncthreads();
    }
#pragma unroll
    for (int i = 0; i < 4; i++)
#pragma unroll
        for (int j = 0; j < 4; j++) {
            int r = m0 + ty * 4 + i, c = n0 + tx * 4 + j;
            C[r * ldc + c] = -acc[i][j];
        }
}

// ---------------- launch ----------------
extern "C" void kernel_launch(void* const* d_in, const int* in_sizes, int n_in,
                              void* d_out, int out_size) {
    const float* seq   = (const float*)d_in[0];
    const float* gsto  = (const float*)d_in[1];
    const float* gret  = (const float*)d_in[2];
    const float* Wq    = (const float*)d_in[3];
    const float* Wk    = (const float*)d_in[4];
    const float* Wv    = (const float*)d_in[5];
    const float* Wa    = (const float*)d_in[6];
    const float* ba    = (const float*)d_in[7];
    const float* Wm    = (const float*)d_in[8];
    const float* Wd    = (const float*)d_in[9];
    const float* bd    = (const float*)d_in[10];
    const float* Wg    = (const float*)d_in[11];
    const float* Wc    = (const float*)d_in[12];
    const float* memg  = (const float*)d_in[13];
    const float* w1    = (const float*)d_in[14];
    const float* w2    = (const float*)d_in[15];
    float* out = (float*)d_out;

    float *p_xs, *p_xr, *p_K, *p_V, *p_Q, *p_lr, *p_gate, *p_Hs, *p_A1, *p_GA,
          *p_dA1, *p_dY, *p_dH, *p_sw1, *p_sw2, *p_sg, *p_Wp1, *p_Wp2, *p_Gp,
          *p_Hq, *p_R, *p_w1T, *p_w2T;
    cudaGetSymbolAddress((void**)&p_xs, g_xs);
    cudaGetSymbolAddress((void**)&p_xr, g_xr);
    cudaGetSymbolAddress((void**)&p_K, g_K);
    cudaGetSymbolAddress((void**)&p_V, g_V);
    cudaGetSymbolAddress((void**)&p_Q, g_Q);
    cudaGetSymbolAddress((void**)&p_lr, g_lr);
    cudaGetSymbolAddress((void**)&p_gate, g_gate);
    cudaGetSymbolAddress((void**)&p_Hs, g_Hs);
    cudaGetSymbolAddress((void**)&p_A1, g_A1);
    cudaGetSymbolAddress((void**)&p_GA, g_GA);
    cudaGetSymbolAddress((void**)&p_dA1, g_dA1);
    cudaGetSymbolAddress((void**)&p_dY, g_dY);
    cudaGetSymbolAddress((void**)&p_dH, g_dH);
    cudaGetSymbolAddress((void**)&p_sw1, g_sw1);
    cudaGetSymbolAddress((void**)&p_sw2, g_sw2);
    cudaGetSymbolAddress((void**)&p_sg, g_sg);
    cudaGetSymbolAddress((void**)&p_Wp1, g_Wp1);
    cudaGetSymbolAddress((void**)&p_Wp2, g_Wp2);
    cudaGetSymbolAddress((void**)&p_Gp, g_Gp);
    cudaGetSymbolAddress((void**)&p_Hq, g_Hq);
    cudaGetSymbolAddress((void**)&p_R, g_R);
    cudaGetSymbolAddress((void**)&p_w1T, g_w1T);
    cudaGetSymbolAddress((void**)&p_w2T, g_w2T);

    // 1) rmsnorm of seq -> xs, xr
    rmsseq_kernel<<<TOK, 256>>>(seq, gsto, gret);

    // 2) projections K,V (from xs), Q (from xr) -> head-major [bh, n, d]
    gemm64<1><<<dim3(8, TOK / 64), 256>>>(p_xs, Wk, p_K, TOK, DIM, DIM, DIM, DIM, 0,
                                          0, 0, 0, nullptr, nullptr, nullptr, nullptr);
    gemm64<1><<<dim3(8, TOK / 64), 256>>>(p_xs, Wv, p_V, TOK, DIM, DIM, DIM, DIM, 0,
                                          0, 0, 0, nullptr, nullptr, nullptr, nullptr);
    gemm64<1><<<dim3(8, TOK / 64), 256>>>(p_xr, Wq, p_Q, TOK, DIM, DIM, DIM, DIM, 0,
                                          0, 0, 0, nullptr, nullptr, nullptr, nullptr);

    // 3) lr, gate ; 4) pooled stats -> beta, alpha
    lrgate_kernel<<<TOK, 128>>>(Wa, ba, Wg);
    pool_kernel<<<Bb * NC, 512>>>(Wm, Wd, bd);

    // 5) Hs = rmsnorm(K, mem_g), save rs
    rmshead_kernel<<<RWS, 128>>>(memg);

    // 6) transposes of init weights
    transpose_kernel<<<(DH * DHID + 255) / 256, 256>>>(w1, p_w1T, DH, DHID);
    transpose_kernel<<<(DHID * DH + 255) / 256, 256>>>(w2, p_w2T, DHID, DH);

    // 7) A1 = Hs @ w1 ; GA = gelu(A1)
    gemm64<2><<<dim3(8, RWS / 64), 256>>>(p_Hs, w1, p_GA, RWS, DHID, DH, DH, DHID, DHID,
                                          0, 0, 0, nullptr, nullptr, nullptr, p_A1);
    // 8) pred = GA @ w2 + K -> dY
    gemm64<3><<<dim3(2, RWS / 64), 256>>>(p_GA, w2, p_dY, RWS, DH, DHID, DHID, DH, DH,
                                          0, 0, 0, p_K, p_V, p_lr, nullptr);
    // 9) dA1 = (dY @ w2^T) * gelu'(A1)
    gemm64<4><<<dim3(8, RWS / 64), 256>>>(p_dY, p_w2T, p_dA1, RWS, DHID, DH, DH, DHID, DHID,
                                          0, 0, 0, p_A1, nullptr, nullptr, nullptr);
    // 10) dH = dA1 @ w1^T
    gemm64<0><<<dim3(2, RWS / 64), 256>>>(p_dA1, p_w1T, p_dH, RWS, DH, DHID, DHID, DH, DH,
                                          0, 0, 0, nullptr, nullptr, nullptr, nullptr);

    // 11) sW1[z] = -Hs_z^T @ dA1_z   (per chunk, K=64)
    gemm_atb<<<dim3(8, 2, NCHUNK), 256>>>(p_Hs, p_dA1, p_sw1, DH, DHID,
                                          DH, DHID, DHID, CH * DH, CH * DHID, DH * DHID);
    // 12) sW2[z] = -GA_z^T @ dY_z
    gemm_atb<<<dim3(2, 8, NCHUNK), 256>>>(p_GA, p_dY, p_sw2, DHID, DH,
                                          DHID, DH, DH, CH * DHID, CH * DH, DHID * DH);
    // 13) s_g
    sg_kernel<<<NCHUNK, 128>>>();

    // 14) scans -> causal w_prev per chunk
    scan_kernel<<<dim3(DH * DHID / 256, BH), 256>>>(p_sw1, w1, p_Wp1, DH * DHID);
    scan_kernel<<<dim3(DHID * DH / 256, BH), 256>>>(p_sw2, w2, p_Wp2, DHID * DH);
    scan_kernel<<<dim3(1, BH), 256>>>(p_sg, memg, p_Gp, DH);

    // 15) Hq = rmsnorm(Q, Gp[chunk])
    hq_kernel<<<RWS, 128>>>();

    // 16) retrieval GEMM1: GAq = gelu(Hq @ Wp1[z])   (reuses g_GA)
    gemm64<6><<<dim3(8, 1, NCHUNK), 256>>>(p_Hq, p_Wp1, p_GA, CH, DHID, DH, DH, DHID, DHID,
                                           CH * DH, DH * DHID, CH * DHID,
                                           nullptr, nullptr, nullptr, nullptr);
    // 17) retrieval GEMM2: y = GAq @ Wp2[z] + q ; gated; combined-head layout -> g_R
    gemm64<7><<<dim3(2, 1, NCHUNK), 256>>>(p_GA, p_Wp2, p_R, CH, DH, DHID, DHID, DH, DH,
                                           CH * DHID, DHID * DH, 0,
                                           p_Q, p_gate, nullptr, p_R);
    // 18) out = R @ Wc
    gemm64<0><<<dim3(8, TOK / 64), 256>>>(p_R, Wc, out, TOK, DIM, DIM, DIM, DIM, DIM,
                                          0, 0, 0, nullptr, nullptr, nullptr, nullptr);
}

// round 2
// speedup vs baseline: 1.8679x; 1.8679x over previous
#include <cuda_runtime.h>
#include <math.h>

// ---------------- problem constants ----------------
constexpr int Bb   = 2;
constexpr int SEQN = 2048;
constexpr int DIM  = 512;
constexpr int NH   = 4;
constexpr int DH   = 128;
constexpr int CH   = 64;
constexpr int NC   = 32;       // SEQN / CH
constexpr int DHID = 512;      // 4 * DH
constexpr int BH   = 8;        // Bb * NH
constexpr int TOK  = Bb * SEQN;      // 4096
constexpr int RWS  = BH * SEQN;      // 16384
constexpr int NCHUNK = BH * NC;      // 256

// ---------------- device scratch ----------------
__device__ float g_xs[TOK * DIM];
__device__ float g_xr[TOK * DIM];
__device__ float g_K[RWS * DH];
__device__ float g_V[RWS * DH];
__device__ float g_Q[RWS * DH];
__device__ float g_lr[TOK * NH];
__device__ float g_gate[TOK * NH];
__device__ float g_beta[Bb * NC * NH];
__device__ float g_alpha[Bb * NC * NH];
__device__ float g_Hs[RWS * DH];
__device__ float g_rsK[RWS];
__device__ float g_A1[RWS * DHID];
__device__ float g_GA[RWS * DHID];
__device__ float g_dA1[RWS * DHID];
__device__ float g_dY[RWS * DH];
__device__ float g_dH[RWS * DH];
__device__ float g_sw1[NCHUNK * DH * DHID];
__device__ float g_sw2[NCHUNK * DHID * DH];
__device__ float g_sg[NCHUNK * DH];
__device__ float g_Wp1[NCHUNK * DH * DHID];
__device__ float g_Wp2[NCHUNK * DHID * DH];
__device__ float g_Gp[NCHUNK * DH];
__device__ float g_Hq[RWS * DH];
__device__ float g_R[TOK * DIM];
__device__ float g_w1T[DHID * DH];
__device__ float g_w2T[DH * DHID];

// ---------------- math helpers ----------------
__device__ __forceinline__ float sigmf(float x) { return 1.0f / (1.0f + expf(-x)); }
__device__ __forceinline__ float gelu_f(float x) {
    return 0.5f * x * (1.0f + erff(x * 0.70710678118654752f));
}
__device__ __forceinline__ float gelup_f(float x) {
    return 0.5f * (1.0f + erff(x * 0.70710678118654752f))
         + x * 0.3989422804014327f * expf(-0.5f * x * x);
}
__device__ __forceinline__ float to_tf32(float x) {
    asm("cvt.rna.tf32.f32 %0, %1;" : "=f"(x) : "f"(x));
    return x;
}
__device__ __forceinline__ void mma8(float c[4], const unsigned a[4],
                                     unsigned b0, unsigned b1) {
    asm volatile(
        "mma.sync.aligned.m16n8k8.row.col.f32.tf32.tf32.f32 "
        "{%0,%1,%2,%3},{%4,%5,%6,%7},{%8,%9},{%0,%1,%2,%3};"
        : "+f"(c[0]), "+f"(c[1]), "+f"(c[2]), "+f"(c[3])
        : "r"(a[0]), "r"(a[1]), "r"(a[2]), "r"(a[3]), "r"(b0), "r"(b1));
}

// ---------------- rmsnorm over DIM=512 (xs, xr) ----------------
__global__ void rmsseq_kernel(const float* __restrict__ seq,
                              const float* __restrict__ gs,
                              const float* __restrict__ gr) {
    int t = blockIdx.x;
    int tid = threadIdx.x;
    float x0 = seq[t * DIM + tid];
    float x1 = seq[t * DIM + tid + 256];
    float ss = x0 * x0 + x1 * x1;
    for (int o = 16; o; o >>= 1) ss += __shfl_down_sync(0xffffffffu, ss, o);
    __shared__ float sm[8];
    if ((tid & 31) == 0) sm[tid >> 5] = ss;
    __syncthreads();
    float tot = 0.f;
#pragma unroll
    for (int i = 0; i < 8; i++) tot += sm[i];
    float rs = rsqrtf(tot * (1.0f / DIM) + 1e-6f);
    g_xs[t * DIM + tid]       = x0 * rs * gs[tid];
    g_xs[t * DIM + tid + 256] = x1 * rs * gs[tid + 256];
    g_xr[t * DIM + tid]       = x0 * rs * gr[tid];
    g_xr[t * DIM + tid + 256] = x1 * rs * gr[tid + 256];
}

// ---------------- lr + gate ----------------
__global__ void lrgate_kernel(const float* __restrict__ Wa, const float* __restrict__ ba,
                              const float* __restrict__ Wg) {
    int t = blockIdx.x;
    int lane = threadIdx.x & 31;
    int h = threadIdx.x >> 5;
    float accA = 0.f, accG = 0.f;
    for (int d = lane; d < DIM; d += 32) {
        accA += g_xs[t * DIM + d] * Wa[d * NH + h];
        accG += g_xr[t * DIM + d] * Wg[d * NH + h];
    }
    for (int o = 16; o; o >>= 1) {
        accA += __shfl_down_sync(0xffffffffu, accA, o);
        accG += __shfl_down_sync(0xffffffffu, accG, o);
    }
    if (lane == 0) {
        g_lr[t * NH + h]   = sigmf(accA + ba[h]);
        g_gate[t * NH + h] = sigmf(accG);
    }
}

// ---------------- pooled chunk stats -> beta, alpha ----------------
__global__ void pool_kernel(const float* __restrict__ Wm, const float* __restrict__ Wd,
                            const float* __restrict__ bd) {
    int bc = blockIdx.x;
    int b = bc / NC, c = bc % NC;
    __shared__ float pooled[DIM];
    int tid = threadIdx.x;
    int t0 = b * SEQN + c * CH;
    float s = 0.f;
    for (int i = 0; i < CH; i++) s += g_xs[(t0 + i) * DIM + tid];
    pooled[tid] = s * (1.0f / CH);
    __syncthreads();
    if (tid < 128) {
        int lane = tid & 31, h = tid >> 5;
        float am = 0.f, ad = 0.f;
        for (int d = lane; d < DIM; d += 32) {
            am += pooled[d] * Wm[d * NH + h];
            ad += pooled[d] * Wd[d * NH + h];
        }
        for (int o = 16; o; o >>= 1) {
            am += __shfl_down_sync(0xffffffffu, am, o);
            ad += __shfl_down_sync(0xffffffffu, ad, o);
        }
        if (lane == 0) {
            g_beta[bc * NH + h]  = sigmf(am);
            g_alpha[bc * NH + h] = 1.0f - sigmf(ad + bd[h]);
        }
    }
}

// ---------------- rmsnorm over DH=128 for K -> Hs ----------------
__global__ void rmshead_kernel(const float* __restrict__ memg) {
    int r = blockIdx.x;
    int d = threadIdx.x;
    float x = g_K[r * DH + d];
    float ss = x * x;
    for (int o = 16; o; o >>= 1) ss += __shfl_down_sync(0xffffffffu, ss, o);
    __shared__ float sm[4];
    if ((d & 31) == 0) sm[d >> 5] = ss;
    __syncthreads();
    float tot = sm[0] + sm[1] + sm[2] + sm[3];
    float rs = rsqrtf(tot * (1.0f / DH) + 1e-6f);
    g_Hs[r * DH + d] = x * rs * memg[d];
    if (d == 0) g_rsK[r] = rs;
}

// ---------------- rmsnorm for Q with per-chunk Gp -> Hq ----------------
__global__ void hq_kernel() {
    int r = blockIdx.x;
    int d = threadIdx.x;
    int bh = r / SEQN, n = r % SEQN, c = n / CH;
    float x = g_Q[r * DH + d];
    float ss = x * x;
    for (int o = 16; o; o >>= 1) ss += __shfl_down_sync(0xffffffffu, ss, o);
    __shared__ float sm[4];
    if ((d & 31) == 0) sm[d >> 5] = ss;
    __syncthreads();
    float tot = sm[0] + sm[1] + sm[2] + sm[3];
    float rs = rsqrtf(tot * (1.0f / DH) + 1e-6f);
    g_Hq[r * DH + d] = x * rs * g_Gp[(bh * NC + c) * DH + d];
}

// ---------------- small transpose ----------------
__global__ void transpose_kernel(const float* __restrict__ in, float* __restrict__ out,
                                 int R, int C) {
    int idx = blockIdx.x * 256 + threadIdx.x;
    if (idx < R * C) {
        int r = idx / C, c = idx % C;
        out[c * R + r] = in[idx];
    }
}

// ---------------- s_g reduction ----------------
__global__ void sg_kernel() {
    int z = blockIdx.x;
    int d = threadIdx.x;
    int row0 = z * CH;
    float acc = 0.f;
    for (int i = 0; i < CH; i++) {
        int r = row0 + i;
        acc += g_dH[r * DH + d] * g_K[r * DH + d] * g_rsK[r];
    }
    g_sg[z * DH + d] = -acc;
}

// ---------------- momentum + decay scan ----------------
__global__ void scan_kernel(const float* __restrict__ s, const float* __restrict__ init,
                            float* __restrict__ wprev, int sz) {
    int bh = blockIdx.y;
    int e = blockIdx.x * 256 + threadIdx.x;
    if (e >= sz) return;
    int b = bh / NH, h = bh % NH;
    float m = 0.f, w = init[e];
    wprev[(bh * NC + 0) * sz + e] = w;
    for (int t = 0; t < NC; t++) {
        float beta  = g_beta[(b * NC + t) * NH + h];
        float alpha = g_alpha[(b * NC + t) * NH + h];
        m = beta * m + s[(bh * NC + t) * sz + e];
        w = alpha * w + m;
        if (t < NC - 1) wprev[(bh * NC + t + 1) * sz + e] = w;
    }
}

// ---------------- tf32 tensor-core GEMM, 64x64 block, 4 warps ----------------
// EPI: 0 plain, 1 permute-to-head-major, 2 store A1 + gelu, 3 pred->dY,
//      4 *gelu'(A1), 6 gelu only, 7 gated retrieval output, 8 negate
// TA: if true, C = op(A^T @ B) with A stored [K][M] in global memory
template <int EPI, bool TA>
__global__ void __launch_bounds__(128) gmma(
    const float* __restrict__ A, const float* __restrict__ Bm, float* __restrict__ C,
    int K, int lda, int ldb, int ldc,
    long sA, long sB, long sC,
    const float* __restrict__ x0, const float* __restrict__ x1,
    const float* __restrict__ x2, float* __restrict__ x3) {
    int z = blockIdx.z;
    A += (long)z * sA; Bm += (long)z * sB; C += (long)z * sC;

    __shared__ float As[32][68];   // k-major, pad 4 -> conflict-free frag reads
    __shared__ float Bs[32][68];

    int tid = threadIdx.x;
    int warp = tid >> 5, lane = tid & 31;
    int g = lane >> 2, tg = lane & 3;
    int warpM = (warp >> 1) * 32, warpN = (warp & 1) * 32;
    int m0 = blockIdx.y * 64, n0 = blockIdx.x * 64;

    float acc[2][4][4] = {};

    for (int kb = 0; kb < K; kb += 32) {
        if (!TA) {
            // A global row-major [M][K]; store transposed into As[k][m]
            int m = tid >> 3, kq = (tid & 7) * 4;
#pragma unroll
            for (int mi = 0; mi < 4; mi++) {
                const float4 v = *(const float4*)(A + (long)(m0 + m + mi * 16) * lda + kb + kq);
                As[kq + 0][m + mi * 16] = to_tf32(v.x);
                As[kq + 1][m + mi * 16] = to_tf32(v.y);
                As[kq + 2][m + mi * 16] = to_tf32(v.z);
                As[kq + 3][m + mi * 16] = to_tf32(v.w);
            }
        } else {
            // A global [K][M]; rows are k -> direct coalesced store
            int k = tid >> 4, mq = (tid & 15) * 4;
#pragma unroll
            for (int ki = 0; ki < 4; ki++) {
                int kk = k + ki * 8;
                const float4 v = *(const float4*)(A + (long)(kb + kk) * lda + m0 + mq);
                As[kk][mq + 0] = to_tf32(v.x);
                As[kk][mq + 1] = to_tf32(v.y);
                As[kk][mq + 2] = to_tf32(v.z);
                As[kk][mq + 3] = to_tf32(v.w);
            }
        }
        {
            int k = tid >> 4, nq = (tid & 15) * 4;
#pragma unroll
            for (int ki = 0; ki < 4; ki++) {
                int kk = k + ki * 8;
                const float4 v = *(const float4*)(Bm + (long)(kb + kk) * ldb + n0 + nq);
                Bs[kk][nq + 0] = to_tf32(v.x);
                Bs[kk][nq + 1] = to_tf32(v.y);
                Bs[kk][nq + 2] = to_tf32(v.z);
                Bs[kk][nq + 3] = to_tf32(v.w);
            }
        }
        __syncthreads();
#pragma unroll
        for (int s = 0; s < 4; s++) {
            int k0 = s * 8 + tg;
            unsigned a[2][4];
#pragma unroll
            for (int ma = 0; ma < 2; ma++) {
                int rb = warpM + ma * 16 + g;
                a[ma][0] = __float_as_uint(As[k0][rb]);
                a[ma][1] = __float_as_uint(As[k0][rb + 8]);
                a[ma][2] = __float_as_uint(As[k0 + 4][rb]);
                a[ma][3] = __float_as_uint(As[k0 + 4][rb + 8]);
            }
#pragma unroll
            for (int na = 0; na < 4; na++) {
                int nb = warpN + na * 8 + g;
                unsigned b0 = __float_as_uint(Bs[k0][nb]);
                unsigned b1 = __float_as_uint(Bs[k0 + 4][nb]);
#pragma unroll
                for (int ma = 0; ma < 2; ma++) mma8(acc[ma][na], a[ma], b0, b1);
            }
        }
        __syncthreads();
    }

    // epilogue
#pragma unroll
    for (int ma = 0; ma < 2; ma++) {
#pragma unroll
        for (int na = 0; na < 4; na++) {
#pragma unroll
            for (int i = 0; i < 4; i++) {
                int r = m0 + warpM + ma * 16 + g + ((i >= 2) ? 8 : 0);
                int c = n0 + warpN + na * 8 + tg * 2 + (i & 1);
                float v = acc[ma][na][i];
                if (EPI == 0) {
                    C[(long)r * ldc + c] = v;
                } else if (EPI == 8) {
                    C[(long)r * ldc + c] = -v;
                } else if (EPI == 1) {
                    int b = r / SEQN, n = r % SEQN, h = c / DH, d = c % DH;
                    C[(long)(((b * NH + h) * SEQN) + n) * DH + d] = v;
                } else if (EPI == 2) {
                    x3[(long)r * ldc + c] = v;
                    C[(long)r * ldc + c]  = gelu_f(v);
                } else if (EPI == 3) {
                    float pred = v + x0[(long)r * DH + c];
                    int bh = r / SEQN, n = r % SEQN;
                    int b = bh / NH, h = bh % NH;
                    float lr = x2[(b * SEQN + n) * NH + h];
                    C[(long)r * DH + c] = (2.0f / DH) * lr * (pred - x1[(long)r * DH + c]);
                } else if (EPI == 4) {
                    float a1 = x0[(long)r * ldc + c];
                    C[(long)r * ldc + c] = v * gelup_f(a1);
                } else if (EPI == 6) {
                    C[(long)r * ldc + c] = gelu_f(v);
                } else if (EPI == 7) {
                    float y = v + x0[(long)z * CH * DH + r * DH + c];
                    int bh = z / NC, cc = z % NC;
                    int n = cc * CH + r;
                    int b = bh / NH, h = bh % NH;
                    float gate = x1[(b * SEQN + n) * NH + h];
                    x3[(long)(b * SEQN + n) * DIM + h * DH + c] = y * gate;
                }
            }
        }
    }
}

// ---------------- launch ----------------
extern "C" void kernel_launch(void* const* d_in, const int* in_sizes, int n_in,
                              void* d_out, int out_size) {
    const float* seq   = (const float*)d_in[0];
    const float* gsto  = (const float*)d_in[1];
    const float* gret  = (const float*)d_in[2];
    const float* Wq    = (const float*)d_in[3];
    const float* Wk    = (const float*)d_in[4];
    const float* Wv    = (const float*)d_in[5];
    const float* Wa    = (const float*)d_in[6];
    const float* ba    = (const float*)d_in[7];
    const float* Wm    = (const float*)d_in[8];
    const float* Wd    = (const float*)d_in[9];
    const float* bd    = (const float*)d_in[10];
    const float* Wg    = (const float*)d_in[11];
    const float* Wc    = (const float*)d_in[12];
    const float* memg  = (const float*)d_in[13];
    const float* w1    = (const float*)d_in[14];
    const float* w2    = (const float*)d_in[15];
    float* out = (float*)d_out;

    float *p_xs, *p_xr, *p_K, *p_V, *p_Q, *p_lr, *p_gate, *p_Hs, *p_A1, *p_GA,
          *p_dA1, *p_dY, *p_dH, *p_sw1, *p_sw2, *p_sg, *p_Wp1, *p_Wp2, *p_Gp,
          *p_Hq, *p_R, *p_w1T, *p_w2T;
    cudaGetSymbolAddress((void**)&p_xs, g_xs);
    cudaGetSymbolAddress((void**)&p_xr, g_xr);
    cudaGetSymbolAddress((void**)&p_K, g_K);
    cudaGetSymbolAddress((void**)&p_V, g_V);
    cudaGetSymbolAddress((void**)&p_Q, g_Q);
    cudaGetSymbolAddress((void**)&p_lr, g_lr);
    cudaGetSymbolAddress((void**)&p_gate, g_gate);
    cudaGetSymbolAddress((void**)&p_Hs, g_Hs);
    cudaGetSymbolAddress((void**)&p_A1, g_A1);
    cudaGetSymbolAddress((void**)&p_GA, g_GA);
    cudaGetSymbolAddress((void**)&p_dA1, g_dA1);
    cudaGetSymbolAddress((void**)&p_dY, g_dY);
    cudaGetSymbolAddress((void**)&p_dH, g_dH);
    cudaGetSymbolAddress((void**)&p_sw1, g_sw1);
    cudaGetSymbolAddress((void**)&p_sw2, g_sw2);
    cudaGetSymbolAddress((void**)&p_sg, g_sg);
    cudaGetSymbolAddress((void**)&p_Wp1, g_Wp1);
    cudaGetSymbolAddress((void**)&p_Wp2, g_Wp2);
    cudaGetSymbolAddress((void**)&p_Gp, g_Gp);
    cudaGetSymbolAddress((void**)&p_Hq, g_Hq);
    cudaGetSymbolAddress((void**)&p_R, g_R);
    cudaGetSymbolAddress((void**)&p_w1T, g_w1T);
    cudaGetSymbolAddress((void**)&p_w2T, g_w2T);

    // 1) rmsnorm of seq -> xs, xr
    rmsseq_kernel<<<TOK, 256>>>(seq, gsto, gret);

    // 2) projections K,V (from xs), Q (from xr) -> head-major
    gmma<1, false><<<dim3(8, TOK / 64), 128>>>(p_xs, Wk, p_K, DIM, DIM, DIM, 0,
        0, 0, 0, nullptr, nullptr, nullptr, nullptr);
    gmma<1, false><<<dim3(8, TOK / 64), 128>>>(p_xs, Wv, p_V, DIM, DIM, DIM, 0,
        0, 0, 0, nullptr, nullptr, nullptr, nullptr);
    gmma<1, false><<<dim3(8, TOK / 64), 128>>>(p_xr, Wq, p_Q, DIM, DIM, DIM, 0,
        0, 0, 0, nullptr, nullptr, nullptr, nullptr);

    // 3) lr, gate ; 4) beta, alpha
    lrgate_kernel<<<TOK, 128>>>(Wa, ba, Wg);
    pool_kernel<<<Bb * NC, 512>>>(Wm, Wd, bd);

    // 5) Hs = rmsnorm(K, mem_g)
    rmshead_kernel<<<RWS, 128>>>(memg);

    // 6) weight transposes
    transpose_kernel<<<(DH * DHID + 255) / 256, 256>>>(w1, p_w1T, DH, DHID);
    transpose_kernel<<<(DHID * DH + 255) / 256, 256>>>(w2, p_w2T, DHID, DH);

    // 7) A1 = Hs @ w1 ; GA = gelu(A1)
    gmma<2, false><<<dim3(8, RWS / 64), 128>>>(p_Hs, w1, p_GA, DH, DH, DHID, DHID,
        0, 0, 0, nullptr, nullptr, nullptr, p_A1);
    // 8) pred = GA @ w2 + K -> dY
    gmma<3, false><<<dim3(2, RWS / 64), 128>>>(p_GA, w2, p_dY, DHID, DHID, DH, DH,
        0, 0, 0, p_K, p_V, p_lr, nullptr);
    // 9) dA1 = (dY @ w2^T) * gelu'(A1)
    gmma<4, false><<<dim3(8, RWS / 64), 128>>>(p_dY, p_w2T, p_dA1, DH, DH, DHID, DHID,
        0, 0, 0, p_A1, nullptr, nullptr, nullptr);
    // 10) dH = dA1 @ w1^T
    gmma<0, false><<<dim3(2, RWS / 64), 128>>>(p_dA1, p_w1T, p_dH, DHID, DHID, DH, DH,
        0, 0, 0, nullptr, nullptr, nullptr, nullptr);

    // 11) sW1[z] = -Hs_z^T @ dA1_z   (K = CH = 64)
    gmma<8, true><<<dim3(8, 2, NCHUNK), 128>>>(p_Hs, p_dA1, p_sw1, CH, DH, DHID, DHID,
        (long)CH * DH, (long)CH * DHID, (long)DH * DHID, nullptr, nullptr, nullptr, nullptr);
    // 12) sW2[z] = -GA_z^T @ dY_z
    gmma<8, true><<<dim3(2, 8, NCHUNK), 128>>>(p_GA, p_dY, p_sw2, CH, DHID, DH, DH,
        (long)CH * DHID, (long)CH * DH, (long)DHID * DH, nullptr, nullptr, nullptr, nullptr);
    // 13) s_g
    sg_kernel<<<NCHUNK, 128>>>();

    // 14) scans -> causal w_prev per chunk
    scan_kernel<<<dim3(DH * DHID / 256, BH), 256>>>(p_sw1, w1, p_Wp1, DH * DHID);
    scan_kernel<<<dim3(DHID * DH / 256, BH), 256>>>(p_sw2, w2, p_Wp2, DHID * DH);
    scan_kernel<<<dim3(1, BH), 256>>>(p_sg, memg, p_Gp, DH);

    // 15) Hq = rmsnorm(Q, Gp[chunk])
    hq_kernel<<<RWS, 128>>>();

    // 16) retrieval GEMM1: GAq = gelu(Hq @ Wp1[z])
    gmma<6, false><<<dim3(8, 1, NCHUNK), 128>>>(p_Hq, p_Wp1, p_GA, DH, DH, DHID, DHID,
        (long)CH * DH, (long)DH * DHID, (long)CH * DHID, nullptr, nullptr, nullptr, nullptr);
    // 17) retrieval GEMM2: y = GAq @ Wp2[z] + q ; gated -> g_R
    gmma<7, false><<<dim3(2, 1, NCHUNK), 128>>>(p_GA, p_Wp2, p_R, DHID, DHID, DH, DH,
        (long)CH * DHID, (long)DHID * DH, 0, p_Q, p_gate, nullptr, p_R);
    // 18) out = R @ Wc
    gmma<0, false><<<dim3(8, TOK / 64), 128>>>(p_R, Wc, out, DIM, DIM, DIM, DIM,
        0, 0, 0, nullptr, nullptr, nullptr, nullptr);
}

// round 3
// speedup vs baseline: 2.2637x; 1.2119x over previous
#include <cuda_runtime.h>
#include <math.h>

// ---------------- problem constants ----------------
constexpr int Bb   = 2;
constexpr int SEQN = 2048;
constexpr int DIM  = 512;
constexpr int NH   = 4;
constexpr int DH   = 128;
constexpr int CH   = 64;
constexpr int NC   = 32;
constexpr int DHID = 512;
constexpr int BH   = 8;
constexpr int TOK  = Bb * SEQN;      // 4096
constexpr int RWS  = BH * SEQN;      // 16384
constexpr int NCHUNK = BH * NC;      // 256

// ---------------- device scratch ----------------
__device__ float g_xs[TOK * DIM];
__device__ float g_xr[TOK * DIM];
__device__ float g_K[RWS * DH];
__device__ float g_V[RWS * DH];
__device__ float g_Q[RWS * DH];
__device__ float g_lr[TOK * NH];
__device__ float g_gate[TOK * NH];
__device__ float g_beta[Bb * NC * NH];
__device__ float g_alpha[Bb * NC * NH];
__device__ float g_Hs[RWS * DH];
__device__ float g_rsK[RWS];
__device__ float g_A1[RWS * DHID];
__device__ float g_GA[RWS * DHID];
__device__ float g_dA1[RWS * DHID];
__device__ float g_dY[RWS * DH];
__device__ float g_dH[RWS * DH];
__device__ float g_sw1[NCHUNK * DH * DHID];
__device__ float g_sw2[NCHUNK * DHID * DH];
__device__ float g_sg[NCHUNK * DH];
__device__ float g_Wp1[NCHUNK * DH * DHID];
__device__ float g_Wp2[NCHUNK * DHID * DH];
__device__ float g_Gp[NCHUNK * DH];
__device__ float g_Hq[RWS * DH];
__device__ float g_R[TOK * DIM];
__device__ float g_w1T[DHID * DH];
__device__ float g_w2T[DH * DHID];

// ---------------- math helpers ----------------
__device__ __forceinline__ float sigmf(float x) { return 1.0f / (1.0f + expf(-x)); }
__device__ __forceinline__ float gelu_f(float x) {
    return 0.5f * x * (1.0f + erff(x * 0.70710678118654752f));
}
__device__ __forceinline__ float gelup_f(float x) {
    return 0.5f * (1.0f + erff(x * 0.70710678118654752f))
         + x * 0.3989422804014327f * expf(-0.5f * x * x);
}
__device__ __forceinline__ unsigned tf32u(float x) {
    asm("cvt.rna.tf32.f32 %0, %1;" : "=f"(x) : "f"(x));
    return __float_as_uint(x);
}
__device__ __forceinline__ void mma8(float c[4], const unsigned a[4],
                                     unsigned b0, unsigned b1) {
    asm volatile(
        "mma.sync.aligned.m16n8k8.row.col.f32.tf32.tf32.f32 "
        "{%0,%1,%2,%3},{%4,%5,%6,%7},{%8,%9},{%0,%1,%2,%3};"
        : "+f"(c[0]), "+f"(c[1]), "+f"(c[2]), "+f"(c[3])
        : "r"(a[0]), "r"(a[1]), "r"(a[2]), "r"(a[3]), "r"(b0), "r"(b1));
}

// ---------------- rmsnorm over DIM=512 (xs, xr) ----------------
__global__ void rmsseq_kernel(const float* __restrict__ seq,
                              const float* __restrict__ gs,
                              const float* __restrict__ gr) {
    int t = blockIdx.x;
    int tid = threadIdx.x;
    float x0 = seq[t * DIM + tid];
    float x1 = seq[t * DIM + tid + 256];
    float ss = x0 * x0 + x1 * x1;
    for (int o = 16; o; o >>= 1) ss += __shfl_down_sync(0xffffffffu, ss, o);
    __shared__ float sm[8];
    if ((tid & 31) == 0) sm[tid >> 5] = ss;
    __syncthreads();
    float tot = 0.f;
#pragma unroll
    for (int i = 0; i < 8; i++) tot += sm[i];
    float rs = rsqrtf(tot * (1.0f / DIM) + 1e-6f);
    g_xs[t * DIM + tid]       = x0 * rs * gs[tid];
    g_xs[t * DIM + tid + 256] = x1 * rs * gs[tid + 256];
    g_xr[t * DIM + tid]       = x0 * rs * gr[tid];
    g_xr[t * DIM + tid + 256] = x1 * rs * gr[tid + 256];
}

// ---------------- lr + gate ----------------
__global__ void lrgate_kernel(const float* __restrict__ Wa, const float* __restrict__ ba,
                              const float* __restrict__ Wg) {
    int t = blockIdx.x;
    int lane = threadIdx.x & 31;
    int h = threadIdx.x >> 5;
    float accA = 0.f, accG = 0.f;
    for (int d = lane; d < DIM; d += 32) {
        accA += g_xs[t * DIM + d] * Wa[d * NH + h];
        accG += g_xr[t * DIM + d] * Wg[d * NH + h];
    }
    for (int o = 16; o; o >>= 1) {
        accA += __shfl_down_sync(0xffffffffu, accA, o);
        accG += __shfl_down_sync(0xffffffffu, accG, o);
    }
    if (lane == 0) {
        g_lr[t * NH + h]   = sigmf(accA + ba[h]);
        g_gate[t * NH + h] = sigmf(accG);
    }
}

// ---------------- pooled chunk stats -> beta, alpha ----------------
__global__ void pool_kernel(const float* __restrict__ Wm, const float* __restrict__ Wd,
                            const float* __restrict__ bd) {
    int bc = blockIdx.x;
    int b = bc / NC, c = bc % NC;
    __shared__ float pooled[DIM];
    int tid = threadIdx.x;
    int t0 = b * SEQN + c * CH;
    float s = 0.f;
    for (int i = 0; i < CH; i++) s += g_xs[(t0 + i) * DIM + tid];
    pooled[tid] = s * (1.0f / CH);
    __syncthreads();
    if (tid < 128) {
        int lane = tid & 31, h = tid >> 5;
        float am = 0.f, ad = 0.f;
        for (int d = lane; d < DIM; d += 32) {
            am += pooled[d] * Wm[d * NH + h];
            ad += pooled[d] * Wd[d * NH + h];
        }
        for (int o = 16; o; o >>= 1) {
            am += __shfl_down_sync(0xffffffffu, am, o);
            ad += __shfl_down_sync(0xffffffffu, ad, o);
        }
        if (lane == 0) {
            g_beta[bc * NH + h]  = sigmf(am);
            g_alpha[bc * NH + h] = 1.0f - sigmf(ad + bd[h]);
        }
    }
}

// ---------------- rmsnorm over DH=128 for K -> Hs ----------------
__global__ void rmshead_kernel(const float* __restrict__ memg) {
    int r = blockIdx.x;
    int d = threadIdx.x;
    float x = g_K[r * DH + d];
    float ss = x * x;
    for (int o = 16; o; o >>= 1) ss += __shfl_down_sync(0xffffffffu, ss, o);
    __shared__ float sm[4];
    if ((d & 31) == 0) sm[d >> 5] = ss;
    __syncthreads();
    float tot = sm[0] + sm[1] + sm[2] + sm[3];
    float rs = rsqrtf(tot * (1.0f / DH) + 1e-6f);
    g_Hs[r * DH + d] = x * rs * memg[d];
    if (d == 0) g_rsK[r] = rs;
}

// ---------------- rmsnorm for Q with per-chunk Gp -> Hq ----------------
__global__ void hq_kernel() {
    int r = blockIdx.x;
    int d = threadIdx.x;
    int bh = r / SEQN, n = r % SEQN, c = n / CH;
    float x = g_Q[r * DH + d];
    float ss = x * x;
    for (int o = 16; o; o >>= 1) ss += __shfl_down_sync(0xffffffffu, ss, o);
    __shared__ float sm[4];
    if ((d & 31) == 0) sm[d >> 5] = ss;
    __syncthreads();
    float tot = sm[0] + sm[1] + sm[2] + sm[3];
    float rs = rsqrtf(tot * (1.0f / DH) + 1e-6f);
    g_Hq[r * DH + d] = x * rs * g_Gp[(bh * NC + c) * DH + d];
}

// ---------------- small transpose ----------------
__global__ void transpose_kernel(const float* __restrict__ in, float* __restrict__ out,
                                 int R, int C) {
    int idx = blockIdx.x * 256 + threadIdx.x;
    if (idx < R * C) {
        int r = idx / C, c = idx % C;
        out[c * R + r] = in[idx];
    }
}

// ---------------- s_g reduction ----------------
__global__ void sg_kernel() {
    int z = blockIdx.x;
    int d = threadIdx.x;
    int row0 = z * CH;
    float acc = 0.f;
    for (int i = 0; i < CH; i++) {
        int r = row0 + i;
        acc += g_dH[r * DH + d] * g_K[r * DH + d] * g_rsK[r];
    }
    g_sg[z * DH + d] = -acc;
}

// ---------------- momentum + decay scan ----------------
__global__ void scan_kernel(const float* __restrict__ s, const float* __restrict__ init,
                            float* __restrict__ wprev, int sz) {
    int bh = blockIdx.y;
    int e = blockIdx.x * 256 + threadIdx.x;
    if (e >= sz) return;
    int b = bh / NH, h = bh % NH;
    float m = 0.f, w = init[e];
    wprev[(bh * NC + 0) * sz + e] = w;
    for (int t = 0; t < NC; t++) {
        float beta  = g_beta[(b * NC + t) * NH + h];
        float alpha = g_alpha[(b * NC + t) * NH + h];
        m = beta * m + s[(bh * NC + t) * sz + e];
        w = alpha * w + m;
        if (t < NC - 1) wprev[(bh * NC + t + 1) * sz + e] = w;
    }
}

// ============ tf32 tensor-core GEMM, BMx128 tile, 256 threads, 8 warps ===========
// EPI: 0 plain, 1 permute-to-head-major, 2 store A1 + gelu, 3 pred->dY,
//      4 *gelu'(A1), 6 gelu only, 7 gated retrieval output, 8 negate
// TA: C = op(A^T @ B) with A stored [K][M] globally (only used with BM=128)
template <int BM, int EPI, bool TA>
__global__ void __launch_bounds__(256, 2) gmma(
    const float* __restrict__ A, const float* __restrict__ Bm, float* __restrict__ C,
    int K, int lda, int ldb, int ldc,
    long sA, long sB, long sC,
    const float* __restrict__ x0, const float* __restrict__ x1,
    const float* __restrict__ x2, float* __restrict__ x3) {
    constexpr int WM = BM / 2;        // warp tile M (64 or 32)
    constexpr int MA = WM / 16;       // m-atoms per warp (4 or 2)
    constexpr int AF = BM / 64;       // float4 A-chunks per thread (2 or 1)
    constexpr int ASZ = TA ? 16 * 136 : BM * 20;

    int z = blockIdx.z;
    A += (long)z * sA; Bm += (long)z * sB; C += (long)z * sC;

    __shared__ float As[2][ASZ];
    __shared__ float Bs[2][16 * 136];

    int tid = threadIdx.x;
    int warp = tid >> 5, lane = tid & 31;
    int g = lane >> 2, tg = lane & 3;
    int wr = warp >> 2, wc = warp & 3;        // 2 x 4 warp grid
    int m0 = blockIdx.y * BM, n0 = blockIdx.x * 128;

    float acc[MA][4][4];
#pragma unroll
    for (int i = 0; i < MA; i++)
#pragma unroll
        for (int j = 0; j < 4; j++)
#pragma unroll
            for (int l = 0; l < 4; l++) acc[i][j][l] = 0.f;

    float4 ar[2], br[2];

    auto ldg = [&](int kb) {
        if (!TA) {
#pragma unroll
            for (int f = 0; f < AF; f++) {
                int cid = tid + f * 256;
                int m = cid >> 2, kq = (cid & 3) * 4;
                ar[f] = *(const float4*)(A + (long)(m0 + m) * lda + kb + kq);
            }
        } else {
#pragma unroll
            for (int h = 0; h < 2; h++) {
                int m4 = lane * 4, krow = (tid >> 5) + 8 * h;
                ar[h] = *(const float4*)(A + (long)(kb + krow) * lda + m0 + m4);
            }
        }
#pragma unroll
        for (int f = 0; f < 2; f++) {
            int cid = tid + f * 256;
            int k = cid >> 5, nq = (cid & 31) * 4;
            br[f] = *(const float4*)(Bm + (long)(kb + k) * ldb + n0 + nq);
        }
    };
    auto sts = [&](int buf) {
        if (!TA) {
#pragma unroll
            for (int f = 0; f < AF; f++) {
                int cid = tid + f * 256;
                int m = cid >> 2, kq = (cid & 3) * 4;
                *(float4*)&As[buf][m * 20 + kq] = ar[f];
            }
        } else {
#pragma unroll
            for (int h = 0; h < 2; h++) {
                int m4 = lane * 4, krow = (tid >> 5) + 8 * h;
                *(float4*)&As[buf][krow * 136 + m4] = ar[h];
            }
        }
#pragma unroll
        for (int f = 0; f < 2; f++) {
            int cid = tid + f * 256;
            int k = cid >> 5, nq = (cid & 31) * 4;
            *(float4*)&Bs[buf][k * 136 + nq] = br[f];
        }
    };

    int nT = K >> 4;
    ldg(0);
    sts(0);
    __syncthreads();
    int cur = 0;
    for (int t = 0; t < nT; t++) {
        if (t + 1 < nT) ldg((t + 1) << 4);
#pragma unroll
        for (int s = 0; s < 2; s++) {
            int k0 = s * 8 + tg;
            unsigned af[MA][4], bf[4][2];
#pragma unroll
            for (int ma = 0; ma < MA; ma++) {
                int rb = wr * WM + ma * 16 + g;
                if (!TA) {
                    af[ma][0] = tf32u(As[cur][rb * 20 + k0]);
                    af[ma][1] = tf32u(As[cur][(rb + 8) * 20 + k0]);
                    af[ma][2] = tf32u(As[cur][rb * 20 + k0 + 4]);
                    af[ma][3] = tf32u(As[cur][(rb + 8) * 20 + k0 + 4]);
                } else {
                    af[ma][0] = tf32u(As[cur][k0 * 136 + rb]);
                    af[ma][1] = tf32u(As[cur][k0 * 136 + rb + 8]);
                    af[ma][2] = tf32u(As[cur][(k0 + 4) * 136 + rb]);
                    af[ma][3] = tf32u(As[cur][(k0 + 4) * 136 + rb + 8]);
                }
            }
#pragma unroll
            for (int na = 0; na < 4; na++) {
                int nb = wc * 32 + na * 8 + g;
                bf[na][0] = tf32u(Bs[cur][k0 * 136 + nb]);
                bf[na][1] = tf32u(Bs[cur][(k0 + 4) * 136 + nb]);
            }
#pragma unroll
            for (int na = 0; na < 4; na++)
#pragma unroll
                for (int ma = 0; ma < MA; ma++)
                    mma8(acc[ma][na], af[ma], bf[na][0], bf[na][1]);
        }
        if (t + 1 < nT) {
            sts(cur ^ 1);
            cur ^= 1;
        }
        __syncthreads();
    }

    // epilogue
#pragma unroll
    for (int ma = 0; ma < MA; ma++) {
#pragma unroll
        for (int na = 0; na < 4; na++) {
#pragma unroll
            for (int i = 0; i < 4; i++) {
                int r = m0 + wr * WM + ma * 16 + g + ((i >= 2) ? 8 : 0);
                int c = n0 + wc * 32 + na * 8 + tg * 2 + (i & 1);
                float v = acc[ma][na][i];
                if (EPI == 0) {
                    C[(long)r * ldc + c] = v;
                } else if (EPI == 8) {
                    C[(long)r * ldc + c] = -v;
                } else if (EPI == 1) {
                    int b = r / SEQN, n = r % SEQN, h = c / DH, d = c % DH;
                    C[(long)(((b * NH + h) * SEQN) + n) * DH + d] = v;
                } else if (EPI == 2) {
                    x3[(long)r * ldc + c] = v;
                    C[(long)r * ldc + c]  = gelu_f(v);
                } else if (EPI == 3) {
                    float pred = v + x0[(long)r * DH + c];
                    int bh = r / SEQN, n = r % SEQN;
                    int b = bh / NH, h = bh % NH;
                    float lr = x2[(b * SEQN + n) * NH + h];
                    C[(long)r * DH + c] = (2.0f / DH) * lr * (pred - x1[(long)r * DH + c]);
                } else if (EPI == 4) {
                    float a1 = x0[(long)r * ldc + c];
                    C[(long)r * ldc + c] = v * gelup_f(a1);
                } else if (EPI == 6) {
                    C[(long)r * ldc + c] = gelu_f(v);
                } else if (EPI == 7) {
                    float y = v + x0[(long)z * CH * DH + r * DH + c];
                    int bh = z / NC, cc = z % NC;
                    int n = cc * CH + r;
                    int b = bh / NH, h = bh % NH;
                    float gate = x1[(b * SEQN + n) * NH + h];
                    x3[(long)(b * SEQN + n) * DIM + h * DH + c] = y * gate;
                }
            }
        }
    }
}

// ---------------- launch ----------------
extern "C" void kernel_launch(void* const* d_in, const int* in_sizes, int n_in,
                              void* d_out, int out_size) {
    const float* seq   = (const float*)d_in[0];
    const float* gsto  = (const float*)d_in[1];
    const float* gret  = (const float*)d_in[2];
    const float* Wq    = (const float*)d_in[3];
    const float* Wk    = (const float*)d_in[4];
    const float* Wv    = (const float*)d_in[5];
    const float* Wa    = (const float*)d_in[6];
    const float* ba    = (const float*)d_in[7];
    const float* Wm    = (const float*)d_in[8];
    const float* Wd    = (const float*)d_in[9];
    const float* bd    = (const float*)d_in[10];
    const float* Wg    = (const float*)d_in[11];
    const float* Wc    = (const float*)d_in[12];
    const float* memg  = (const float*)d_in[13];
    const float* w1    = (const float*)d_in[14];
    const float* w2    = (const float*)d_in[15];
    float* out = (float*)d_out;

    float *p_xs, *p_xr, *p_K, *p_V, *p_Q, *p_lr, *p_gate, *p_Hs, *p_A1, *p_GA,
          *p_dA1, *p_dY, *p_dH, *p_sw1, *p_sw2, *p_sg, *p_Wp1, *p_Wp2, *p_Gp,
          *p_Hq, *p_R, *p_w1T, *p_w2T;
    cudaGetSymbolAddress((void**)&p_xs, g_xs);
    cudaGetSymbolAddress((void**)&p_xr, g_xr);
    cudaGetSymbolAddress((void**)&p_K, g_K);
    cudaGetSymbolAddress((void**)&p_V, g_V);
    cudaGetSymbolAddress((void**)&p_Q, g_Q);
    cudaGetSymbolAddress((void**)&p_lr, g_lr);
    cudaGetSymbolAddress((void**)&p_gate, g_gate);
    cudaGetSymbolAddress((void**)&p_Hs, g_Hs);
    cudaGetSymbolAddress((void**)&p_A1, g_A1);
    cudaGetSymbolAddress((void**)&p_GA, g_GA);
    cudaGetSymbolAddress((void**)&p_dA1, g_dA1);
    cudaGetSymbolAddress((void**)&p_dY, g_dY);
    cudaGetSymbolAddress((void**)&p_dH, g_dH);
    cudaGetSymbolAddress((void**)&p_sw1, g_sw1);
    cudaGetSymbolAddress((void**)&p_sw2, g_sw2);
    cudaGetSymbolAddress((void**)&p_sg, g_sg);
    cudaGetSymbolAddress((void**)&p_Wp1, g_Wp1);
    cudaGetSymbolAddress((void**)&p_Wp2, g_Wp2);
    cudaGetSymbolAddress((void**)&p_Gp, g_Gp);
    cudaGetSymbolAddress((void**)&p_Hq, g_Hq);
    cudaGetSymbolAddress((void**)&p_R, g_R);
    cudaGetSymbolAddress((void**)&p_w1T, g_w1T);
    cudaGetSymbolAddress((void**)&p_w2T, g_w2T);

    // 1) rmsnorm of seq -> xs, xr
    rmsseq_kernel<<<TOK, 256>>>(seq, gsto, gret);

    // 2) projections K,V (from xs), Q (from xr) -> head-major
    gmma<128, 1, false><<<dim3(4, 32), 256>>>(p_xs, Wk, p_K, DIM, DIM, DIM, 0,
        0, 0, 0, nullptr, nullptr, nullptr, nullptr);
    gmma<128, 1, false><<<dim3(4, 32), 256>>>(p_xs, Wv, p_V, DIM, DIM, DIM, 0,
        0, 0, 0, nullptr, nullptr, nullptr, nullptr);
    gmma<128, 1, false><<<dim3(4, 32), 256>>>(p_xr, Wq, p_Q, DIM, DIM, DIM, 0,
        0, 0, 0, nullptr, nullptr, nullptr, nullptr);

    // 3) lr, gate ; 4) beta, alpha
    lrgate_kernel<<<TOK, 128>>>(Wa, ba, Wg);
    pool_kernel<<<Bb * NC, 512>>>(Wm, Wd, bd);

    // 5) Hs = rmsnorm(K, mem_g)
    rmshead_kernel<<<RWS, 128>>>(memg);

    // 6) weight transposes
    transpose_kernel<<<(DH * DHID + 255) / 256, 256>>>(w1, p_w1T, DH, DHID);
    transpose_kernel<<<(DHID * DH + 255) / 256, 256>>>(w2, p_w2T, DHID, DH);

    // 7) A1 = Hs @ w1 ; GA = gelu(A1)
    gmma<128, 2, false><<<dim3(4, 128), 256>>>(p_Hs, w1, p_GA, DH, DH, DHID, DHID,
        0, 0, 0, nullptr, nullptr, nullptr, p_A1);
    // 8) pred = GA @ w2 + K -> dY
    gmma<128, 3, false><<<dim3(1, 128), 256>>>(p_GA, w2, p_dY, DHID, DHID, DH, DH,
        0, 0, 0, p_K, p_V, p_lr, nullptr);
    // 9) dA1 = (dY @ w2^T) * gelu'(A1)
    gmma<128, 4, false><<<dim3(4, 128), 256>>>(p_dY, p_w2T, p_dA1, DH, DH, DHID, DHID,
        0, 0, 0, p_A1, nullptr, nullptr, nullptr);
    // 10) dH = dA1 @ w1^T
    gmma<128, 0, false><<<dim3(1, 128), 256>>>(p_dA1, p_w1T, p_dH, DHID, DHID, DH, DH,
        0, 0, 0, nullptr, nullptr, nullptr, nullptr);

    // 11) sW1[z] = -Hs_z^T @ dA1_z   (K = CH = 64)
    gmma<128, 8, true><<<dim3(4, 1, NCHUNK), 256>>>(p_Hs, p_dA1, p_sw1, CH, DH, DHID, DHID,
        (long)CH * DH, (long)CH * DHID, (long)DH * DHID, nullptr, nullptr, nullptr, nullptr);
    // 12) sW2[z] = -GA_z^T @ dY_z
    gmma<128, 8, true><<<dim3(1, 4, NCHUNK), 256>>>(p_GA, p_dY, p_sw2, CH, DHID, DH, DH,
        (long)CH * DHID, (long)CH * DH, (long)DHID * DH, nullptr, nullptr, nullptr, nullptr);
    // 13) s_g
    sg_kernel<<<NCHUNK, 128>>>();

    // 14) scans -> causal w_prev per chunk
    scan_kernel<<<dim3(DH * DHID / 256, BH), 256>>>(p_sw1, w1, p_Wp1, DH * DHID);
    scan_kernel<<<dim3(DHID * DH / 256, BH), 256>>>(p_sw2, w2, p_Wp2, DHID * DH);
    scan_kernel<<<dim3(1, BH), 256>>>(p_sg, memg, p_Gp, DH);

    // 15) Hq = rmsnorm(Q, Gp[chunk])
    hq_kernel<<<RWS, 128>>>();

    // 16) retrieval GEMM1: GAq = gelu(Hq @ Wp1[z])
    gmma<64, 6, false><<<dim3(4, 1, NCHUNK), 256>>>(p_Hq, p_Wp1, p_GA, DH, DH, DHID, DHID,
        (long)CH * DH, (long)DH * DHID, (long)CH * DHID, nullptr, nullptr, nullptr, nullptr);
    // 17) retrieval GEMM2: y = GAq @ Wp2[z] + q ; gated -> g_R
    gmma<64, 7, false><<<dim3(1, 1, NCHUNK), 256>>>(p_GA, p_Wp2, p_R, DHID, DHID, DH, DH,
        (long)CH * DHID, (long)DHID * DH, 0, p_Q, p_gate, nullptr, p_R);
    // 18) out = R @ Wc
    gmma<128, 0, false><<<dim3(4, 32), 256>>>(p_R, Wc, out, DIM, DIM, DIM, DIM,
        0, 0, 0, nullptr, nullptr, nullptr, nullptr);
}

// round 4
// speedup vs baseline: 2.4408x; 1.0782x over previous
#include <cuda_runtime.h>
#include <math.h>

// ---------------- problem constants ----------------
constexpr int Bb   = 2;
constexpr int SEQN = 2048;
constexpr int DIM  = 512;
constexpr int NH   = 4;
constexpr int DH   = 128;
constexpr int CH   = 64;
constexpr int NC   = 32;
constexpr int DHID = 512;
constexpr int BH   = 8;
constexpr int TOK  = Bb * SEQN;      // 4096
constexpr int RWS  = BH * SEQN;      // 16384
constexpr int NCHUNK = BH * NC;      // 256
constexpr long RWSDH = (long)RWS * DH;

// ---------------- device scratch ----------------
__device__ float g_xs[TOK * DIM];
__device__ float g_xr[TOK * DIM];
__device__ float g_KVQ[3 * RWS * DH];          // K | V | Q
__device__ float g_lr[TOK * NH];
__device__ float g_gate[TOK * NH];
__device__ float g_beta[Bb * NC * NH];
__device__ float g_alpha[Bb * NC * NH];
__device__ float g_Hs[RWS * DH];
__device__ float g_rsK[RWS];
__device__ float g_A1[RWS * DHID];
__device__ float g_GA[RWS * DHID];
__device__ float g_dA1[RWS * DHID];
__device__ float g_dY[RWS * DH];
__device__ float g_dH[RWS * DH];
__device__ float g_sw1[NCHUNK * DH * DHID];
__device__ float g_sw2[NCHUNK * DHID * DH];
__device__ float g_sg[NCHUNK * DH];
__device__ float g_Wp1[NCHUNK * DH * DHID];
__device__ float g_Wp2[NCHUNK * DHID * DH];
__device__ float g_Gp[NCHUNK * DH];
__device__ float g_Hq[RWS * DH];
__device__ float g_R[TOK * DIM];
__device__ float g_w1T[DHID * DH];
__device__ float g_w2T[DH * DHID];
// tf32-rounded weight copies
__device__ float g_Wr[3 * DIM * DIM];          // Wk | Wv | Wq
__device__ float g_Wcr[DIM * DIM];
__device__ float g_w1r[DH * DHID];
__device__ float g_w2r[DHID * DH];

// ---------------- math helpers ----------------
__device__ __forceinline__ float sigmf(float x) { return 1.0f / (1.0f + expf(-x)); }
__device__ __forceinline__ float gelu_f(float x) {
    return 0.5f * x * (1.0f + erff(x * 0.70710678118654752f));
}
__device__ __forceinline__ float gelup_f(float x) {
    return 0.5f * (1.0f + erff(x * 0.70710678118654752f))
         + x * 0.3989422804014327f * expf(-0.5f * x * x);
}
__device__ __forceinline__ float rndf(float x) {      // round-to-nearest tf32
    asm("cvt.rna.tf32.f32 %0, %1;" : "=f"(x) : "f"(x));
    return x;
}
__device__ __forceinline__ void mma8(float c[4], const unsigned a[4],
                                     unsigned b0, unsigned b1) {
    asm volatile(
        "mma.sync.aligned.m16n8k8.row.col.f32.tf32.tf32.f32 "
        "{%0,%1,%2,%3},{%4,%5,%6,%7},{%8,%9},{%0,%1,%2,%3};"
        : "+f"(c[0]), "+f"(c[1]), "+f"(c[2]), "+f"(c[3])
        : "r"(a[0]), "r"(a[1]), "r"(a[2]), "r"(a[3]), "r"(b0), "r"(b1));
}
__device__ __forceinline__ void cpa16(float* s, const float* g) {
    unsigned sa = (unsigned)__cvta_generic_to_shared(s);
    asm volatile("cp.async.cg.shared.global [%0], [%1], 16;\n" :: "r"(sa), "l"(g));
}
#define CP_COMMIT() asm volatile("cp.async.commit_group;\n" ::: "memory")
#define CP_WAIT1()  asm volatile("cp.async.wait_group 1;\n" ::: "memory")

// ---------------- weight rounding (tf32 copies of input weights) ----------------
__global__ void roundw_kernel(const float* __restrict__ Wk, const float* __restrict__ Wv,
                              const float* __restrict__ Wq, const float* __restrict__ Wc,
                              const float* __restrict__ w1, const float* __restrict__ w2) {
    int z = blockIdx.y;
    int idx = blockIdx.x * 256 + threadIdx.x;
    if (z < 3) {
        if (idx < DIM * DIM) g_Wr[z * DIM * DIM + idx] = rndf(z == 0 ? Wk[idx] : z == 1 ? Wv[idx] : Wq[idx]);
    } else if (z == 3) {
        if (idx < DIM * DIM) g_Wcr[idx] = rndf(Wc[idx]);
    } else if (z == 4) {
        if (idx < DH * DHID) g_w1r[idx] = rndf(w1[idx]);
    } else {
        if (idx < DHID * DH) g_w2r[idx] = rndf(w2[idx]);
    }
}

// ---------------- rmsnorm over DIM=512 (xs, xr) ----------------
__global__ void rmsseq_kernel(const float* __restrict__ seq,
                              const float* __restrict__ gs,
                              const float* __restrict__ gr) {
    int t = blockIdx.x;
    int tid = threadIdx.x;
    float x0 = seq[t * DIM + tid];
    float x1 = seq[t * DIM + tid + 256];
    float ss = x0 * x0 + x1 * x1;
    for (int o = 16; o; o >>= 1) ss += __shfl_down_sync(0xffffffffu, ss, o);
    __shared__ float sm[8];
    if ((tid & 31) == 0) sm[tid >> 5] = ss;
    __syncthreads();
    float tot = 0.f;
#pragma unroll
    for (int i = 0; i < 8; i++) tot += sm[i];
    float rs = rsqrtf(tot * (1.0f / DIM) + 1e-6f);
    g_xs[t * DIM + tid]       = rndf(x0 * rs * gs[tid]);
    g_xs[t * DIM + tid + 256] = rndf(x1 * rs * gs[tid + 256]);
    g_xr[t * DIM + tid]       = rndf(x0 * rs * gr[tid]);
    g_xr[t * DIM + tid + 256] = rndf(x1 * rs * gr[tid + 256]);
}

// ---------------- lr + gate ----------------
__global__ void lrgate_kernel(const float* __restrict__ Wa, const float* __restrict__ ba,
                              const float* __restrict__ Wg) {
    int t = blockIdx.x;
    int lane = threadIdx.x & 31;
    int h = threadIdx.x >> 5;
    float accA = 0.f, accG = 0.f;
    for (int d = lane; d < DIM; d += 32) {
        accA += g_xs[t * DIM + d] * Wa[d * NH + h];
        accG += g_xr[t * DIM + d] * Wg[d * NH + h];
    }
    for (int o = 16; o; o >>= 1) {
        accA += __shfl_down_sync(0xffffffffu, accA, o);
        accG += __shfl_down_sync(0xffffffffu, accG, o);
    }
    if (lane == 0) {
        g_lr[t * NH + h]   = sigmf(accA + ba[h]);
        g_gate[t * NH + h] = sigmf(accG);
    }
}

// ---------------- pooled chunk stats -> beta, alpha ----------------
__global__ void pool_kernel(const float* __restrict__ Wm, const float* __restrict__ Wd,
                            const float* __restrict__ bd) {
    int bc = blockIdx.x;
    int b = bc / NC, c = bc % NC;
    __shared__ float pooled[DIM];
    int tid = threadIdx.x;
    int t0 = b * SEQN + c * CH;
    float s = 0.f;
    for (int i = 0; i < CH; i++) s += g_xs[(t0 + i) * DIM + tid];
    pooled[tid] = s * (1.0f / CH);
    __syncthreads();
    if (tid < 128) {
        int lane = tid & 31, h = tid >> 5;
        float am = 0.f, ad = 0.f;
        for (int d = lane; d < DIM; d += 32) {
            am += pooled[d] * Wm[d * NH + h];
            ad += pooled[d] * Wd[d * NH + h];
        }
        for (int o = 16; o; o >>= 1) {
            am += __shfl_down_sync(0xffffffffu, am, o);
            ad += __shfl_down_sync(0xffffffffu, ad, o);
        }
        if (lane == 0) {
            g_beta[bc * NH + h]  = sigmf(am);
            g_alpha[bc * NH + h] = 1.0f - sigmf(ad + bd[h]);
        }
    }
}

// ---------------- rmsnorm over DH=128 for K -> Hs ----------------
__global__ void rmshead_kernel(const float* __restrict__ memg) {
    int r = blockIdx.x;
    int d = threadIdx.x;
    float x = g_KVQ[(long)r * DH + d];          // K
    float ss = x * x;
    for (int o = 16; o; o >>= 1) ss += __shfl_down_sync(0xffffffffu, ss, o);
    __shared__ float sm[4];
    if ((d & 31) == 0) sm[d >> 5] = ss;
    __syncthreads();
    float tot = sm[0] + sm[1] + sm[2] + sm[3];
    float rs = rsqrtf(tot * (1.0f / DH) + 1e-6f);
    g_Hs[r * DH + d] = rndf(x * rs * memg[d]);
    if (d == 0) g_rsK[r] = rs;
}

// ---------------- rmsnorm for Q with per-chunk Gp -> Hq ----------------
__global__ void hq_kernel() {
    int r = blockIdx.x;
    int d = threadIdx.x;
    int bh = r / SEQN, n = r % SEQN, c = n / CH;
    float x = g_KVQ[2 * RWSDH + (long)r * DH + d];   // Q
    float ss = x * x;
    for (int o = 16; o; o >>= 1) ss += __shfl_down_sync(0xffffffffu, ss, o);
    __shared__ float sm[4];
    if ((d & 31) == 0) sm[d >> 5] = ss;
    __syncthreads();
    float tot = sm[0] + sm[1] + sm[2] + sm[3];
    float rs = rsqrtf(tot * (1.0f / DH) + 1e-6f);
    g_Hq[r * DH + d] = rndf(x * rs * g_Gp[(bh * NC + c) * DH + d]);
}

// ---------------- small transpose (rounded outputs) ----------------
__global__ void transpose_kernel(const float* __restrict__ in, float* __restrict__ out,
                                 int R, int C) {
    int idx = blockIdx.x * 256 + threadIdx.x;
    if (idx < R * C) {
        int r = idx / C, c = idx % C;
        out[c * R + r] = rndf(in[idx]);
    }
}

// ---------------- s_g reduction ----------------
__global__ void sg_kernel() {
    int z = blockIdx.x;
    int d = threadIdx.x;
    int row0 = z * CH;
    float acc = 0.f;
    for (int i = 0; i < CH; i++) {
        int r = row0 + i;
        acc += g_dH[r * DH + d] * g_KVQ[(long)r * DH + d] * g_rsK[r];
    }
    g_sg[z * DH + d] = -acc;
}

// ---------------- momentum + decay scan (rounded weight outputs) ----------------
__global__ void scan_kernel(const float* __restrict__ s, const float* __restrict__ init,
                            float* __restrict__ wprev, int sz) {
    int bh = blockIdx.y;
    int e = blockIdx.x * 256 + threadIdx.x;
    if (e >= sz) return;
    int b = bh / NH, h = bh % NH;
    float m = 0.f, w = init[e];
    wprev[(long)(bh * NC + 0) * sz + e] = rndf(w);
    for (int t = 0; t < NC; t++) {
        float beta  = g_beta[(b * NC + t) * NH + h];
        float alpha = g_alpha[(b * NC + t) * NH + h];
        m = beta * m + s[(long)(bh * NC + t) * sz + e];
        w = alpha * w + m;
        if (t < NC - 1) wprev[(long)(bh * NC + t + 1) * sz + e] = rndf(w);
    }
}

// ======= tf32 tensor-core GEMM, BMx128 tile, cp.async 3-stage pipeline =======
// EPI: 0 plain, 1 fused QKV (z selects A/B/C), 2 store A1 + gelu, 3 pred->dY,
//      4 *gelu'(A1), 6 gelu only, 7 gated retrieval output, 8 negate
// TA: C = op(A^T @ B), A stored [K][M] globally (BM=128 only)
template <int BM, int EPI, bool TA>
__global__ void __launch_bounds__(256, 2) gmma(
    const float* __restrict__ A, const float* __restrict__ Bm, float* __restrict__ C,
    int K, int lda, int ldb, int ldc,
    long sA, long sB, long sC,
    const float* __restrict__ x0, const float* __restrict__ x1,
    const float* __restrict__ x2, float* __restrict__ x3) {
    constexpr int STG = 3;
    constexpr int WM  = BM / 2;
    constexpr int MA  = WM / 16;
    constexpr int AF  = BM / 64;
    constexpr int ASZ = TA ? 16 * 136 : BM * 20;
    constexpr int BSZ = 16 * 136;

    int z = blockIdx.z;
    if (EPI == 1) {
        // fused QKV: A in {A(xs), A(xs), x0(xr)}, B in {Bm, x1, x2}, C += z*RWSDH
        if (z == 2) A = x0;
        Bm = (z == 0) ? Bm : (z == 1) ? x1 : x2;
        C += (long)z * RWSDH;
    } else {
        A += (long)z * sA; Bm += (long)z * sB; C += (long)z * sC;
    }

    extern __shared__ float smp[];
    float* Asm = smp;
    float* Bsm = smp + STG * ASZ;

    int tid = threadIdx.x;
    int warp = tid >> 5, lane = tid & 31;
    int g = lane >> 2, tg = lane & 3;
    int wr = warp >> 2, wc = warp & 3;
    int m0 = blockIdx.y * BM, n0 = blockIdx.x * 128;

    float acc[MA][4][4];
#pragma unroll
    for (int i = 0; i < MA; i++)
#pragma unroll
        for (int j = 0; j < 4; j++)
#pragma unroll
            for (int l = 0; l < 4; l++) acc[i][j][l] = 0.f;

    auto issue = [&](int st, int kb) {
        float* as = Asm + st * ASZ;
        float* bs = Bsm + st * BSZ;
        if (!TA) {
#pragma unroll
            for (int f = 0; f < AF; f++) {
                int cid = tid + f * 256;
                int m = cid >> 2, kq = (cid & 3) * 4;
                cpa16(&as[m * 20 + kq], A + (long)(m0 + m) * lda + kb + kq);
            }
        } else {
#pragma unroll
            for (int f = 0; f < 2; f++) {
                int cid = tid + f * 256;
                int k = cid >> 5, mq = (cid & 31) * 4;
                cpa16(&as[k * 136 + mq], A + (long)(kb + k) * lda + m0 + mq);
            }
        }
#pragma unroll
        for (int f = 0; f < 2; f++) {
            int cid = tid + f * 256;
            int k = cid >> 5, nq = (cid & 31) * 4;
            cpa16(&bs[k * 136 + nq], Bm + (long)(kb + k) * ldb + n0 + nq);
        }
    };

    int nT = K >> 4;
#pragma unroll
    for (int s = 0; s < STG - 1; s++) {
        if (s < nT) issue(s, s << 4);
        CP_COMMIT();
    }

    for (int t = 0; t < nT; t++) {
        CP_WAIT1();
        __syncthreads();
        int nx = t + STG - 1;
        if (nx < nT) issue(nx % STG, nx << 4);
        CP_COMMIT();

        const float* as = Asm + (t % STG) * ASZ;
        const float* bs = Bsm + (t % STG) * BSZ;
#pragma unroll
        for (int s = 0; s < 2; s++) {
            int k0 = s * 8 + tg;
            unsigned af[MA][4], bf[4][2];
#pragma unroll
            for (int ma = 0; ma < MA; ma++) {
                int rb = wr * WM + ma * 16 + g;
                if (!TA) {
                    af[ma][0] = __float_as_uint(as[rb * 20 + k0]);
                    af[ma][1] = __float_as_uint(as[(rb + 8) * 20 + k0]);
                    af[ma][2] = __float_as_uint(as[rb * 20 + k0 + 4]);
                    af[ma][3] = __float_as_uint(as[(rb + 8) * 20 + k0 + 4]);
                } else {
                    af[ma][0] = __float_as_uint(as[k0 * 136 + rb]);
                    af[ma][1] = __float_as_uint(as[k0 * 136 + rb + 8]);
                    af[ma][2] = __float_as_uint(as[(k0 + 4) * 136 + rb]);
                    af[ma][3] = __float_as_uint(as[(k0 + 4) * 136 + rb + 8]);
                }
            }
#pragma unroll
            for (int na = 0; na < 4; na++) {
                int nb = wc * 32 + na * 8 + g;
                bf[na][0] = __float_as_uint(bs[k0 * 136 + nb]);
                bf[na][1] = __float_as_uint(bs[(k0 + 4) * 136 + nb]);
            }
#pragma unroll
            for (int na = 0; na < 4; na++)
#pragma unroll
                for (int ma = 0; ma < MA; ma++)
                    mma8(acc[ma][na], af[ma], bf[na][0], bf[na][1]);
        }
    }

    // epilogue
#pragma unroll
    for (int ma = 0; ma < MA; ma++) {
#pragma unroll
        for (int na = 0; na < 4; na++) {
#pragma unroll
            for (int i = 0; i < 4; i++) {
                int r = m0 + wr * WM + ma * 16 + g + ((i >= 2) ? 8 : 0);
                int c = n0 + wc * 32 + na * 8 + tg * 2 + (i & 1);
                float v = acc[ma][na][i];
                if (EPI == 0) {
                    C[(long)r * ldc + c] = v;
                } else if (EPI == 8) {
                    C[(long)r * ldc + c] = rndf(-v);
                } else if (EPI == 1) {
                    int b = r / SEQN, n = r % SEQN, h = c / DH, d = c % DH;
                    C[(long)(((b * NH + h) * SEQN) + n) * DH + d] = rndf(v);
                } else if (EPI == 2) {
                    x3[(long)r * ldc + c] = v;
                    C[(long)r * ldc + c]  = rndf(gelu_f(v));
                } else if (EPI == 3) {
                    float pred = v + x0[(long)r * DH + c];
                    int bh = r / SEQN, n = r % SEQN;
                    int b = bh / NH, h = bh % NH;
                    float lr = x2[(b * SEQN + n) * NH + h];
                    C[(long)r * DH + c] = rndf((2.0f / DH) * lr * (pred - x1[(long)r * DH + c]));
                } else if (EPI == 4) {
                    float a1 = x0[(long)r * ldc + c];
                    C[(long)r * ldc + c] = rndf(v * gelup_f(a1));
                } else if (EPI == 6) {
                    C[(long)r * ldc + c] = rndf(gelu_f(v));
                } else if (EPI == 7) {
                    float y = v + x0[(long)z * CH * DH + r * DH + c];
                    int bh = z / NC, cc = z % NC;
                    int n = cc * CH + r;
                    int b = bh / NH, h = bh % NH;
                    float gate = x1[(b * SEQN + n) * NH + h];
                    x3[(long)(b * SEQN + n) * DIM + h * DH + c] = rndf(y * gate);
                }
            }
        }
    }
}

// smem bytes per instantiation
constexpr int smem_bytes(int BM, bool TA) {
    return 3 * ((TA ? 16 * 136 : BM * 20) + 16 * 136) * 4;
}

// ---------------- launch ----------------
extern "C" void kernel_launch(void* const* d_in, const int* in_sizes, int n_in,
                              void* d_out, int out_size) {
    const float* seq   = (const float*)d_in[0];
    const float* gsto  = (const float*)d_in[1];
    const float* gret  = (const float*)d_in[2];
    const float* Wq    = (const float*)d_in[3];
    const float* Wk    = (const float*)d_in[4];
    const float* Wv    = (const float*)d_in[5];
    const float* Wa    = (const float*)d_in[6];
    const float* ba    = (const float*)d_in[7];
    const float* Wm    = (const float*)d_in[8];
    const float* Wd    = (const float*)d_in[9];
    const float* bd    = (const float*)d_in[10];
    const float* Wg    = (const float*)d_in[11];
    const float* Wc    = (const float*)d_in[12];
    const float* memg  = (const float*)d_in[13];
    const float* w1    = (const float*)d_in[14];
    const float* w2    = (const float*)d_in[15];
    float* out = (float*)d_out;

    float *p_xs, *p_xr, *p_KVQ, *p_lr, *p_gate, *p_Hs, *p_A1, *p_GA,
          *p_dA1, *p_dY, *p_dH, *p_sw1, *p_sw2, *p_sg, *p_Wp1, *p_Wp2, *p_Gp,
          *p_Hq, *p_R, *p_w1T, *p_w2T, *p_Wr, *p_Wcr, *p_w1r, *p_w2r;
    cudaGetSymbolAddress((void**)&p_xs, g_xs);
    cudaGetSymbolAddress((void**)&p_xr, g_xr);
    cudaGetSymbolAddress((void**)&p_KVQ, g_KVQ);
    cudaGetSymbolAddress((void**)&p_lr, g_lr);
    cudaGetSymbolAddress((void**)&p_gate, g_gate);
    cudaGetSymbolAddress((void**)&p_Hs, g_Hs);
    cudaGetSymbolAddress((void**)&p_A1, g_A1);
    cudaGetSymbolAddress((void**)&p_GA, g_GA);
    cudaGetSymbolAddress((void**)&p_dA1, g_dA1);
    cudaGetSymbolAddress((void**)&p_dY, g_dY);
    cudaGetSymbolAddress((void**)&p_dH, g_dH);
    cudaGetSymbolAddress((void**)&p_sw1, g_sw1);
    cudaGetSymbolAddress((void**)&p_sw2, g_sw2);
    cudaGetSymbolAddress((void**)&p_sg, g_sg);
    cudaGetSymbolAddress((void**)&p_Wp1, g_Wp1);
    cudaGetSymbolAddress((void**)&p_Wp2, g_Wp2);
    cudaGetSymbolAddress((void**)&p_Gp, g_Gp);
    cudaGetSymbolAddress((void**)&p_Hq, g_Hq);
    cudaGetSymbolAddress((void**)&p_R, g_R);
    cudaGetSymbolAddress((void**)&p_w1T, g_w1T);
    cudaGetSymbolAddress((void**)&p_w2T, g_w2T);
    cudaGetSymbolAddress((void**)&p_Wr, g_Wr);
    cudaGetSymbolAddress((void**)&p_Wcr, g_Wcr);
    cudaGetSymbolAddress((void**)&p_w1r, g_w1r);
    cudaGetSymbolAddress((void**)&p_w2r, g_w2r);

    float* p_K = p_KVQ;
    float* p_V = p_KVQ + RWSDH;
    float* p_Q = p_KVQ + 2 * RWSDH;

    // raise dynamic smem limits (idempotent host calls)
    constexpr int S128  = smem_bytes(128, false);
    constexpr int S128T = smem_bytes(128, true);
    constexpr int S64   = smem_bytes(64, false);
    cudaFuncSetAttribute(gmma<128, 1, false>, cudaFuncAttributeMaxDynamicSharedMemorySize, S128);
    cudaFuncSetAttribute(gmma<128, 2, false>, cudaFuncAttributeMaxDynamicSharedMemorySize, S128);
    cudaFuncSetAttribute(gmma<128, 3, false>, cudaFuncAttributeMaxDynamicSharedMemorySize, S128);
    cudaFuncSetAttribute(gmma<128, 4, false>, cudaFuncAttributeMaxDynamicSharedMemorySize, S128);
    cudaFuncSetAttribute(gmma<128, 0, false>, cudaFuncAttributeMaxDynamicSharedMemorySize, S128);
    cudaFuncSetAttribute(gmma<128, 8, true>,  cudaFuncAttributeMaxDynamicSharedMemorySize, S128T);
    cudaFuncSetAttribute(gmma<64, 6, false>,  cudaFuncAttributeMaxDynamicSharedMemorySize, S64);
    cudaFuncSetAttribute(gmma<64, 7, false>,  cudaFuncAttributeMaxDynamicSharedMemorySize, S64);

    // 0) rounded weight copies
    roundw_kernel<<<dim3(1024, 6), 256>>>(Wk, Wv, Wq, Wc, w1, w2);

    // 1) rmsnorm of seq -> xs, xr (rounded)
    rmsseq_kernel<<<TOK, 256>>>(seq, gsto, gret);

    // 2) fused QKV projections -> head-major K|V|Q
    gmma<128, 1, false><<<dim3(4, 32, 3), 256, S128>>>(p_xs, p_Wr, p_KVQ, DIM, DIM, DIM, 0,
        0, 0, 0, p_xr, p_Wr + DIM * DIM, p_Wr + 2 * DIM * DIM, nullptr);

    // 3) lr, gate ; 4) beta, alpha
    lrgate_kernel<<<TOK, 128>>>(Wa, ba, Wg);
    pool_kernel<<<Bb * NC, 512>>>(Wm, Wd, bd);

    // 5) Hs = rmsnorm(K, mem_g)
    rmshead_kernel<<<RWS, 128>>>(memg);

    // 6) weight transposes (rounded)
    transpose_kernel<<<(DH * DHID + 255) / 256, 256>>>(w1, p_w1T, DH, DHID);
    transpose_kernel<<<(DHID * DH + 255) / 256, 256>>>(w2, p_w2T, DHID, DH);

    // 7) A1 = Hs @ w1 ; GA = gelu(A1)
    gmma<128, 2, false><<<dim3(4, 128), 256, S128>>>(p_Hs, p_w1r, p_GA, DH, DH, DHID, DHID,
        0, 0, 0, nullptr, nullptr, nullptr, p_A1);
    // 8) pred = GA @ w2 + K -> dY
    gmma<128, 3, false><<<dim3(1, 128), 256, S128>>>(p_GA, p_w2r, p_dY, DHID, DHID, DH, DH,
        0, 0, 0, p_K, p_V, p_lr, nullptr);
    // 9) dA1 = (dY @ w2^T) * gelu'(A1)
    gmma<128, 4, false><<<dim3(4, 128), 256, S128>>>(p_dY, p_w2T, p_dA1, DH, DH, DHID, DHID,
        0, 0, 0, p_A1, nullptr, nullptr, nullptr);
    // 10) dH = dA1 @ w1^T
    gmma<128, 0, false><<<dim3(1, 128), 256, S128>>>(p_dA1, p_w1T, p_dH, DHID, DHID, DH, DH,
        0, 0, 0, nullptr, nullptr, nullptr, nullptr);

    // 11) sW1[z] = -Hs_z^T @ dA1_z   (K = CH = 64)
    gmma<128, 8, true><<<dim3(4, 1, NCHUNK), 256, S128T>>>(p_Hs, p_dA1, p_sw1, CH, DH, DHID, DHID,
        (long)CH * DH, (long)CH * DHID, (long)DH * DHID, nullptr, nullptr, nullptr, nullptr);
    // 12) sW2[z] = -GA_z^T @ dY_z
    gmma<128, 8, true><<<dim3(1, 4, NCHUNK), 256, S128T>>>(p_GA, p_dY, p_sw2, CH, DHID, DH, DH,
        (long)CH * DHID, (long)CH * DH, (long)DHID * DH, nullptr, nullptr, nullptr, nullptr);
    // 13) s_g
    sg_kernel<<<NCHUNK, 128>>>();

    // 14) scans -> causal w_prev per chunk (rounded)
    scan_kernel<<<dim3(DH * DHID / 256, BH), 256>>>(p_sw1, w1, p_Wp1, DH * DHID);
    scan_kernel<<<dim3(DHID * DH / 256, BH), 256>>>(p_sw2, w2, p_Wp2, DHID * DH);
    scan_kernel<<<dim3(1, BH), 256>>>(p_sg, memg, p_Gp, DH);

    // 15) Hq = rmsnorm(Q, Gp[chunk]) (rounded)
    hq_kernel<<<RWS, 128>>>();

    // 16) retrieval GEMM1: GAq = gelu(Hq @ Wp1[z])
    gmma<64, 6, false><<<dim3(4, 1, NCHUNK), 256, S64>>>(p_Hq, p_Wp1, p_GA, DH, DH, DHID, DHID,
        (long)CH * DH, (long)DH * DHID, (long)CH * DHID, nullptr, nullptr, nullptr, nullptr);
    // 17) retrieval GEMM2: y = GAq @ Wp2[z] + q ; gated -> g_R (rounded)
    gmma<64, 7, false><<<dim3(1, 1, NCHUNK), 256, S64>>>(p_GA, p_Wp2, p_R, DHID, DHID, DH, DH,
        (long)CH * DHID, (long)DHID * DH, 0, p_Q, p_gate, nullptr, p_R);
    // 18) out = R @ Wc
    gmma<128, 0, false><<<dim3(4, 32), 256, S128>>>(p_R, p_Wcr, out, DIM, DIM, DIM, DIM,
        0, 0, 0, nullptr, nullptr, nullptr, nullptr);
}

// round 5
// speedup vs baseline: 2.6166x; 1.0720x over previous
#include <cuda_runtime.h>
#include <math.h>

// ---------------- problem constants ----------------
constexpr int Bb   = 2;
constexpr int SEQN = 2048;
constexpr int DIM  = 512;
constexpr int NH   = 4;
constexpr int DH   = 128;
constexpr int CH   = 64;
constexpr int NC   = 32;
constexpr int DHID = 512;
constexpr int BH   = 8;
constexpr int TOK  = Bb * SEQN;      // 4096
constexpr int RWS  = BH * SEQN;      // 16384
constexpr int NCHUNK = BH * NC;      // 256
constexpr long RWSDH = (long)RWS * DH;

// ---------------- device scratch ----------------
__device__ float g_xs[TOK * DIM];
__device__ float g_xr[TOK * DIM];
__device__ float g_KVQ[3 * RWS * DH];          // K | V | Q
__device__ float g_lr[TOK * NH];
__device__ float g_gate[TOK * NH];
__device__ float g_beta[Bb * NC * NH];
__device__ float g_alpha[Bb * NC * NH];
__device__ float g_Hs[RWS * DH];
__device__ float g_rsK[RWS];
__device__ float g_A1[RWS * DHID];
__device__ float g_GA[RWS * DHID];
__device__ float g_dA1[RWS * DHID];
__device__ float g_dY[RWS * DH];
__device__ float g_sw1[NCHUNK * DH * DHID];
__device__ float g_sw2[NCHUNK * DHID * DH];
__device__ float g_sg[NCHUNK * DH];
__device__ float g_Wp1[NCHUNK * DH * DHID];
__device__ float g_Wp2[NCHUNK * DHID * DH];
__device__ float g_Gp[NCHUNK * DH];
__device__ float g_Hq[RWS * DH];
__device__ float g_R[TOK * DIM];
__device__ float g_w1T[DHID * DH];
__device__ float g_w2T[DH * DHID];
// tf32-rounded weight copies
__device__ float g_Wr[3 * DIM * DIM];          // Wk | Wv | Wq
__device__ float g_Wcr[DIM * DIM];
__device__ float g_w1r[DH * DHID];
__device__ float g_w2r[DHID * DH];

// ---------------- math helpers ----------------
__device__ __forceinline__ float sigmf(float x) { return 1.0f / (1.0f + expf(-x)); }
__device__ __forceinline__ float gelu_f(float x) {
    return 0.5f * x * (1.0f + erff(x * 0.70710678118654752f));
}
__device__ __forceinline__ float gelup_f(float x) {
    return 0.5f * (1.0f + erff(x * 0.70710678118654752f))
         + x * 0.3989422804014327f * expf(-0.5f * x * x);
}
__device__ __forceinline__ float rndf(float x) {      // round-to-nearest tf32
    asm("cvt.rna.tf32.f32 %0, %1;" : "=f"(x) : "f"(x));
    return x;
}
__device__ __forceinline__ void mma8(float c[4], const unsigned a[4],
                                     unsigned b0, unsigned b1) {
    asm volatile(
        "mma.sync.aligned.m16n8k8.row.col.f32.tf32.tf32.f32 "
        "{%0,%1,%2,%3},{%4,%5,%6,%7},{%8,%9},{%0,%1,%2,%3};"
        : "+f"(c[0]), "+f"(c[1]), "+f"(c[2]), "+f"(c[3])
        : "r"(a[0]), "r"(a[1]), "r"(a[2]), "r"(a[3]), "r"(b0), "r"(b1));
}
__device__ __forceinline__ void cpa16(float* s, const float* g) {
    unsigned sa = (unsigned)__cvta_generic_to_shared(s);
    asm volatile("cp.async.cg.shared.global [%0], [%1], 16;\n" :: "r"(sa), "l"(g));
}
#define CP_COMMIT() asm volatile("cp.async.commit_group;\n" ::: "memory")
#define CP_WAIT1()  asm volatile("cp.async.wait_group 1;\n" ::: "memory")

// ---------------- weight rounding ----------------
__global__ void roundw_kernel(const float* __restrict__ Wk, const float* __restrict__ Wv,
                              const float* __restrict__ Wq, const float* __restrict__ Wc,
                              const float* __restrict__ w1, const float* __restrict__ w2) {
    int z = blockIdx.y;
    int idx = blockIdx.x * 256 + threadIdx.x;
    if (z < 3) {
        if (idx < DIM * DIM) g_Wr[z * DIM * DIM + idx] = rndf(z == 0 ? Wk[idx] : z == 1 ? Wv[idx] : Wq[idx]);
    } else if (z == 3) {
        if (idx < DIM * DIM) g_Wcr[idx] = rndf(Wc[idx]);
    } else if (z == 4) {
        if (idx < DH * DHID) g_w1r[idx] = rndf(w1[idx]);
    } else {
        if (idx < DHID * DH) g_w2r[idx] = rndf(w2[idx]);
    }
}

// ------- rmsnorm over DIM=512 (xs, xr) + fused lr/gate projections -------
__global__ void rmsseq_kernel(const float* __restrict__ seq,
                              const float* __restrict__ gs,
                              const float* __restrict__ gr,
                              const float* __restrict__ Wa,
                              const float* __restrict__ ba,
                              const float* __restrict__ Wg) {
    int t = blockIdx.x;
    int tid = threadIdx.x;
    int lane = tid & 31, warp = tid >> 5;
    float x0 = seq[t * DIM + tid];
    float x1 = seq[t * DIM + tid + 256];
    float ss = x0 * x0 + x1 * x1;
    for (int o = 16; o; o >>= 1) ss += __shfl_down_sync(0xffffffffu, ss, o);
    __shared__ float sm[8];
    __shared__ float sma[8][4], smg[8][4];
    if (lane == 0) sm[warp] = ss;
    __syncthreads();
    float tot = 0.f;
#pragma unroll
    for (int i = 0; i < 8; i++) tot += sm[i];
    float rs = rsqrtf(tot * (1.0f / DIM) + 1e-6f);
    float a0 = x0 * rs * gs[tid],       a1 = x1 * rs * gs[tid + 256];
    float r0 = x0 * rs * gr[tid],       r1 = x1 * rs * gr[tid + 256];
    g_xs[t * DIM + tid]       = rndf(a0);
    g_xs[t * DIM + tid + 256] = rndf(a1);
    g_xr[t * DIM + tid]       = rndf(r0);
    g_xr[t * DIM + tid + 256] = rndf(r1);
    // fused lr/gate: 4-head dot products
    float pa[4], pg[4];
#pragma unroll
    for (int h = 0; h < 4; h++) {
        pa[h] = a0 * Wa[tid * NH + h] + a1 * Wa[(tid + 256) * NH + h];
        pg[h] = r0 * Wg[tid * NH + h] + r1 * Wg[(tid + 256) * NH + h];
    }
#pragma unroll
    for (int o = 16; o; o >>= 1)
#pragma unroll
        for (int h = 0; h < 4; h++) {
            pa[h] += __shfl_down_sync(0xffffffffu, pa[h], o);
            pg[h] += __shfl_down_sync(0xffffffffu, pg[h], o);
        }
    if (lane == 0)
#pragma unroll
        for (int h = 0; h < 4; h++) { sma[warp][h] = pa[h]; smg[warp][h] = pg[h]; }
    __syncthreads();
    if (tid < 4) {
        float sa = 0.f, sg2 = 0.f;
#pragma unroll
        for (int i = 0; i < 8; i++) { sa += sma[i][tid]; sg2 += smg[i][tid]; }
        g_lr[t * NH + tid]   = sigmf(sa + ba[tid]);
        g_gate[t * NH + tid] = sigmf(sg2);
    }
}

// ---------------- pooled chunk stats -> beta, alpha ----------------
__global__ void pool_kernel(const float* __restrict__ Wm, const float* __restrict__ Wd,
                            const float* __restrict__ bd) {
    int bc = blockIdx.x;
    int b = bc / NC, c = bc % NC;
    __shared__ float pooled[DIM];
    int tid = threadIdx.x;
    int t0 = b * SEQN + c * CH;
    float s = 0.f;
    for (int i = 0; i < CH; i++) s += g_xs[(t0 + i) * DIM + tid];
    pooled[tid] = s * (1.0f / CH);
    __syncthreads();
    if (tid < 128) {
        int lane = tid & 31, h = tid >> 5;
        float am = 0.f, ad = 0.f;
        for (int d = lane; d < DIM; d += 32) {
            am += pooled[d] * Wm[d * NH + h];
            ad += pooled[d] * Wd[d * NH + h];
        }
        for (int o = 16; o; o >>= 1) {
            am += __shfl_down_sync(0xffffffffu, am, o);
            ad += __shfl_down_sync(0xffffffffu, ad, o);
        }
        if (lane == 0) {
            g_beta[bc * NH + h]  = sigmf(am);
            g_alpha[bc * NH + h] = 1.0f - sigmf(ad + bd[h]);
        }
    }
}

// ---------------- rmsnorm over DH=128 for K -> Hs ----------------
__global__ void rmshead_kernel(const float* __restrict__ memg) {
    int r = blockIdx.x;
    int d = threadIdx.x;
    float x = g_KVQ[(long)r * DH + d];          // K
    float ss = x * x;
    for (int o = 16; o; o >>= 1) ss += __shfl_down_sync(0xffffffffu, ss, o);
    __shared__ float sm[4];
    if ((d & 31) == 0) sm[d >> 5] = ss;
    __syncthreads();
    float tot = sm[0] + sm[1] + sm[2] + sm[3];
    float rs = rsqrtf(tot * (1.0f / DH) + 1e-6f);
    g_Hs[r * DH + d] = rndf(x * rs * memg[d]);
    if (d == 0) g_rsK[r] = rs;
}

// ---------------- rmsnorm for Q with per-chunk Gp -> Hq ----------------
__global__ void hq_kernel() {
    int r = blockIdx.x;
    int d = threadIdx.x;
    int bh = r / SEQN, n = r % SEQN, c = n / CH;
    float x = g_KVQ[2 * RWSDH + (long)r * DH + d];   // Q
    float ss = x * x;
    for (int o = 16; o; o >>= 1) ss += __shfl_down_sync(0xffffffffu, ss, o);
    __shared__ float sm[4];
    if ((d & 31) == 0) sm[d >> 5] = ss;
    __syncthreads();
    float tot = sm[0] + sm[1] + sm[2] + sm[3];
    float rs = rsqrtf(tot * (1.0f / DH) + 1e-6f);
    g_Hq[r * DH + d] = rndf(x * rs * g_Gp[(bh * NC + c) * DH + d]);
}

// ---------------- small transpose (rounded) ----------------
__global__ void transpose_kernel(const float* __restrict__ in, float* __restrict__ out,
                                 int R, int C) {
    int idx = blockIdx.x * 256 + threadIdx.x;
    if (idx < R * C) {
        int r = idx / C, c = idx % C;
        out[c * R + r] = rndf(in[idx]);
    }
}

// ---------------- momentum + decay scans ----------------
__global__ void scan4_kernel(const float4* __restrict__ s, const float4* __restrict__ init,
                             float4* __restrict__ wprev, int sz4) {
    int bh = blockIdx.y;
    int e = blockIdx.x * 256 + threadIdx.x;
    if (e >= sz4) return;
    int b = bh / NH, h = bh % NH;
    float4 m = make_float4(0.f, 0.f, 0.f, 0.f);
    float4 w = init[e];
    float4 o;
    o.x = rndf(w.x); o.y = rndf(w.y); o.z = rndf(w.z); o.w = rndf(w.w);
    wprev[(long)(bh * NC) * sz4 + e] = o;
    for (int t = 0; t < NC; t++) {
        float beta  = g_beta[(b * NC + t) * NH + h];
        float alpha = g_alpha[(b * NC + t) * NH + h];
        float4 sv = s[(long)(bh * NC + t) * sz4 + e];
        m.x = beta * m.x + sv.x; m.y = beta * m.y + sv.y;
        m.z = beta * m.z + sv.z; m.w = beta * m.w + sv.w;
        w.x = alpha * w.x + m.x; w.y = alpha * w.y + m.y;
        w.z = alpha * w.z + m.z; w.w = alpha * w.w + m.w;
        if (t < NC - 1) {
            o.x = rndf(w.x); o.y = rndf(w.y); o.z = rndf(w.z); o.w = rndf(w.w);
            wprev[(long)(bh * NC + t + 1) * sz4 + e] = o;
        }
    }
}
__global__ void scan_kernel(const float* __restrict__ s, const float* __restrict__ init,
                            float* __restrict__ wprev, int sz) {
    int bh = blockIdx.y;
    int e = blockIdx.x * 256 + threadIdx.x;
    if (e >= sz) return;
    int b = bh / NH, h = bh % NH;
    float m = 0.f, w = init[e];
    wprev[(long)(bh * NC) * sz + e] = rndf(w);
    for (int t = 0; t < NC; t++) {
        float beta  = g_beta[(b * NC + t) * NH + h];
        float alpha = g_alpha[(b * NC + t) * NH + h];
        m = beta * m + s[(long)(bh * NC + t) * sz + e];
        w = alpha * w + m;
        if (t < NC - 1) wprev[(long)(bh * NC + t + 1) * sz + e] = rndf(w);
    }
}

// ======= tf32 tensor-core GEMM, BMx128 tile, cp.async 3-stage pipeline =======
// EPI: 0 plain, 1 fused QKV, 2 store A1 + gelu, 3 pred->dY, 4 *gelu'(A1),
//      6 gelu only, 7 gated retrieval output, 8 negate,
//      9 fused dH->s_g column reduction (BM=64, block == chunk)
template <int BM, int EPI, bool TA>
__global__ void __launch_bounds__(256, 2) gmma(
    const float* __restrict__ A, const float* __restrict__ Bm, float* __restrict__ C,
    int K, int lda, int ldb, int ldc,
    long sA, long sB, long sC,
    const float* __restrict__ x0, const float* __restrict__ x1,
    const float* __restrict__ x2, float* __restrict__ x3) {
    constexpr int STG = 3;
    constexpr int WM  = BM / 2;
    constexpr int MA  = WM / 16;
    constexpr int AF  = BM / 64;
    constexpr int ASZ = TA ? 16 * 136 : BM * 20;
    constexpr int BSZ = 16 * 136;

    int z = blockIdx.z;
    if (EPI == 1) {
        if (z == 2) A = x0;
        Bm = (z == 0) ? Bm : (z == 1) ? x1 : x2;
        C += (long)z * RWSDH;
    } else {
        A += (long)z * sA; Bm += (long)z * sB; C += (long)z * sC;
    }

    extern __shared__ float smp[];
    float* Asm = smp;
    float* Bsm = smp + STG * ASZ;
    __shared__ float sgacc[128];

    int tid = threadIdx.x;
    int warp = tid >> 5, lane = tid & 31;
    int g = lane >> 2, tg = lane & 3;
    int wr = warp >> 2, wc = warp & 3;
    int m0 = blockIdx.y * BM, n0 = blockIdx.x * 128;

    float acc[MA][4][4];
#pragma unroll
    for (int i = 0; i < MA; i++)
#pragma unroll
        for (int j = 0; j < 4; j++)
#pragma unroll
            for (int l = 0; l < 4; l++) acc[i][j][l] = 0.f;

    auto issue = [&](int st, int kb) {
        float* as = Asm + st * ASZ;
        float* bs = Bsm + st * BSZ;
        if (!TA) {
#pragma unroll
            for (int f = 0; f < AF; f++) {
                int cid = tid + f * 256;
                int m = cid >> 2, kq = (cid & 3) * 4;
                cpa16(&as[m * 20 + kq], A + (long)(m0 + m) * lda + kb + kq);
            }
        } else {
#pragma unroll
            for (int f = 0; f < 2; f++) {
                int cid = tid + f * 256;
                int k = cid >> 5, mq = (cid & 31) * 4;
                cpa16(&as[k * 136 + mq], A + (long)(kb + k) * lda + m0 + mq);
            }
        }
#pragma unroll
        for (int f = 0; f < 2; f++) {
            int cid = tid + f * 256;
            int k = cid >> 5, nq = (cid & 31) * 4;
            cpa16(&bs[k * 136 + nq], Bm + (long)(kb + k) * ldb + n0 + nq);
        }
    };

    if (EPI == 9) {
        if (tid < 128) sgacc[tid] = 0.f;
    }

    int nT = K >> 4;
#pragma unroll
    for (int s = 0; s < STG - 1; s++) {
        if (s < nT) issue(s, s << 4);
        CP_COMMIT();
    }

    for (int t = 0; t < nT; t++) {
        CP_WAIT1();
        __syncthreads();
        int nx = t + STG - 1;
        if (nx < nT) issue(nx % STG, nx << 4);
        CP_COMMIT();

        const float* as = Asm + (t % STG) * ASZ;
        const float* bs = Bsm + (t % STG) * BSZ;
#pragma unroll
        for (int s = 0; s < 2; s++) {
            int k0 = s * 8 + tg;
            unsigned af[MA][4], bf[4][2];
#pragma unroll
            for (int ma = 0; ma < MA; ma++) {
                int rb = wr * WM + ma * 16 + g;
                if (!TA) {
                    af[ma][0] = __float_as_uint(as[rb * 20 + k0]);
                    af[ma][1] = __float_as_uint(as[(rb + 8) * 20 + k0]);
                    af[ma][2] = __float_as_uint(as[rb * 20 + k0 + 4]);
                    af[ma][3] = __float_as_uint(as[(rb + 8) * 20 + k0 + 4]);
                } else {
                    af[ma][0] = __float_as_uint(as[k0 * 136 + rb]);
                    af[ma][1] = __float_as_uint(as[k0 * 136 + rb + 8]);
                    af[ma][2] = __float_as_uint(as[(k0 + 4) * 136 + rb]);
                    af[ma][3] = __float_as_uint(as[(k0 + 4) * 136 + rb + 8]);
                }
            }
#pragma unroll
            for (int na = 0; na < 4; na++) {
                int nb = wc * 32 + na * 8 + g;
                bf[na][0] = __float_as_uint(bs[k0 * 136 + nb]);
                bf[na][1] = __float_as_uint(bs[(k0 + 4) * 136 + nb]);
            }
#pragma unroll
            for (int na = 0; na < 4; na++)
#pragma unroll
                for (int ma = 0; ma < MA; ma++)
                    mma8(acc[ma][na], af[ma], bf[na][0], bf[na][1]);
        }
    }

    if (EPI == 9) {
        // dH = acc; s_g[chunk, c] = -sum_rows dH[r,c] * K[r,c] * rsK[r]
#pragma unroll
        for (int na = 0; na < 4; na++) {
#pragma unroll
            for (int half = 0; half < 2; half++) {
                int c = n0 + wc * 32 + na * 8 + tg * 2 + half;
                float csum = 0.f;
#pragma unroll
                for (int ma = 0; ma < MA; ma++)
#pragma unroll
                    for (int ih = 0; ih < 2; ih++) {
                        int i = ih * 2 + half;
                        int r = m0 + wr * WM + ma * 16 + g + ih * 8;
                        csum += acc[ma][na][i] * x0[(long)r * DH + c] * x1[r];
                    }
                for (int o = 16; o >= 4; o >>= 1)
                    csum += __shfl_down_sync(0xffffffffu, csum, o);
                if (g == 0) atomicAdd(&sgacc[wc * 32 + na * 8 + tg * 2 + half], csum);
            }
        }
        __syncthreads();
        if (tid < 128) C[(long)blockIdx.y * DH + tid] = -sgacc[tid];
        return;
    }

    // epilogue
#pragma unroll
    for (int ma = 0; ma < MA; ma++) {
#pragma unroll
        for (int na = 0; na < 4; na++) {
#pragma unroll
            for (int i = 0; i < 4; i++) {
                int r = m0 + wr * WM + ma * 16 + g + ((i >= 2) ? 8 : 0);
                int c = n0 + wc * 32 + na * 8 + tg * 2 + (i & 1);
                float v = acc[ma][na][i];
                if (EPI == 0) {
                    C[(long)r * ldc + c] = v;
                } else if (EPI == 8) {
                    C[(long)r * ldc + c] = rndf(-v);
                } else if (EPI == 1) {
                    int b = r / SEQN, n = r % SEQN, h = c / DH, d = c % DH;
                    C[(long)(((b * NH + h) * SEQN) + n) * DH + d] = rndf(v);
                } else if (EPI == 2) {
                    x3[(long)r * ldc + c] = v;
                    C[(long)r * ldc + c]  = rndf(gelu_f(v));
                } else if (EPI == 3) {
                    float pred = v + x0[(long)r * DH + c];
                    int bh = r / SEQN, n = r % SEQN;
                    int b = bh / NH, h = bh % NH;
                    float lr = x2[(b * SEQN + n) * NH + h];
                    C[(long)r * DH + c] = rndf((2.0f / DH) * lr * (pred - x1[(long)r * DH + c]));
                } else if (EPI == 4) {
                    float a1 = x0[(long)r * ldc + c];
                    C[(long)r * ldc + c] = rndf(v * gelup_f(a1));
                } else if (EPI == 6) {
                    C[(long)r * ldc + c] = rndf(gelu_f(v));
                } else if (EPI == 7) {
                    float y = v + x0[(long)z * CH * DH + r * DH + c];
                    int bh = z / NC, cc = z % NC;
                    int n = cc * CH + r;
                    int b = bh / NH, h = bh % NH;
                    float gate = x1[(b * SEQN + n) * NH + h];
                    x3[(long)(b * SEQN + n) * DIM + h * DH + c] = rndf(y * gate);
                }
            }
        }
    }
}

constexpr int smem_bytes(int BM, bool TA) {
    return 3 * ((TA ? 16 * 136 : BM * 20) + 16 * 136) * 4;
}

// ---------------- launch ----------------
extern "C" void kernel_launch(void* const* d_in, const int* in_sizes, int n_in,
                              void* d_out, int out_size) {
    const float* seq   = (const float*)d_in[0];
    const float* gsto  = (const float*)d_in[1];
    const float* gret  = (const float*)d_in[2];
    const float* Wq    = (const float*)d_in[3];
    const float* Wk    = (const float*)d_in[4];
    const float* Wv    = (const float*)d_in[5];
    const float* Wa    = (const float*)d_in[6];
    const float* ba    = (const float*)d_in[7];
    const float* Wm    = (const float*)d_in[8];
    const float* Wd    = (const float*)d_in[9];
    const float* bd    = (const float*)d_in[10];
    const float* Wg    = (const float*)d_in[11];
    const float* Wc    = (const float*)d_in[12];
    const float* memg  = (const float*)d_in[13];
    const float* w1    = (const float*)d_in[14];
    const float* w2    = (const float*)d_in[15];
    float* out = (float*)d_out;

    float *p_xs, *p_xr, *p_KVQ, *p_lr, *p_gate, *p_Hs, *p_rsK, *p_A1, *p_GA,
          *p_dA1, *p_dY, *p_sw1, *p_sw2, *p_sg, *p_Wp1, *p_Wp2, *p_Gp,
          *p_Hq, *p_R, *p_w1T, *p_w2T, *p_Wr, *p_Wcr, *p_w1r, *p_w2r;
    cudaGetSymbolAddress((void**)&p_xs, g_xs);
    cudaGetSymbolAddress((void**)&p_xr, g_xr);
    cudaGetSymbolAddress((void**)&p_KVQ, g_KVQ);
    cudaGetSymbolAddress((void**)&p_lr, g_lr);
    cudaGetSymbolAddress((void**)&p_gate, g_gate);
    cudaGetSymbolAddress((void**)&p_Hs, g_Hs);
    cudaGetSymbolAddress((void**)&p_rsK, g_rsK);
    cudaGetSymbolAddress((void**)&p_A1, g_A1);
    cudaGetSymbolAddress((void**)&p_GA, g_GA);
    cudaGetSymbolAddress((void**)&p_dA1, g_dA1);
    cudaGetSymbolAddress((void**)&p_dY, g_dY);
    cudaGetSymbolAddress((void**)&p_sw1, g_sw1);
    cudaGetSymbolAddress((void**)&p_sw2, g_sw2);
    cudaGetSymbolAddress((void**)&p_sg, g_sg);
    cudaGetSymbolAddress((void**)&p_Wp1, g_Wp1);
    cudaGetSymbolAddress((void**)&p_Wp2, g_Wp2);
    cudaGetSymbolAddress((void**)&p_Gp, g_Gp);
    cudaGetSymbolAddress((void**)&p_Hq, g_Hq);
    cudaGetSymbolAddress((void**)&p_R, g_R);
    cudaGetSymbolAddress((void**)&p_w1T, g_w1T);
    cudaGetSymbolAddress((void**)&p_w2T, g_w2T);
    cudaGetSymbolAddress((void**)&p_Wr, g_Wr);
    cudaGetSymbolAddress((void**)&p_Wcr, g_Wcr);
    cudaGetSymbolAddress((void**)&p_w1r, g_w1r);
    cudaGetSymbolAddress((void**)&p_w2r, g_w2r);

    float* p_K = p_KVQ;
    float* p_V = p_KVQ + RWSDH;
    float* p_Q = p_KVQ + 2 * RWSDH;

    constexpr int S128  = smem_bytes(128, false);
    constexpr int S128T = smem_bytes(128, true);
    constexpr int S64   = smem_bytes(64, false);
    cudaFuncSetAttribute(gmma<128, 1, false>, cudaFuncAttributeMaxDynamicSharedMemorySize, S128);
    cudaFuncSetAttribute(gmma<128, 2, false>, cudaFuncAttributeMaxDynamicSharedMemorySize, S128);
    cudaFuncSetAttribute(gmma<64, 3, false>,  cudaFuncAttributeMaxDynamicSharedMemorySize, S64);
    cudaFuncSetAttribute(gmma<128, 4, false>, cudaFuncAttributeMaxDynamicSharedMemorySize, S128);
    cudaFuncSetAttribute(gmma<64, 9, false>,  cudaFuncAttributeMaxDynamicSharedMemorySize, S64);
    cudaFuncSetAttribute(gmma<128, 0, false>, cudaFuncAttributeMaxDynamicSharedMemorySize, S128);
    cudaFuncSetAttribute(gmma<128, 8, true>,  cudaFuncAttributeMaxDynamicSharedMemorySize, S128T);
    cudaFuncSetAttribute(gmma<64, 6, false>,  cudaFuncAttributeMaxDynamicSharedMemorySize, S64);
    cudaFuncSetAttribute(gmma<64, 7, false>,  cudaFuncAttributeMaxDynamicSharedMemorySize, S64);

    // 0) rounded weight copies
    roundw_kernel<<<dim3(1024, 6), 256>>>(Wk, Wv, Wq, Wc, w1, w2);

    // 1) rmsnorm of seq -> xs, xr (+ fused lr/gate)
    rmsseq_kernel<<<TOK, 256>>>(seq, gsto, gret, Wa, ba, Wg);

    // 2) fused QKV projections -> head-major K|V|Q
    gmma<128, 1, false><<<dim3(4, 32, 3), 256, S128>>>(p_xs, p_Wr, p_KVQ, DIM, DIM, DIM, 0,
        0, 0, 0, p_xr, p_Wr + DIM * DIM, p_Wr + 2 * DIM * DIM, nullptr);

    // 4) beta, alpha
    pool_kernel<<<Bb * NC, 512>>>(Wm, Wd, bd);

    // 5) Hs = rmsnorm(K, mem_g)
    rmshead_kernel<<<RWS, 128>>>(memg);

    // 6) weight transposes (rounded)
    transpose_kernel<<<(DH * DHID + 255) / 256, 256>>>(w1, p_w1T, DH, DHID);
    transpose_kernel<<<(DHID * DH + 255) / 256, 256>>>(w2, p_w2T, DHID, DH);

    // 7) A1 = Hs @ w1 ; GA = gelu(A1)
    gmma<128, 2, false><<<dim3(4, 128), 256, S128>>>(p_Hs, p_w1r, p_GA, DH, DH, DHID, DHID,
        0, 0, 0, nullptr, nullptr, nullptr, p_A1);
    // 8) pred = GA @ w2 + K -> dY (BM=64: 256-block wave)
    gmma<64, 3, false><<<dim3(1, 256), 256, S64>>>(p_GA, p_w2r, p_dY, DHID, DHID, DH, DH,
        0, 0, 0, p_K, p_V, p_lr, nullptr);
    // 9) dA1 = (dY @ w2^T) * gelu'(A1)
    gmma<128, 4, false><<<dim3(4, 128), 256, S128>>>(p_dY, p_w2T, p_dA1, DH, DH, DHID, DHID,
        0, 0, 0, p_A1, nullptr, nullptr, nullptr);
    // 10+13) s_g = -colsum(dH * K * rsK) fused into dH GEMM (block == chunk)
    gmma<64, 9, false><<<dim3(1, 256), 256, S64>>>(p_dA1, p_w1T, p_sg, DHID, DHID, DH, DH,
        0, 0, 0, p_K, p_rsK, nullptr, nullptr);

    // 11) sW1[z] = -Hs_z^T @ dA1_z
    gmma<128, 8, true><<<dim3(4, 1, NCHUNK), 256, S128T>>>(p_Hs, p_dA1, p_sw1, CH, DH, DHID, DHID,
        (long)CH * DH, (long)CH * DHID, (long)DH * DHID, nullptr, nullptr, nullptr, nullptr);
    // 12) sW2[z] = -GA_z^T @ dY_z
    gmma<128, 8, true><<<dim3(1, 4, NCHUNK), 256, S128T>>>(p_GA, p_dY, p_sw2, CH, DHID, DH, DH,
        (long)CH * DHID, (long)CH * DH, (long)DHID * DH, nullptr, nullptr, nullptr, nullptr);

    // 14) scans -> causal w_prev per chunk (rounded)
    scan4_kernel<<<dim3(DH * DHID / 1024, BH), 256>>>((const float4*)p_sw1, (const float4*)w1,
                                                      (float4*)p_Wp1, DH * DHID / 4);
    scan4_kernel<<<dim3(DHID * DH / 1024, BH), 256>>>((const float4*)p_sw2, (const float4*)w2,
                                                      (float4*)p_Wp2, DHID * DH / 4);
    scan_kernel<<<dim3(1, BH), 256>>>(p_sg, memg, p_Gp, DH);

    // 15) Hq = rmsnorm(Q, Gp[chunk])
    hq_kernel<<<RWS, 128>>>();

    // 16) retrieval GEMM1: GAq = gelu(Hq @ Wp1[z])
    gmma<64, 6, false><<<dim3(4, 1, NCHUNK), 256, S64>>>(p_Hq, p_Wp1, p_GA, DH, DH, DHID, DHID,
        (long)CH * DH, (long)DH * DHID, (long)CH * DHID, nullptr, nullptr, nullptr, nullptr);
    // 17) retrieval GEMM2: y = GAq @ Wp2[z] + q ; gated -> g_R
    gmma<64, 7, false><<<dim3(1, 1, NCHUNK), 256, S64>>>(p_GA, p_Wp2, p_R, DHID, DHID, DH, DH,
        (long)CH * DHID, (long)DHID * DH, 0, p_Q, p_gate, nullptr, p_R);
    // 18) out = R @ Wc
    gmma<128, 0, false><<<dim3(4, 32), 256, S128>>>(p_R, p_Wcr, out, DIM, DIM, DIM, DIM,
        0, 0, 0, nullptr, nullptr, nullptr, nullptr);
}

// round 6
// speedup vs baseline: 2.6890x; 1.0277x over previous
#include <cuda_runtime.h>
#include <math.h>

// ---------------- problem constants ----------------
constexpr int Bb   = 2;
constexpr int SEQN = 2048;
constexpr int DIM  = 512;
constexpr int NH   = 4;
constexpr int DH   = 128;
constexpr int CH   = 64;
constexpr int NC   = 32;
constexpr int DHID = 512;
constexpr int BH   = 8;
constexpr int TOK  = Bb * SEQN;      // 4096
constexpr int RWS  = BH * SEQN;      // 16384
constexpr int NCHUNK = BH * NC;      // 256
constexpr long RWSDH = (long)RWS * DH;

// ---------------- device scratch ----------------
__device__ float g_xs[TOK * DIM];
__device__ float g_xr[TOK * DIM];
__device__ float g_KVQ[3 * RWS * DH];          // K | V | Q
__device__ float g_lr[TOK * NH];
__device__ float g_gate[TOK * NH];
__device__ float g_beta[Bb * NC * NH];
__device__ float g_alpha[Bb * NC * NH];
__device__ float g_Hs[RWS * DH];
__device__ float g_rsK[RWS];
__device__ float g_A1[RWS * DHID];
__device__ float g_GA[RWS * DHID];
__device__ float g_dA1[RWS * DHID];
__device__ float g_dY[RWS * DH];
__device__ float g_sw1[NCHUNK * DH * DHID];
__device__ float g_sw2[NCHUNK * DHID * DH];
__device__ float g_sg[NCHUNK * DH];
__device__ float g_Wp1[NCHUNK * DH * DHID];
__device__ float g_Wp2[NCHUNK * DHID * DH];
__device__ float g_Gp[NCHUNK * DH];
__device__ float g_Hq[RWS * DH];
__device__ float g_R[TOK * DIM];
__device__ float g_w1T[DHID * DH];
__device__ float g_w2T[DH * DHID];
__device__ float g_poolp[Bb * NC * 8 * DIM];   // pooled partials
// tf32-rounded weight copies
__device__ float g_Wr[3 * DIM * DIM];          // Wk | Wv | Wq
__device__ float g_Wcr[DIM * DIM];
__device__ float g_w1r[DH * DHID];
__device__ float g_w2r[DHID * DH];

// ---------------- math helpers ----------------
__device__ __forceinline__ float sigmf(float x) { return 1.0f / (1.0f + expf(-x)); }
__device__ __forceinline__ float gelu_f(float x) {
    return 0.5f * x * (1.0f + erff(x * 0.70710678118654752f));
}
__device__ __forceinline__ float gelup_f(float x) {
    return 0.5f * (1.0f + erff(x * 0.70710678118654752f))
         + x * 0.3989422804014327f * expf(-0.5f * x * x);
}
__device__ __forceinline__ float rndf(float x) {      // round-to-nearest tf32
    asm("cvt.rna.tf32.f32 %0, %1;" : "=f"(x) : "f"(x));
    return x;
}
__device__ __forceinline__ float4 rnd4(float4 v) {
    v.x = rndf(v.x); v.y = rndf(v.y); v.z = rndf(v.z); v.w = rndf(v.w);
    return v;
}
__device__ __forceinline__ void mma8(float c[4], const unsigned a[4],
                                     unsigned b0, unsigned b1) {
    asm volatile(
        "mma.sync.aligned.m16n8k8.row.col.f32.tf32.tf32.f32 "
        "{%0,%1,%2,%3},{%4,%5,%6,%7},{%8,%9},{%0,%1,%2,%3};"
        : "+f"(c[0]), "+f"(c[1]), "+f"(c[2]), "+f"(c[3])
        : "r"(a[0]), "r"(a[1]), "r"(a[2]), "r"(a[3]), "r"(b0), "r"(b1));
}
__device__ __forceinline__ void cpa16(float* s, const float* g) {
    unsigned sa = (unsigned)__cvta_generic_to_shared(s);
    asm volatile("cp.async.cg.shared.global [%0], [%1], 16;\n" :: "r"(sa), "l"(g));
}
#define CP_COMMIT() asm volatile("cp.async.commit_group;\n" ::: "memory")
#define CP_WAIT1()  asm volatile("cp.async.wait_group 1;\n" ::: "memory")

// --------- prep: rounded weight copies + rounded weight transposes ---------
__global__ void prep_kernel(const float* __restrict__ Wk, const float* __restrict__ Wv,
                            const float* __restrict__ Wq, const float* __restrict__ Wc,
                            const float* __restrict__ w1, const float* __restrict__ w2) {
    int z = blockIdx.y;
    int idx = blockIdx.x * 256 + threadIdx.x;
    if (z < 3) {
        if (idx < DIM * DIM) g_Wr[z * DIM * DIM + idx] = rndf(z == 0 ? Wk[idx] : z == 1 ? Wv[idx] : Wq[idx]);
    } else if (z == 3) {
        if (idx < DIM * DIM) g_Wcr[idx] = rndf(Wc[idx]);
    } else if (z == 4) {
        if (idx < DH * DHID) g_w1r[idx] = rndf(w1[idx]);
    } else if (z == 5) {
        if (idx < DHID * DH) g_w2r[idx] = rndf(w2[idx]);
    } else if (z == 6) {
        if (idx < DH * DHID) {
            int r = idx / DHID, c = idx % DHID;
            g_w1T[c * DH + r] = rndf(w1[idx]);
        }
    } else {
        if (idx < DHID * DH) {
            int r = idx / DH, c = idx % DH;
            g_w2T[c * DHID + r] = rndf(w2[idx]);
        }
    }
}

// ------- rmsnorm over DIM=512 (xs, xr) + fused lr/gate projections -------
__global__ void rmsseq_kernel(const float* __restrict__ seq,
                              const float* __restrict__ gs,
                              const float* __restrict__ gr,
                              const float* __restrict__ Wa,
                              const float* __restrict__ ba,
                              const float* __restrict__ Wg) {
    int t = blockIdx.x;
    int tid = threadIdx.x;
    int lane = tid & 31, warp = tid >> 5;
    float x0 = seq[t * DIM + tid];
    float x1 = seq[t * DIM + tid + 256];
    float ss = x0 * x0 + x1 * x1;
    for (int o = 16; o; o >>= 1) ss += __shfl_down_sync(0xffffffffu, ss, o);
    __shared__ float sm[8];
    __shared__ float sma[8][4], smg[8][4];
    if (lane == 0) sm[warp] = ss;
    __syncthreads();
    float tot = 0.f;
#pragma unroll
    for (int i = 0; i < 8; i++) tot += sm[i];
    float rs = rsqrtf(tot * (1.0f / DIM) + 1e-6f);
    float a0 = x0 * rs * gs[tid],       a1 = x1 * rs * gs[tid + 256];
    float r0 = x0 * rs * gr[tid],       r1 = x1 * rs * gr[tid + 256];
    g_xs[t * DIM + tid]       = rndf(a0);
    g_xs[t * DIM + tid + 256] = rndf(a1);
    g_xr[t * DIM + tid]       = rndf(r0);
    g_xr[t * DIM + tid + 256] = rndf(r1);
    float pa[4], pg[4];
#pragma unroll
    for (int h = 0; h < 4; h++) {
        pa[h] = a0 * Wa[tid * NH + h] + a1 * Wa[(tid + 256) * NH + h];
        pg[h] = r0 * Wg[tid * NH + h] + r1 * Wg[(tid + 256) * NH + h];
    }
#pragma unroll
    for (int o = 16; o; o >>= 1)
#pragma unroll
        for (int h = 0; h < 4; h++) {
            pa[h] += __shfl_down_sync(0xffffffffu, pa[h], o);
            pg[h] += __shfl_down_sync(0xffffffffu, pg[h], o);
        }
    if (lane == 0)
#pragma unroll
        for (int h = 0; h < 4; h++) { sma[warp][h] = pa[h]; smg[warp][h] = pg[h]; }
    __syncthreads();
    if (tid < 4) {
        float sa = 0.f, sg2 = 0.f;
#pragma unroll
        for (int i = 0; i < 8; i++) { sa += sma[i][tid]; sg2 += smg[i][tid]; }
        g_lr[t * NH + tid]   = sigmf(sa + ba[tid]);
        g_gate[t * NH + tid] = sigmf(sg2);
    }
}

// ---------------- pooled chunk stats: stage 1 (8-row partial sums) ----------------
__global__ void pool1_kernel() {
    int bc = blockIdx.x, seg = blockIdx.y;
    int tid = threadIdx.x;                    // 512 threads
    int b = bc / NC, c = bc % NC;
    int t0 = b * SEQN + c * CH + seg * 8;
    float s = 0.f;
#pragma unroll
    for (int i = 0; i < 8; i++) s += g_xs[(t0 + i) * DIM + tid];
    g_poolp[(bc * 8 + seg) * DIM + tid] = s;
}

// ---------------- pooled chunk stats: stage 2 (reduce + matvec) ----------------
__global__ void pool2_kernel(const float* __restrict__ Wm, const float* __restrict__ Wd,
                             const float* __restrict__ bd) {
    int bc = blockIdx.x;
    int tid = threadIdx.x;                    // 512 threads
    __shared__ float pooled[DIM];
    float s = 0.f;
#pragma unroll
    for (int seg = 0; seg < 8; seg++) s += g_poolp[(bc * 8 + seg) * DIM + tid];
    pooled[tid] = s * (1.0f / CH);
    __syncthreads();
    if (tid < 128) {
        int lane = tid & 31, h = tid >> 5;
        float am = 0.f, ad = 0.f;
        for (int d = lane; d < DIM; d += 32) {
            am += pooled[d] * Wm[d * NH + h];
            ad += pooled[d] * Wd[d * NH + h];
        }
        for (int o = 16; o; o >>= 1) {
            am += __shfl_down_sync(0xffffffffu, am, o);
            ad += __shfl_down_sync(0xffffffffu, ad, o);
        }
        if (lane == 0) {
            g_beta[bc * NH + h]  = sigmf(am);
            g_alpha[bc * NH + h] = 1.0f - sigmf(ad + bd[h]);
        }
    }
}

// ---------------- rmsnorm over DH=128 for K -> Hs ----------------
__global__ void rmshead_kernel(const float* __restrict__ memg) {
    int r = blockIdx.x;
    int d = threadIdx.x;
    float x = g_KVQ[(long)r * DH + d];          // K
    float ss = x * x;
    for (int o = 16; o; o >>= 1) ss += __shfl_down_sync(0xffffffffu, ss, o);
    __shared__ float sm[4];
    if ((d & 31) == 0) sm[d >> 5] = ss;
    __syncthreads();
    float tot = sm[0] + sm[1] + sm[2] + sm[3];
    float rs = rsqrtf(tot * (1.0f / DH) + 1e-6f);
    g_Hs[r * DH + d] = rndf(x * rs * memg[d]);
    if (d == 0) g_rsK[r] = rs;
}

// ---------------- rmsnorm for Q with per-chunk Gp -> Hq ----------------
__global__ void hq_kernel() {
    int r = blockIdx.x;
    int d = threadIdx.x;
    int bh = r / SEQN, n = r % SEQN, c = n / CH;
    float x = g_KVQ[2 * RWSDH + (long)r * DH + d];   // Q
    float ss = x * x;
    for (int o = 16; o; o >>= 1) ss += __shfl_down_sync(0xffffffffu, ss, o);
    __shared__ float sm[4];
    if ((d & 31) == 0) sm[d >> 5] = ss;
    __syncthreads();
    float tot = sm[0] + sm[1] + sm[2] + sm[3];
    float rs = rsqrtf(tot * (1.0f / DH) + 1e-6f);
    g_Hq[r * DH + d] = rndf(x * rs * g_Gp[(bh * NC + c) * DH + d]);
}

// ---------------- combined big scans (sw1 & sw2) with prefetch ----------------
__global__ void scan4_kernel(const float4* __restrict__ s1, const float4* __restrict__ i1,
                             float4* __restrict__ o1,
                             const float4* __restrict__ s2, const float4* __restrict__ i2,
                             float4* __restrict__ o2) {
    constexpr int sz4 = DH * DHID / 4;        // 16384
    const float4* s;
    const float4* init;
    float4* wprev;
    if (blockIdx.z == 0) { s = s1; init = i1; wprev = o1; }
    else                 { s = s2; init = i2; wprev = o2; }
    int bh = blockIdx.y;
    int e = blockIdx.x * 256 + threadIdx.x;
    if (e >= sz4) return;
    int b = bh / NH, h = bh % NH;
    float4 m = make_float4(0.f, 0.f, 0.f, 0.f);
    float4 w = init[e];
    wprev[(long)(bh * NC) * sz4 + e] = rnd4(w);
    float4 sv = s[(long)(bh * NC) * sz4 + e];
    for (int t = 0; t < NC; t++) {
        float4 nx = make_float4(0.f, 0.f, 0.f, 0.f);
        if (t + 1 < NC) nx = s[(long)(bh * NC + t + 1) * sz4 + e];
        float beta  = g_beta[(b * NC + t) * NH + h];
        float alpha = g_alpha[(b * NC + t) * NH + h];
        m.x = beta * m.x + sv.x; m.y = beta * m.y + sv.y;
        m.z = beta * m.z + sv.z; m.w = beta * m.w + sv.w;
        w.x = alpha * w.x + m.x; w.y = alpha * w.y + m.y;
        w.z = alpha * w.z + m.z; w.w = alpha * w.w + m.w;
        if (t < NC - 1) {
            wprev[(long)(bh * NC + t + 1) * sz4 + e] = rnd4(w);
            sv = nx;
        }
    }
}

// ---------------- small scan for s_g -> Gp ----------------
__global__ void scan_kernel(const float* __restrict__ s, const float* __restrict__ init,
                            float* __restrict__ wprev, int sz) {
    int bh = blockIdx.y;
    int e = blockIdx.x * 256 + threadIdx.x;
    if (e >= sz) return;
    int b = bh / NH, h = bh % NH;
    float m = 0.f, w = init[e];
    wprev[(long)(bh * NC) * sz + e] = rndf(w);
    for (int t = 0; t < NC; t++) {
        float beta  = g_beta[(b * NC + t) * NH + h];
        float alpha = g_alpha[(b * NC + t) * NH + h];
        m = beta * m + s[(long)(bh * NC + t) * sz + e];
        w = alpha * w + m;
        if (t < NC - 1) wprev[(long)(bh * NC + t + 1) * sz + e] = rndf(w);
    }
}

// ======= tf32 tensor-core GEMM, BMx128 tile, cp.async 3-stage pipeline =======
// EPI: 0 plain, 1 fused QKV, 2 store A1 + gelu, 3 pred->dY, 4 *gelu'(A1),
//      6 gelu only, 7 gated retrieval output, 8 negate,
//      9 fused dH->s_g column reduction (BM=64, block == chunk)
template <int BM, int EPI, bool TA>
__global__ void __launch_bounds__(256, 2) gmma(
    const float* __restrict__ A, const float* __restrict__ Bm, float* __restrict__ C,
    int K, int lda, int ldb, int ldc,
    long sA, long sB, long sC,
    const float* __restrict__ x0, const float* __restrict__ x1,
    const float* __restrict__ x2, float* __restrict__ x3) {
    constexpr int STG = 3;
    constexpr int WM  = BM / 2;
    constexpr int MA  = WM / 16;
    constexpr int AF  = BM / 64;
    constexpr int ASZ = TA ? 16 * 136 : BM * 20;
    constexpr int BSZ = 16 * 136;

    int z = blockIdx.z;
    if (EPI == 1) {
        if (z == 2) A = x0;
        Bm = (z == 0) ? Bm : (z == 1) ? x1 : x2;
        C += (long)z * RWSDH;
    } else {
        A += (long)z * sA; Bm += (long)z * sB; C += (long)z * sC;
    }

    extern __shared__ float smp[];
    float* Asm = smp;
    float* Bsm = smp + STG * ASZ;
    __shared__ float sgacc[128];

    int tid = threadIdx.x;
    int warp = tid >> 5, lane = tid & 31;
    int g = lane >> 2, tg = lane & 3;
    int wr = warp >> 2, wc = warp & 3;
    int m0 = blockIdx.y * BM, n0 = blockIdx.x * 128;

    float acc[MA][4][4];
#pragma unroll
    for (int i = 0; i < MA; i++)
#pragma unroll
        for (int j = 0; j < 4; j++)
#pragma unroll
            for (int l = 0; l < 4; l++) acc[i][j][l] = 0.f;

    auto issue = [&](int st, int kb) {
        float* as = Asm + st * ASZ;
        float* bs = Bsm + st * BSZ;
        if (!TA) {
#pragma unroll
            for (int f = 0; f < AF; f++) {
                int cid = tid + f * 256;
                int m = cid >> 2, kq = (cid & 3) * 4;
                cpa16(&as[m * 20 + kq], A + (long)(m0 + m) * lda + kb + kq);
            }
        } else {
#pragma unroll
            for (int f = 0; f < 2; f++) {
                int cid = tid + f * 256;
                int k = cid >> 5, mq = (cid & 31) * 4;
                cpa16(&as[k * 136 + mq], A + (long)(kb + k) * lda + m0 + mq);
            }
        }
#pragma unroll
        for (int f = 0; f < 2; f++) {
            int cid = tid + f * 256;
            int k = cid >> 5, nq = (cid & 31) * 4;
            cpa16(&bs[k * 136 + nq], Bm + (long)(kb + k) * ldb + n0 + nq);
        }
    };

    if (EPI == 9) {
        if (tid < 128) sgacc[tid] = 0.f;
    }

    int nT = K >> 4;
#pragma unroll
    for (int s = 0; s < STG - 1; s++) {
        if (s < nT) issue(s, s << 4);
        CP_COMMIT();
    }

    for (int t = 0; t < nT; t++) {
        CP_WAIT1();
        __syncthreads();
        int nx = t + STG - 1;
        if (nx < nT) issue(nx % STG, nx << 4);
        CP_COMMIT();

        const float* as = Asm + (t % STG) * ASZ;
        const float* bs = Bsm + (t % STG) * BSZ;
#pragma unroll
        for (int s = 0; s < 2; s++) {
            int k0 = s * 8 + tg;
            unsigned af[MA][4], bf[4][2];
#pragma unroll
            for (int ma = 0; ma < MA; ma++) {
                int rb = wr * WM + ma * 16 + g;
                if (!TA) {
                    af[ma][0] = __float_as_uint(as[rb * 20 + k0]);
                    af[ma][1] = __float_as_uint(as[(rb + 8) * 20 + k0]);
                    af[ma][2] = __float_as_uint(as[rb * 20 + k0 + 4]);
                    af[ma][3] = __float_as_uint(as[(rb + 8) * 20 + k0 + 4]);
                } else {
                    af[ma][0] = __float_as_uint(as[k0 * 136 + rb]);
                    af[ma][1] = __float_as_uint(as[k0 * 136 + rb + 8]);
                    af[ma][2] = __float_as_uint(as[(k0 + 4) * 136 + rb]);
                    af[ma][3] = __float_as_uint(as[(k0 + 4) * 136 + rb + 8]);
                }
            }
#pragma unroll
            for (int na = 0; na < 4; na++) {
                int nb = wc * 32 + na * 8 + g;
                bf[na][0] = __float_as_uint(bs[k0 * 136 + nb]);
                bf[na][1] = __float_as_uint(bs[(k0 + 4) * 136 + nb]);
            }
#pragma unroll
            for (int na = 0; na < 4; na++)
#pragma unroll
                for (int ma = 0; ma < MA; ma++)
                    mma8(acc[ma][na], af[ma], bf[na][0], bf[na][1]);
        }
    }

    if (EPI == 9) {
        // dH = acc; s_g[chunk, c] = -sum_rows dH[r,c] * K[r,c] * rsK[r]
#pragma unroll
        for (int na = 0; na < 4; na++) {
#pragma unroll
            for (int half = 0; half < 2; half++) {
                int c = n0 + wc * 32 + na * 8 + tg * 2 + half;
                float csum = 0.f;
#pragma unroll
                for (int ma = 0; ma < MA; ma++)
#pragma unroll
                    for (int ih = 0; ih < 2; ih++) {
                        int i = ih * 2 + half;
                        int r = m0 + wr * WM + ma * 16 + g + ih * 8;
                        csum += acc[ma][na][i] * x0[(long)r * DH + c] * x1[r];
                    }
                for (int o = 16; o >= 4; o >>= 1)
                    csum += __shfl_down_sync(0xffffffffu, csum, o);
                if (g == 0) atomicAdd(&sgacc[wc * 32 + na * 8 + tg * 2 + half], csum);
            }
        }
        __syncthreads();
        if (tid < 128) C[(long)blockIdx.y * DH + tid] = -sgacc[tid];
        return;
    }

    // epilogue
#pragma unroll
    for (int ma = 0; ma < MA; ma++) {
#pragma unroll
        for (int na = 0; na < 4; na++) {
#pragma unroll
            for (int i = 0; i < 4; i++) {
                int r = m0 + wr * WM + ma * 16 + g + ((i >= 2) ? 8 : 0);
                int c = n0 + wc * 32 + na * 8 + tg * 2 + (i & 1);
                float v = acc[ma][na][i];
                if (EPI == 0) {
                    C[(long)r * ldc + c] = v;
                } else if (EPI == 8) {
                    C[(long)r * ldc + c] = rndf(-v);
                } else if (EPI == 1) {
                    int b = r / SEQN, n = r % SEQN, h = c / DH, d = c % DH;
                    C[(long)(((b * NH + h) * SEQN) + n) * DH + d] = rndf(v);
                } else if (EPI == 2) {
                    x3[(long)r * ldc + c] = v;
                    C[(long)r * ldc + c]  = rndf(gelu_f(v));
                } else if (EPI == 3) {
                    float pred = v + x0[(long)r * DH + c];
                    int bh = r / SEQN, n = r % SEQN;
                    int b = bh / NH, h = bh % NH;
                    float lr = x2[(b * SEQN + n) * NH + h];
                    C[(long)r * DH + c] = rndf((2.0f / DH) * lr * (pred - x1[(long)r * DH + c]));
                } else if (EPI == 4) {
                    float a1 = x0[(long)r * ldc + c];
                    C[(long)r * ldc + c] = rndf(v * gelup_f(a1));
                } else if (EPI == 6) {
                    C[(long)r * ldc + c] = rndf(gelu_f(v));
                } else if (EPI == 7) {
                    float y = v + x0[(long)z * CH * DH + r * DH + c];
                    int bh = z / NC, cc = z % NC;
                    int n = cc * CH + r;
                    int b = bh / NH, h = bh % NH;
                    float gate = x1[(b * SEQN + n) * NH + h];
                    x3[(long)(b * SEQN + n) * DIM + h * DH + c] = rndf(y * gate);
                }
            }
        }
    }
}

constexpr int smem_bytes(int BM, bool TA) {
    return 3 * ((TA ? 16 * 136 : BM * 20) + 16 * 136) * 4;
}

// ---------------- launch ----------------
extern "C" void kernel_launch(void* const* d_in, const int* in_sizes, int n_in,
                              void* d_out, int out_size) {
    const float* seq   = (const float*)d_in[0];
    const float* gsto  = (const float*)d_in[1];
    const float* gret  = (const float*)d_in[2];
    const float* Wq    = (const float*)d_in[3];
    const float* Wk    = (const float*)d_in[4];
    const float* Wv    = (const float*)d_in[5];
    const float* Wa    = (const float*)d_in[6];
    const float* ba    = (const float*)d_in[7];
    const float* Wm    = (const float*)d_in[8];
    const float* Wd    = (const float*)d_in[9];
    const float* bd    = (const float*)d_in[10];
    const float* Wg    = (const float*)d_in[11];
    const float* Wc    = (const float*)d_in[12];
    const float* memg  = (const float*)d_in[13];
    const float* w1    = (const float*)d_in[14];
    const float* w2    = (const float*)d_in[15];
    float* out = (float*)d_out;

    float *p_xs, *p_xr, *p_KVQ, *p_lr, *p_gate, *p_Hs, *p_rsK, *p_A1, *p_GA,
          *p_dA1, *p_dY, *p_sw1, *p_sw2, *p_sg, *p_Wp1, *p_Wp2, *p_Gp,
          *p_Hq, *p_R, *p_w1T, *p_w2T, *p_Wr, *p_Wcr, *p_w1r, *p_w2r;
    cudaGetSymbolAddress((void**)&p_xs, g_xs);
    cudaGetSymbolAddress((void**)&p_xr, g_xr);
    cudaGetSymbolAddress((void**)&p_KVQ, g_KVQ);
    cudaGetSymbolAddress((void**)&p_lr, g_lr);
    cudaGetSymbolAddress((void**)&p_gate, g_gate);
    cudaGetSymbolAddress((void**)&p_Hs, g_Hs);
    cudaGetSymbolAddress((void**)&p_rsK, g_rsK);
    cudaGetSymbolAddress((void**)&p_A1, g_A1);
    cudaGetSymbolAddress((void**)&p_GA, g_GA);
    cudaGetSymbolAddress((void**)&p_dA1, g_dA1);
    cudaGetSymbolAddress((void**)&p_dY, g_dY);
    cudaGetSymbolAddress((void**)&p_sw1, g_sw1);
    cudaGetSymbolAddress((void**)&p_sw2, g_sw2);
    cudaGetSymbolAddress((void**)&p_sg, g_sg);
    cudaGetSymbolAddress((void**)&p_Wp1, g_Wp1);
    cudaGetSymbolAddress((void**)&p_Wp2, g_Wp2);
    cudaGetSymbolAddress((void**)&p_Gp, g_Gp);
    cudaGetSymbolAddress((void**)&p_Hq, g_Hq);
    cudaGetSymbolAddress((void**)&p_R, g_R);
    cudaGetSymbolAddress((void**)&p_w1T, g_w1T);
    cudaGetSymbolAddress((void**)&p_w2T, g_w2T);
    cudaGetSymbolAddress((void**)&p_Wr, g_Wr);
    cudaGetSymbolAddress((void**)&p_Wcr, g_Wcr);
    cudaGetSymbolAddress((void**)&p_w1r, g_w1r);
    cudaGetSymbolAddress((void**)&p_w2r, g_w2r);

    float* p_K = p_KVQ;
    float* p_V = p_KVQ + RWSDH;
    float* p_Q = p_KVQ + 2 * RWSDH;

    constexpr int S128  = smem_bytes(128, false);
    constexpr int S128T = smem_bytes(128, true);
    constexpr int S64   = smem_bytes(64, false);
    cudaFuncSetAttribute(gmma<128, 1, false>, cudaFuncAttributeMaxDynamicSharedMemorySize, S128);
    cudaFuncSetAttribute(gmma<128, 2, false>, cudaFuncAttributeMaxDynamicSharedMemorySize, S128);
    cudaFuncSetAttribute(gmma<64, 3, false>,  cudaFuncAttributeMaxDynamicSharedMemorySize, S64);
    cudaFuncSetAttribute(gmma<128, 4, false>, cudaFuncAttributeMaxDynamicSharedMemorySize, S128);
    cudaFuncSetAttribute(gmma<64, 9, false>,  cudaFuncAttributeMaxDynamicSharedMemorySize, S64);
    cudaFuncSetAttribute(gmma<64, 0, false>,  cudaFuncAttributeMaxDynamicSharedMemorySize, S64);
    cudaFuncSetAttribute(gmma<128, 8, true>,  cudaFuncAttributeMaxDynamicSharedMemorySize, S128T);
    cudaFuncSetAttribute(gmma<64, 6, false>,  cudaFuncAttributeMaxDynamicSharedMemorySize, S64);
    cudaFuncSetAttribute(gmma<64, 7, false>,  cudaFuncAttributeMaxDynamicSharedMemorySize, S64);

    // 0) rounded weight copies + rounded transposes (one launch)
    prep_kernel<<<dim3(1024, 8), 256>>>(Wk, Wv, Wq, Wc, w1, w2);

    // 1) rmsnorm of seq -> xs, xr (+ fused lr/gate)
    rmsseq_kernel<<<TOK, 256>>>(seq, gsto, gret, Wa, ba, Wg);

    // 2) fused QKV projections -> head-major K|V|Q
    gmma<128, 1, false><<<dim3(4, 32, 3), 256, S128>>>(p_xs, p_Wr, p_KVQ, DIM, DIM, DIM, 0,
        0, 0, 0, p_xr, p_Wr + DIM * DIM, p_Wr + 2 * DIM * DIM, nullptr);

    // 4) beta, alpha (two-stage pooling)
    pool1_kernel<<<dim3(Bb * NC, 8), 512>>>();
    pool2_kernel<<<Bb * NC, 512>>>(Wm, Wd, bd);

    // 5) Hs = rmsnorm(K, mem_g)
    rmshead_kernel<<<RWS, 128>>>(memg);

    // 7) A1 = Hs @ w1 ; GA = gelu(A1)
    gmma<128, 2, false><<<dim3(4, 128), 256, S128>>>(p_Hs, p_w1r, p_GA, DH, DH, DHID, DHID,
        0, 0, 0, nullptr, nullptr, nullptr, p_A1);
    // 8) pred = GA @ w2 + K -> dY
    gmma<64, 3, false><<<dim3(1, 256), 256, S64>>>(p_GA, p_w2r, p_dY, DHID, DHID, DH, DH,
        0, 0, 0, p_K, p_V, p_lr, nullptr);
    // 9) dA1 = (dY @ w2^T) * gelu'(A1)
    gmma<128, 4, false><<<dim3(4, 128), 256, S128>>>(p_dY, p_w2T, p_dA1, DH, DH, DHID, DHID,
        0, 0, 0, p_A1, nullptr, nullptr, nullptr);
    // 10+13) s_g = -colsum(dH * K * rsK) fused into dH GEMM (block == chunk)
    gmma<64, 9, false><<<dim3(1, 256), 256, S64>>>(p_dA1, p_w1T, p_sg, DHID, DHID, DH, DH,
        0, 0, 0, p_K, p_rsK, nullptr, nullptr);

    // 11) sW1[z] = -Hs_z^T @ dA1_z
    gmma<128, 8, true><<<dim3(4, 1, NCHUNK), 256, S128T>>>(p_Hs, p_dA1, p_sw1, CH, DH, DHID, DHID,
        (long)CH * DH, (long)CH * DHID, (long)DH * DHID, nullptr, nullptr, nullptr, nullptr);
    // 12) sW2[z] = -GA_z^T @ dY_z
    gmma<128, 8, true><<<dim3(1, 4, NCHUNK), 256, S128T>>>(p_GA, p_dY, p_sw2, CH, DHID, DH, DH,
        (long)CH * DHID, (long)CH * DH, (long)DHID * DH, nullptr, nullptr, nullptr, nullptr);

    // 14) scans -> causal w_prev per chunk (combined launch + Gp)
    scan4_kernel<<<dim3(64, BH, 2), 256>>>((const float4*)p_sw1, (const float4*)w1, (float4*)p_Wp1,
                                           (const float4*)p_sw2, (const float4*)w2, (float4*)p_Wp2);
    scan_kernel<<<dim3(1, BH), 256>>>(p_sg, memg, p_Gp, DH);

    // 15) Hq = rmsnorm(Q, Gp[chunk])
    hq_kernel<<<RWS, 128>>>();

    // 16) retrieval GEMM1: GAq = gelu(Hq @ Wp1[z])
    gmma<64, 6, false><<<dim3(4, 1, NCHUNK), 256, S64>>>(p_Hq, p_Wp1, p_GA, DH, DH, DHID, DHID,
        (long)CH * DH, (long)DH * DHID, (long)CH * DHID, nullptr, nullptr, nullptr, nullptr);
    // 17) retrieval GEMM2: y = GAq @ Wp2[z] + q ; gated -> g_R
    gmma<64, 7, false><<<dim3(1, 1, NCHUNK), 256, S64>>>(p_GA, p_Wp2, p_R, DHID, DHID, DH, DH,
        (long)CH * DHID, (long)DHID * DH, 0, p_Q, p_gate, nullptr, p_R);
    // 18) out = R @ Wc  (BM=64 -> full wave)
    gmma<64, 0, false><<<dim3(4, 64), 256, S64>>>(p_R, p_Wcr, out, DIM, DIM, DIM, DIM,
        0, 0, 0, nullptr, nullptr, nullptr, nullptr);
}

// round 7
// speedup vs baseline: 2.6969x; 1.0029x over previous
#include <cuda_runtime.h>
#include <math.h>

// ---------------- problem constants ----------------
constexpr int Bb   = 2;
constexpr int SEQN = 2048;
constexpr int DIM  = 512;
constexpr int NH   = 4;
constexpr int DH   = 128;
constexpr int CH   = 64;
constexpr int NC   = 32;
constexpr int DHID = 512;
constexpr int BH   = 8;
constexpr int TOK  = Bb * SEQN;      // 4096
constexpr int RWS  = BH * SEQN;      // 16384
constexpr int NCHUNK = BH * NC;      // 256
constexpr long RWSDH = (long)RWS * DH;

// ---------------- device scratch ----------------
__device__ float g_xs[TOK * DIM];
__device__ float g_xr[TOK * DIM];
__device__ float g_KVQ[3 * RWS * DH];          // K | V | Q
__device__ float g_lr[TOK * NH];
__device__ float g_gate[TOK * NH];
__device__ float g_beta[Bb * NC * NH];
__device__ float g_alpha[Bb * NC * NH];
__device__ float g_Hs[RWS * DH];
__device__ float g_rsK[RWS];
__device__ float g_A1[RWS * DHID];
__device__ float g_GA[RWS * DHID];
__device__ float g_dA1[RWS * DHID];
__device__ float g_dY[RWS * DH];
__device__ float g_sw1[NCHUNK * DH * DHID];
__device__ float g_sw2[NCHUNK * DHID * DH];
__device__ float g_sg[NCHUNK * DH];
__device__ float g_Wp1[NCHUNK * DH * DHID];
__device__ float g_Wp2[NCHUNK * DHID * DH];
__device__ float g_Gp[NCHUNK * DH];
__device__ float g_Hq[RWS * DH];
__device__ float g_R[TOK * DIM];
__device__ float g_w1T[DHID * DH];
__device__ float g_w2T[DH * DHID];
__device__ float g_poolp[Bb * NC * 8 * DIM];   // pooled partials
// tf32-rounded weight copies
__device__ float g_Wr[3 * DIM * DIM];          // Wk | Wv | Wq
__device__ float g_Wcr[DIM * DIM];
__device__ float g_w1r[DH * DHID];
__device__ float g_w2r[DHID * DH];

// ---------------- math helpers ----------------
__device__ __forceinline__ float sigmf(float x) { return 1.0f / (1.0f + expf(-x)); }
__device__ __forceinline__ float gelu_f(float x) {
    return 0.5f * x * (1.0f + erff(x * 0.70710678118654752f));
}
__device__ __forceinline__ float gelup_f(float x) {
    return 0.5f * (1.0f + erff(x * 0.70710678118654752f))
         + x * 0.3989422804014327f * expf(-0.5f * x * x);
}
__device__ __forceinline__ float rndf(float x) {      // round-to-nearest tf32
    asm("cvt.rna.tf32.f32 %0, %1;" : "=f"(x) : "f"(x));
    return x;
}
__device__ __forceinline__ float4 rnd4(float4 v) {
    v.x = rndf(v.x); v.y = rndf(v.y); v.z = rndf(v.z); v.w = rndf(v.w);
    return v;
}
__device__ __forceinline__ void mma8(float c[4], const unsigned a[4],
                                     unsigned b0, unsigned b1) {
    asm volatile(
        "mma.sync.aligned.m16n8k8.row.col.f32.tf32.tf32.f32 "
        "{%0,%1,%2,%3},{%4,%5,%6,%7},{%8,%9},{%0,%1,%2,%3};"
        : "+f"(c[0]), "+f"(c[1]), "+f"(c[2]), "+f"(c[3])
        : "r"(a[0]), "r"(a[1]), "r"(a[2]), "r"(a[3]), "r"(b0), "r"(b1));
}
__device__ __forceinline__ void ldsm4(unsigned& r0, unsigned& r1, unsigned& r2,
                                      unsigned& r3, unsigned addr) {
    asm volatile("ldmatrix.sync.aligned.m8n8.x4.shared.b16 {%0,%1,%2,%3}, [%4];"
                 : "=r"(r0), "=r"(r1), "=r"(r2), "=r"(r3) : "r"(addr));
}
__device__ __forceinline__ void cpa16(float* s, const float* g) {
    unsigned sa = (unsigned)__cvta_generic_to_shared(s);
    asm volatile("cp.async.cg.shared.global [%0], [%1], 16;\n" :: "r"(sa), "l"(g));
}
#define CP_COMMIT() asm volatile("cp.async.commit_group;\n" ::: "memory")
#define CP_WAIT1()  asm volatile("cp.async.wait_group 1;\n" ::: "memory")

// --------- prep: rounded weight copies + rounded weight transposes ---------
__global__ void prep_kernel(const float* __restrict__ Wk, const float* __restrict__ Wv,
                            const float* __restrict__ Wq, const float* __restrict__ Wc,
                            const float* __restrict__ w1, const float* __restrict__ w2) {
    int z = blockIdx.y;
    int idx = blockIdx.x * 256 + threadIdx.x;
    if (z < 3) {
        if (idx < DIM * DIM) g_Wr[z * DIM * DIM + idx] = rndf(z == 0 ? Wk[idx] : z == 1 ? Wv[idx] : Wq[idx]);
    } else if (z == 3) {
        if (idx < DIM * DIM) g_Wcr[idx] = rndf(Wc[idx]);
    } else if (z == 4) {
        if (idx < DH * DHID) g_w1r[idx] = rndf(w1[idx]);
    } else if (z == 5) {
        if (idx < DHID * DH) g_w2r[idx] = rndf(w2[idx]);
    } else if (z == 6) {
        if (idx < DH * DHID) {
            int r = idx / DHID, c = idx % DHID;
            g_w1T[c * DH + r] = rndf(w1[idx]);
        }
    } else {
        if (idx < DHID * DH) {
            int r = idx / DH, c = idx % DH;
            g_w2T[c * DHID + r] = rndf(w2[idx]);
        }
    }
}

// ------- rmsnorm over DIM=512 (xs, xr) + fused lr/gate projections -------
__global__ void rmsseq_kernel(const float* __restrict__ seq,
                              const float* __restrict__ gs,
                              const float* __restrict__ gr,
                              const float* __restrict__ Wa,
                              const float* __restrict__ ba,
                              const float* __restrict__ Wg) {
    int t = blockIdx.x;
    int tid = threadIdx.x;
    int lane = tid & 31, warp = tid >> 5;
    float x0 = seq[t * DIM + tid];
    float x1 = seq[t * DIM + tid + 256];
    float ss = x0 * x0 + x1 * x1;
    for (int o = 16; o; o >>= 1) ss += __shfl_down_sync(0xffffffffu, ss, o);
    __shared__ float sm[8];
    __shared__ float sma[8][4], smg[8][4];
    if (lane == 0) sm[warp] = ss;
    __syncthreads();
    float tot = 0.f;
#pragma unroll
    for (int i = 0; i < 8; i++) tot += sm[i];
    float rs = rsqrtf(tot * (1.0f / DIM) + 1e-6f);
    float a0 = x0 * rs * gs[tid],       a1 = x1 * rs * gs[tid + 256];
    float r0 = x0 * rs * gr[tid],       r1 = x1 * rs * gr[tid + 256];
    g_xs[t * DIM + tid]       = rndf(a0);
    g_xs[t * DIM + tid + 256] = rndf(a1);
    g_xr[t * DIM + tid]       = rndf(r0);
    g_xr[t * DIM + tid + 256] = rndf(r1);
    float pa[4], pg[4];
#pragma unroll
    for (int h = 0; h < 4; h++) {
        pa[h] = a0 * Wa[tid * NH + h] + a1 * Wa[(tid + 256) * NH + h];
        pg[h] = r0 * Wg[tid * NH + h] + r1 * Wg[(tid + 256) * NH + h];
    }
#pragma unroll
    for (int o = 16; o; o >>= 1)
#pragma unroll
        for (int h = 0; h < 4; h++) {
            pa[h] += __shfl_down_sync(0xffffffffu, pa[h], o);
            pg[h] += __shfl_down_sync(0xffffffffu, pg[h], o);
        }
    if (lane == 0)
#pragma unroll
        for (int h = 0; h < 4; h++) { sma[warp][h] = pa[h]; smg[warp][h] = pg[h]; }
    __syncthreads();
    if (tid < 4) {
        float sa = 0.f, sg2 = 0.f;
#pragma unroll
        for (int i = 0; i < 8; i++) { sa += sma[i][tid]; sg2 += smg[i][tid]; }
        g_lr[t * NH + tid]   = sigmf(sa + ba[tid]);
        g_gate[t * NH + tid] = sigmf(sg2);
    }
}

// ---------------- pooled chunk stats: stage 1 (8-row partial sums) ----------------
__global__ void pool1_kernel() {
    int bc = blockIdx.x, seg = blockIdx.y;
    int tid = threadIdx.x;                    // 512 threads
    int b = bc / NC, c = bc % NC;
    int t0 = b * SEQN + c * CH + seg * 8;
    float s = 0.f;
#pragma unroll
    for (int i = 0; i < 8; i++) s += g_xs[(t0 + i) * DIM + tid];
    g_poolp[(bc * 8 + seg) * DIM + tid] = s;
}

// ---------------- pooled chunk stats: stage 2 (reduce + matvec) ----------------
__global__ void pool2_kernel(const float* __restrict__ Wm, const float* __restrict__ Wd,
                             const float* __restrict__ bd) {
    int bc = blockIdx.x;
    int tid = threadIdx.x;                    // 512 threads
    __shared__ float pooled[DIM];
    float s = 0.f;
#pragma unroll
    for (int seg = 0; seg < 8; seg++) s += g_poolp[(bc * 8 + seg) * DIM + tid];
    pooled[tid] = s * (1.0f / CH);
    __syncthreads();
    if (tid < 128) {
        int lane = tid & 31, h = tid >> 5;
        float am = 0.f, ad = 0.f;
        for (int d = lane; d < DIM; d += 32) {
            am += pooled[d] * Wm[d * NH + h];
            ad += pooled[d] * Wd[d * NH + h];
        }
        for (int o = 16; o; o >>= 1) {
            am += __shfl_down_sync(0xffffffffu, am, o);
            ad += __shfl_down_sync(0xffffffffu, ad, o);
        }
        if (lane == 0) {
            g_beta[bc * NH + h]  = sigmf(am);
            g_alpha[bc * NH + h] = 1.0f - sigmf(ad + bd[h]);
        }
    }
}

// ---------------- rmsnorm over DH=128 for K -> Hs ----------------
__global__ void rmshead_kernel(const float* __restrict__ memg) {
    int r = blockIdx.x;
    int d = threadIdx.x;
    float x = g_KVQ[(long)r * DH + d];          // K
    float ss = x * x;
    for (int o = 16; o; o >>= 1) ss += __shfl_down_sync(0xffffffffu, ss, o);
    __shared__ float sm[4];
    if ((d & 31) == 0) sm[d >> 5] = ss;
    __syncthreads();
    float tot = sm[0] + sm[1] + sm[2] + sm[3];
    float rs = rsqrtf(tot * (1.0f / DH) + 1e-6f);
    g_Hs[r * DH + d] = rndf(x * rs * memg[d]);
    if (d == 0) g_rsK[r] = rs;
}

// ---------------- rmsnorm for Q with per-chunk Gp -> Hq ----------------
__global__ void hq_kernel() {
    int r = blockIdx.x;
    int d = threadIdx.x;
    int bh = r / SEQN, n = r % SEQN, c = n / CH;
    float x = g_KVQ[2 * RWSDH + (long)r * DH + d];   // Q
    float ss = x * x;
    for (int o = 16; o; o >>= 1) ss += __shfl_down_sync(0xffffffffu, ss, o);
    __shared__ float sm[4];
    if ((d & 31) == 0) sm[d >> 5] = ss;
    __syncthreads();
    float tot = sm[0] + sm[1] + sm[2] + sm[3];
    float rs = rsqrtf(tot * (1.0f / DH) + 1e-6f);
    g_Hq[r * DH + d] = rndf(x * rs * g_Gp[(bh * NC + c) * DH + d]);
}

// ---------------- combined big scans (sw1 & sw2) with prefetch ----------------
__global__ void scan4_kernel(const float4* __restrict__ s1, const float4* __restrict__ i1,
                             float4* __restrict__ o1,
                             const float4* __restrict__ s2, const float4* __restrict__ i2,
                             float4* __restrict__ o2) {
    constexpr int sz4 = DH * DHID / 4;        // 16384
    const float4* s;
    const float4* init;
    float4* wprev;
    if (blockIdx.z == 0) { s = s1; init = i1; wprev = o1; }
    else                 { s = s2; init = i2; wprev = o2; }
    int bh = blockIdx.y;
    int e = blockIdx.x * 256 + threadIdx.x;
    if (e >= sz4) return;
    int b = bh / NH, h = bh % NH;
    float4 m = make_float4(0.f, 0.f, 0.f, 0.f);
    float4 w = init[e];
    wprev[(long)(bh * NC) * sz4 + e] = rnd4(w);
    float4 sv = s[(long)(bh * NC) * sz4 + e];
    for (int t = 0; t < NC; t++) {
        float4 nx = make_float4(0.f, 0.f, 0.f, 0.f);
        if (t + 1 < NC) nx = s[(long)(bh * NC + t + 1) * sz4 + e];
        float beta  = g_beta[(b * NC + t) * NH + h];
        float alpha = g_alpha[(b * NC + t) * NH + h];
        m.x = beta * m.x + sv.x; m.y = beta * m.y + sv.y;
        m.z = beta * m.z + sv.z; m.w = beta * m.w + sv.w;
        w.x = alpha * w.x + m.x; w.y = alpha * w.y + m.y;
        w.z = alpha * w.z + m.z; w.w = alpha * w.w + m.w;
        if (t < NC - 1) {
            wprev[(long)(bh * NC + t + 1) * sz4 + e] = rnd4(w);
            sv = nx;
        }
    }
}

// ---------------- small scan for s_g -> Gp ----------------
__global__ void scan_kernel(const float* __restrict__ s, const float* __restrict__ init,
                            float* __restrict__ wprev, int sz) {
    int bh = blockIdx.y;
    int e = blockIdx.x * 256 + threadIdx.x;
    if (e >= sz) return;
    int b = bh / NH, h = bh % NH;
    float m = 0.f, w = init[e];
    wprev[(long)(bh * NC) * sz + e] = rndf(w);
    for (int t = 0; t < NC; t++) {
        float beta  = g_beta[(b * NC + t) * NH + h];
        float alpha = g_alpha[(b * NC + t) * NH + h];
        m = beta * m + s[(long)(bh * NC + t) * sz + e];
        w = alpha * w + m;
        if (t < NC - 1) wprev[(long)(bh * NC + t + 1) * sz + e] = rndf(w);
    }
}

// ======= tf32 tensor-core GEMM, BMx128 tile, cp.async pipeline + ldmatrix =======
// EPI: 0 plain, 1 fused QKV, 2 store A1 + gelu, 3 pred->dY, 4 *gelu'(A1),
//      6 gelu only, 7 gated retrieval output, 8 negate,
//      9 fused dH->s_g column reduction (BM=64, block == chunk)
template <int BM, int EPI, bool TA>
__global__ void __launch_bounds__(256, 2) gmma(
    const float* __restrict__ A, const float* __restrict__ Bm, float* __restrict__ C,
    int K, int lda, int ldb, int ldc,
    long sA, long sB, long sC,
    const float* __restrict__ x0, const float* __restrict__ x1,
    const float* __restrict__ x2, float* __restrict__ x3) {
    constexpr int STG = 3;
    constexpr int WM  = BM / 2;
    constexpr int MA  = WM / 16;
    constexpr int AF  = BM / 64;
    constexpr int ASZ = TA ? 16 * 136 : BM * 20;
    constexpr int BSZ = 16 * 136;

    int z = blockIdx.z;
    if (EPI == 1) {
        if (z == 2) A = x0;
        Bm = (z == 0) ? Bm : (z == 1) ? x1 : x2;
        C += (long)z * RWSDH;
    } else {
        A += (long)z * sA; Bm += (long)z * sB; C += (long)z * sC;
    }

    extern __shared__ float smp[];
    float* Asm = smp;
    float* Bsm = smp + STG * ASZ;
    __shared__ float sgacc[128];

    int tid = threadIdx.x;
    int warp = tid >> 5, lane = tid & 31;
    int g = lane >> 2, tg = lane & 3;
    int wr = warp >> 2, wc = warp & 3;
    int m0 = blockIdx.y * BM, n0 = blockIdx.x * 128;

    // ldmatrix per-lane address components (A, non-TA path)
    int ldsmRow = wr * WM + (lane & 7) + ((lane >> 3) & 1) * 8;
    int ldsmK4  = (lane >> 4) * 4;

    float acc[MA][4][4];
#pragma unroll
    for (int i = 0; i < MA; i++)
#pragma unroll
        for (int j = 0; j < 4; j++)
#pragma unroll
            for (int l = 0; l < 4; l++) acc[i][j][l] = 0.f;

    auto issue = [&](int st, int kb) {
        float* as = Asm + st * ASZ;
        float* bs = Bsm + st * BSZ;
        if (!TA) {
#pragma unroll
            for (int f = 0; f < AF; f++) {
                int cid = tid + f * 256;
                int m = cid >> 2, kq = (cid & 3) * 4;
                cpa16(&as[m * 20 + kq], A + (long)(m0 + m) * lda + kb + kq);
            }
        } else {
#pragma unroll
            for (int f = 0; f < 2; f++) {
                int cid = tid + f * 256;
                int k = cid >> 5, mq = (cid & 31) * 4;
                cpa16(&as[k * 136 + mq], A + (long)(kb + k) * lda + m0 + mq);
            }
        }
#pragma unroll
        for (int f = 0; f < 2; f++) {
            int cid = tid + f * 256;
            int k = cid >> 5, nq = (cid & 31) * 4;
            cpa16(&bs[k * 136 + nq], Bm + (long)(kb + k) * ldb + n0 + nq);
        }
    };

    if (EPI == 9) {
        if (tid < 128) sgacc[tid] = 0.f;
    }

    int nT = K >> 4;
#pragma unroll
    for (int s = 0; s < STG - 1; s++) {
        if (s < nT) issue(s, s << 4);
        CP_COMMIT();
    }

    for (int t = 0; t < nT; t++) {
        CP_WAIT1();
        __syncthreads();
        int nx = t + STG - 1;
        if (nx < nT) issue(nx % STG, nx << 4);
        CP_COMMIT();

        const float* as = Asm + (t % STG) * ASZ;
        const float* bs = Bsm + (t % STG) * BSZ;
        unsigned asb = (unsigned)__cvta_generic_to_shared(as);
#pragma unroll
        for (int s = 0; s < 2; s++) {
            int k0 = s * 8 + tg;
            unsigned af[MA][4], bf[4][2];
            if (!TA) {
#pragma unroll
                for (int ma = 0; ma < MA; ma++) {
                    unsigned addr = asb + (unsigned)(((ldsmRow + ma * 16) * 20 + s * 8 + ldsmK4) * 4);
                    ldsm4(af[ma][0], af[ma][1], af[ma][2], af[ma][3], addr);
                }
            } else {
#pragma unroll
                for (int ma = 0; ma < MA; ma++) {
                    int rb = wr * WM + ma * 16 + g;
                    af[ma][0] = __float_as_uint(as[k0 * 136 + rb]);
                    af[ma][1] = __float_as_uint(as[k0 * 136 + rb + 8]);
                    af[ma][2] = __float_as_uint(as[(k0 + 4) * 136 + rb]);
                    af[ma][3] = __float_as_uint(as[(k0 + 4) * 136 + rb + 8]);
                }
            }
#pragma unroll
            for (int na = 0; na < 4; na++) {
                int nb = wc * 32 + na * 8 + g;
                bf[na][0] = __float_as_uint(bs[k0 * 136 + nb]);
                bf[na][1] = __float_as_uint(bs[(k0 + 4) * 136 + nb]);
            }
#pragma unroll
            for (int na = 0; na < 4; na++)
#pragma unroll
                for (int ma = 0; ma < MA; ma++)
                    mma8(acc[ma][na], af[ma], bf[na][0], bf[na][1]);
        }
    }

    if (EPI == 9) {
        // dH = acc; s_g[chunk, c] = -sum_rows dH[r,c] * K[r,c] * rsK[r]
#pragma unroll
        for (int na = 0; na < 4; na++) {
#pragma unroll
            for (int half = 0; half < 2; half++) {
                int c = n0 + wc * 32 + na * 8 + tg * 2 + half;
                float csum = 0.f;
#pragma unroll
                for (int ma = 0; ma < MA; ma++)
#pragma unroll
                    for (int ih = 0; ih < 2; ih++) {
                        int i = ih * 2 + half;
                        int r = m0 + wr * WM + ma * 16 + g + ih * 8;
                        csum += acc[ma][na][i] * x0[(long)r * DH + c] * x1[r];
                    }
                for (int o = 16; o >= 4; o >>= 1)
                    csum += __shfl_down_sync(0xffffffffu, csum, o);
                if (g == 0) atomicAdd(&sgacc[wc * 32 + na * 8 + tg * 2 + half], csum);
            }
        }
        __syncthreads();
        if (tid < 128) C[(long)blockIdx.y * DH + tid] = -sgacc[tid];
        return;
    }

    // epilogue
#pragma unroll
    for (int ma = 0; ma < MA; ma++) {
#pragma unroll
        for (int na = 0; na < 4; na++) {
#pragma unroll
            for (int i = 0; i < 4; i++) {
                int r = m0 + wr * WM + ma * 16 + g + ((i >= 2) ? 8 : 0);
                int c = n0 + wc * 32 + na * 8 + tg * 2 + (i & 1);
                float v = acc[ma][na][i];
                if (EPI == 0) {
                    C[(long)r * ldc + c] = v;
                } else if (EPI == 8) {
                    C[(long)r * ldc + c] = rndf(-v);
                } else if (EPI == 1) {
                    int b = r / SEQN, n = r % SEQN, h = c / DH, d = c % DH;
                    C[(long)(((b * NH + h) * SEQN) + n) * DH + d] = rndf(v);
                } else if (EPI == 2) {
                    x3[(long)r * ldc + c] = v;
                    C[(long)r * ldc + c]  = rndf(gelu_f(v));
                } else if (EPI == 3) {
                    float pred = v + x0[(long)r * DH + c];
                    int bh = r / SEQN, n = r % SEQN;
                    int b = bh / NH, h = bh % NH;
                    float lr = x2[(b * SEQN + n) * NH + h];
                    C[(long)r * DH + c] = rndf((2.0f / DH) * lr * (pred - x1[(long)r * DH + c]));
                } else if (EPI == 4) {
                    float a1 = x0[(long)r * ldc + c];
                    C[(long)r * ldc + c] = rndf(v * gelup_f(a1));
                } else if (EPI == 6) {
                    C[(long)r * ldc + c] = rndf(gelu_f(v));
                } else if (EPI == 7) {
                    float y = v + x0[(long)z * CH * DH + r * DH + c];
                    int bh = z / NC, cc = z % NC;
                    int n = cc * CH + r;
                    int b = bh / NH, h = bh % NH;
                    float gate = x1[(b * SEQN + n) * NH + h];
                    x3[(long)(b * SEQN + n) * DIM + h * DH + c] = rndf(y * gate);
                }
            }
        }
    }
}

constexpr int smem_bytes(int BM, bool TA) {
    return 3 * ((TA ? 16 * 136 : BM * 20) + 16 * 136) * 4;
}

// ---------------- launch ----------------
extern "C" void kernel_launch(void* const* d_in, const int* in_sizes, int n_in,
                              void* d_out, int out_size) {
    const float* seq   = (const float*)d_in[0];
    const float* gsto  = (const float*)d_in[1];
    const float* gret  = (const float*)d_in[2];
    const float* Wq    = (const float*)d_in[3];
    const float* Wk    = (const float*)d_in[4];
    const float* Wv    = (const float*)d_in[5];
    const float* Wa    = (const float*)d_in[6];
    const float* ba    = (const float*)d_in[7];
    const float* Wm    = (const float*)d_in[8];
    const float* Wd    = (const float*)d_in[9];
    const float* bd    = (const float*)d_in[10];
    const float* Wg    = (const float*)d_in[11];
    const float* Wc    = (const float*)d_in[12];
    const float* memg  = (const float*)d_in[13];
    const float* w1    = (const float*)d_in[14];
    const float* w2    = (const float*)d_in[15];
    float* out = (float*)d_out;

    float *p_xs, *p_xr, *p_KVQ, *p_lr, *p_gate, *p_Hs, *p_rsK, *p_A1, *p_GA,
          *p_dA1, *p_dY, *p_sw1, *p_sw2, *p_sg, *p_Wp1, *p_Wp2, *p_Gp,
          *p_Hq, *p_R, *p_w1T, *p_w2T, *p_Wr, *p_Wcr, *p_w1r, *p_w2r;
    cudaGetSymbolAddress((void**)&p_xs, g_xs);
    cudaGetSymbolAddress((void**)&p_xr, g_xr);
    cudaGetSymbolAddress((void**)&p_KVQ, g_KVQ);
    cudaGetSymbolAddress((void**)&p_lr, g_lr);
    cudaGetSymbolAddress((void**)&p_gate, g_gate);
    cudaGetSymbolAddress((void**)&p_Hs, g_Hs);
    cudaGetSymbolAddress((void**)&p_rsK, g_rsK);
    cudaGetSymbolAddress((void**)&p_A1, g_A1);
    cudaGetSymbolAddress((void**)&p_GA, g_GA);
    cudaGetSymbolAddress((void**)&p_dA1, g_dA1);
    cudaGetSymbolAddress((void**)&p_dY, g_dY);
    cudaGetSymbolAddress((void**)&p_sw1, g_sw1);
    cudaGetSymbolAddress((void**)&p_sw2, g_sw2);
    cudaGetSymbolAddress((void**)&p_sg, g_sg);
    cudaGetSymbolAddress((void**)&p_Wp1, g_Wp1);
    cudaGetSymbolAddress((void**)&p_Wp2, g_Wp2);
    cudaGetSymbolAddress((void**)&p_Gp, g_Gp);
    cudaGetSymbolAddress((void**)&p_Hq, g_Hq);
    cudaGetSymbolAddress((void**)&p_R, g_R);
    cudaGetSymbolAddress((void**)&p_w1T, g_w1T);
    cudaGetSymbolAddress((void**)&p_w2T, g_w2T);
    cudaGetSymbolAddress((void**)&p_Wr, g_Wr);
    cudaGetSymbolAddress((void**)&p_Wcr, g_Wcr);
    cudaGetSymbolAddress((void**)&p_w1r, g_w1r);
    cudaGetSymbolAddress((void**)&p_w2r, g_w2r);

    float* p_K = p_KVQ;
    float* p_V = p_KVQ + RWSDH;
    float* p_Q = p_KVQ + 2 * RWSDH;

    constexpr int S128  = smem_bytes(128, false);
    constexpr int S128T = smem_bytes(128, true);
    constexpr int S64   = smem_bytes(64, false);
    cudaFuncSetAttribute(gmma<128, 1, false>, cudaFuncAttributeMaxDynamicSharedMemorySize, S128);
    cudaFuncSetAttribute(gmma<128, 2, false>, cudaFuncAttributeMaxDynamicSharedMemorySize, S128);
    cudaFuncSetAttribute(gmma<64, 3, false>,  cudaFuncAttributeMaxDynamicSharedMemorySize, S64);
    cudaFuncSetAttribute(gmma<128, 4, false>, cudaFuncAttributeMaxDynamicSharedMemorySize, S128);
    cudaFuncSetAttribute(gmma<64, 9, false>,  cudaFuncAttributeMaxDynamicSharedMemorySize, S64);
    cudaFuncSetAttribute(gmma<64, 0, false>,  cudaFuncAttributeMaxDynamicSharedMemorySize, S64);
    cudaFuncSetAttribute(gmma<128, 8, true>,  cudaFuncAttributeMaxDynamicSharedMemorySize, S128T);
    cudaFuncSetAttribute(gmma<64, 6, false>,  cudaFuncAttributeMaxDynamicSharedMemorySize, S64);
    cudaFuncSetAttribute(gmma<64, 7, false>,  cudaFuncAttributeMaxDynamicSharedMemorySize, S64);

    // 0) rounded weight copies + rounded transposes (one launch)
    prep_kernel<<<dim3(1024, 8), 256>>>(Wk, Wv, Wq, Wc, w1, w2);

    // 1) rmsnorm of seq -> xs, xr (+ fused lr/gate)
    rmsseq_kernel<<<TOK, 256>>>(seq, gsto, gret, Wa, ba, Wg);

    // 2) fused QKV projections -> head-major K|V|Q
    gmma<128, 1, false><<<dim3(4, 32, 3), 256, S128>>>(p_xs, p_Wr, p_KVQ, DIM, DIM, DIM, 0,
        0, 0, 0, p_xr, p_Wr + DIM * DIM, p_Wr + 2 * DIM * DIM, nullptr);

    // 4) beta, alpha (two-stage pooling)
    pool1_kernel<<<dim3(Bb * NC, 8), 512>>>();
    pool2_kernel<<<Bb * NC, 512>>>(Wm, Wd, bd);

    // 5) Hs = rmsnorm(K, mem_g)
    rmshead_kernel<<<RWS, 128>>>(memg);

    // 7) A1 = Hs @ w1 ; GA = gelu(A1)
    gmma<128, 2, false><<<dim3(4, 128), 256, S128>>>(p_Hs, p_w1r, p_GA, DH, DH, DHID, DHID,
        0, 0, 0, nullptr, nullptr, nullptr, p_A1);
    // 8) pred = GA @ w2 + K -> dY
    gmma<64, 3, false><<<dim3(1, 256), 256, S64>>>(p_GA, p_w2r, p_dY, DHID, DHID, DH, DH,
        0, 0, 0, p_K, p_V, p_lr, nullptr);
    // 9) dA1 = (dY @ w2^T) * gelu'(A1)
    gmma<128, 4, false><<<dim3(4, 128), 256, S128>>>(p_dY, p_w2T, p_dA1, DH, DH, DHID, DHID,
        0, 0, 0, p_A1, nullptr, nullptr, nullptr);
    // 10+13) s_g = -colsum(dH * K * rsK) fused into dH GEMM (block == chunk)
    gmma<64, 9, false><<<dim3(1, 256), 256, S64>>>(p_dA1, p_w1T, p_sg, DHID, DHID, DH, DH,
        0, 0, 0, p_K, p_rsK, nullptr, nullptr);

    // 11) sW1[z] = -Hs_z^T @ dA1_z
    gmma<128, 8, true><<<dim3(4, 1, NCHUNK), 256, S128T>>>(p_Hs, p_dA1, p_sw1, CH, DH, DHID, DHID,
        (long)CH * DH, (long)CH * DHID, (long)DH * DHID, nullptr, nullptr, nullptr, nullptr);
    // 12) sW2[z] = -GA_z^T @ dY_z
    gmma<128, 8, true><<<dim3(1, 4, NCHUNK), 256, S128T>>>(p_GA, p_dY, p_sw2, CH, DHID, DH, DH,
        (long)CH * DHID, (long)CH * DH, (long)DHID * DH, nullptr, nullptr, nullptr, nullptr);

    // 14) scans -> causal w_prev per chunk (combined launch + Gp)
    scan4_kernel<<<dim3(64, BH, 2), 256>>>((const float4*)p_sw1, (const float4*)w1, (float4*)p_Wp1,
                                           (const float4*)p_sw2, (const float4*)w2, (float4*)p_Wp2);
    scan_kernel<<<dim3(1, BH), 256>>>(p_sg, memg, p_Gp, DH);

    // 15) Hq = rmsnorm(Q, Gp[chunk])
    hq_kernel<<<RWS, 128>>>();

    // 16) retrieval GEMM1: GAq = gelu(Hq @ Wp1[z])
    gmma<64, 6, false><<<dim3(4, 1, NCHUNK), 256, S64>>>(p_Hq, p_Wp1, p_GA, DH, DH, DHID, DHID,
        (long)CH * DH, (long)DH * DHID, (long)CH * DHID, nullptr, nullptr, nullptr, nullptr);
    // 17) retrieval GEMM2: y = GAq @ Wp2[z] + q ; gated -> g_R
    gmma<64, 7, false><<<dim3(1, 1, NCHUNK), 256, S64>>>(p_GA, p_Wp2, p_R, DHID, DHID, DH, DH,
        (long)CH * DHID, (long)DHID * DH, 0, p_Q, p_gate, nullptr, p_R);
    // 18) out = R @ Wc  (BM=64 -> full wave)
    gmma<64, 0, false><<<dim3(4, 64), 256, S64>>>(p_R, p_Wcr, out, DIM, DIM, DIM, DIM,
        0, 0, 0, nullptr, nullptr, nullptr, nullptr);
}

// round 14
// speedup vs baseline: 2.7386x; 1.0155x over previous
#include <cuda_runtime.h>
#include <cuda_fp16.h>
#include <math.h>

// ---------------- problem constants ----------------
constexpr int Bb   = 2;
constexpr int SEQN = 2048;
constexpr int DIM  = 512;
constexpr int NH   = 4;
constexpr int DH   = 128;
constexpr int CH   = 64;
constexpr int NC   = 32;
constexpr int DHID = 512;
constexpr int BH   = 8;
constexpr int TOK  = Bb * SEQN;      // 4096
constexpr int RWS  = BH * SEQN;      // 16384
constexpr int NCHUNK = BH * NC;      // 256
constexpr long RWSDH = (long)RWS * DH;

// ---------------- device scratch ----------------
__device__ float g_xs[TOK * DIM];
__device__ float g_xr[TOK * DIM];
__device__ float g_KVQ[3 * RWS * DH];          // K | V | Q
__device__ float g_lr[TOK * NH];
__device__ float g_gate[TOK * NH];
__device__ float g_beta[Bb * NC * NH];
__device__ float g_alpha[Bb * NC * NH];
__device__ float g_Hs[RWS * DH];
__device__ float g_rsK[RWS];
__device__ float g_A1[RWS * DHID];
__device__ float g_GA[RWS * DHID];
__device__ float g_dA1[RWS * DHID];
__device__ float g_dY[RWS * DH];
__device__ __half g_sw1h[NCHUNK * DH * DHID];
__device__ __half g_sw2h[NCHUNK * DHID * DH];
__device__ float  g_sg[NCHUNK * DH];
__device__ __half g_Wp1h[NCHUNK * DH * DHID];
__device__ __half g_Wp2h[NCHUNK * DHID * DH];
__device__ float g_Gp[NCHUNK * DH];
__device__ float g_Hq[RWS * DH];
__device__ float g_R[TOK * DIM];
__device__ float g_w1T[DHID * DH];
__device__ float g_w2T[DH * DHID];
__device__ float g_poolp[Bb * NC * 8 * DIM];   // pooled partials
// tf32-rounded weight copies
__device__ float g_Wr[3 * DIM * DIM];          // Wk | Wv | Wq
__device__ float g_Wcr[DIM * DIM];
__device__ float g_w1r[DH * DHID];
__device__ float g_w2r[DHID * DH];

// ---------------- math helpers ----------------
__device__ __forceinline__ float sigmf(float x) { return 1.0f / (1.0f + expf(-x)); }
__device__ __forceinline__ float gelu_f(float x) {
    return 0.5f * x * (1.0f + erff(x * 0.70710678118654752f));
}
__device__ __forceinline__ float gelup_f(float x) {
    return 0.5f * (1.0f + erff(x * 0.70710678118654752f))
         + x * 0.3989422804014327f * expf(-0.5f * x * x);
}
__device__ __forceinline__ float rndf(float x) {      // round-to-nearest tf32
    asm("cvt.rna.tf32.f32 %0, %1;" : "=f"(x) : "f"(x));
    return x;
}
__device__ __forceinline__ void mma8(float c[4], const unsigned a[4],
                                     unsigned b0, unsigned b1) {
    asm volatile(
        "mma.sync.aligned.m16n8k8.row.col.f32.tf32.tf32.f32 "
        "{%0,%1,%2,%3},{%4,%5,%6,%7},{%8,%9},{%0,%1,%2,%3};"
        : "+f"(c[0]), "+f"(c[1]), "+f"(c[2]), "+f"(c[3])
        : "r"(a[0]), "r"(a[1]), "r"(a[2]), "r"(a[3]), "r"(b0), "r"(b1));
}
__device__ __forceinline__ void ldsm4(unsigned& r0, unsigned& r1, unsigned& r2,
                                      unsigned& r3, unsigned addr) {
    asm volatile("ldmatrix.sync.aligned.m8n8.x4.shared.b16 {%0,%1,%2,%3}, [%4];"
                 : "=r"(r0), "=r"(r1), "=r"(r2), "=r"(r3) : "r"(addr));
}
__device__ __forceinline__ void cpa16(void* s, const void* g) {
    unsigned sa = (unsigned)__cvta_generic_to_shared(s);
    asm volatile("cp.async.cg.shared.global [%0], [%1], 16;\n" :: "r"(sa), "l"(g));
}
#define CP_COMMIT() asm volatile("cp.async.commit_group;\n" ::: "memory")
#define CP_WAIT1()  asm volatile("cp.async.wait_group 1;\n" ::: "memory")

// --------- prep: rounded weight copies + rounded weight transposes ---------
__global__ void prep_kernel(const float* __restrict__ Wk, const float* __restrict__ Wv,
                            const float* __restrict__ Wq, const float* __restrict__ Wc,
                            const float* __restrict__ w1, const float* __restrict__ w2) {
    int z = blockIdx.y;
    int idx = blockIdx.x * 256 + threadIdx.x;
    if (z < 3) {
        if (idx < DIM * DIM) g_Wr[z * DIM * DIM + idx] = rndf(z == 0 ? Wk[idx] : z == 1 ? Wv[idx] : Wq[idx]);
    } else if (z == 3) {
        if (idx < DIM * DIM) g_Wcr[idx] = rndf(Wc[idx]);
    } else if (z == 4) {
        if (idx < DH * DHID) g_w1r[idx] = rndf(w1[idx]);
    } else if (z == 5) {
        if (idx < DHID * DH) g_w2r[idx] = rndf(w2[idx]);
    } else if (z == 6) {
        if (idx < DH * DHID) {
            int r = idx / DHID, c = idx % DHID;
            g_w1T[c * DH + r] = rndf(w1[idx]);
        }
    } else {
        if (idx < DHID * DH) {
            int r = idx / DH, c = idx % DH;
            g_w2T[c * DHID + r] = rndf(w2[idx]);
        }
    }
}

// ------- rmsnorm over DIM=512 (xs, xr) + fused lr/gate projections -------
__global__ void rmsseq_kernel(const float* __restrict__ seq,
                              const float* __restrict__ gs,
                              const float* __restrict__ gr,
                              const float* __restrict__ Wa,
                              const float* __restrict__ ba,
                              const float* __restrict__ Wg) {
    int t = blockIdx.x;
    int tid = threadIdx.x;
    int lane = tid & 31, warp = tid >> 5;
    float x0 = seq[t * DIM + tid];
    float x1 = seq[t * DIM + tid + 256];
    float ss = x0 * x0 + x1 * x1;
    for (int o = 16; o; o >>= 1) ss += __shfl_down_sync(0xffffffffu, ss, o);
    __shared__ float sm[8];
    __shared__ float sma[8][4], smg[8][4];
    if (lane == 0) sm[warp] = ss;
    __syncthreads();
    float tot = 0.f;
#pragma unroll
    for (int i = 0; i < 8; i++) tot += sm[i];
    float rs = rsqrtf(tot * (1.0f / DIM) + 1e-6f);
    float a0 = x0 * rs * gs[tid],       a1 = x1 * rs * gs[tid + 256];
    float r0 = x0 * rs * gr[tid],       r1 = x1 * rs * gr[tid + 256];
    g_xs[t * DIM + tid]       = rndf(a0);
    g_xs[t * DIM + tid + 256] = rndf(a1);
    g_xr[t * DIM + tid]       = rndf(r0);
    g_xr[t * DIM + tid + 256] = rndf(r1);
    float pa[4], pg[4];
#pragma unroll
    for (int h = 0; h < 4; h++) {
        pa[h] = a0 * Wa[tid * NH + h] + a1 * Wa[(tid + 256) * NH + h];
        pg[h] = r0 * Wg[tid * NH + h] + r1 * Wg[(tid + 256) * NH + h];
    }
#pragma unroll
    for (int o = 16; o; o >>= 1)
#pragma unroll
        for (int h = 0; h < 4; h++) {
            pa[h] += __shfl_down_sync(0xffffffffu, pa[h], o);
            pg[h] += __shfl_down_sync(0xffffffffu, pg[h], o);
        }
    if (lane == 0)
#pragma unroll
        for (int h = 0; h < 4; h++) { sma[warp][h] = pa[h]; smg[warp][h] = pg[h]; }
    __syncthreads();
    if (tid < 4) {
        float sa = 0.f, sg2 = 0.f;
#pragma unroll
        for (int i = 0; i < 8; i++) { sa += sma[i][tid]; sg2 += smg[i][tid]; }
        g_lr[t * NH + tid]   = sigmf(sa + ba[tid]);
        g_gate[t * NH + tid] = sigmf(sg2);
    }
}

// ---------------- pooled chunk stats: stage 1 (8-row partial sums) ----------------
__global__ void pool1_kernel() {
    int bc = blockIdx.x, seg = blockIdx.y;
    int tid = threadIdx.x;                    // 512 threads
    int b = bc / NC, c = bc % NC;
    int t0 = b * SEQN + c * CH + seg * 8;
    float s = 0.f;
#pragma unroll
    for (int i = 0; i < 8; i++) s += g_xs[(t0 + i) * DIM + tid];
    g_poolp[(bc * 8 + seg) * DIM + tid] = s;
}

// ---------------- pooled chunk stats: stage 2 (reduce + matvec) ----------------
__global__ void pool2_kernel(const float* __restrict__ Wm, const float* __restrict__ Wd,
                             const float* __restrict__ bd) {
    int bc = blockIdx.x;
    int tid = threadIdx.x;                    // 512 threads
    __shared__ float pooled[DIM];
    float s = 0.f;
#pragma unroll
    for (int seg = 0; seg < 8; seg++) s += g_poolp[(bc * 8 + seg) * DIM + tid];
    pooled[tid] = s * (1.0f / CH);
    __syncthreads();
    if (tid < 128) {
        int lane = tid & 31, h = tid >> 5;
        float am = 0.f, ad = 0.f;
        for (int d = lane; d < DIM; d += 32) {
            am += pooled[d] * Wm[d * NH + h];
            ad += pooled[d] * Wd[d * NH + h];
        }
        for (int o = 16; o; o >>= 1) {
            am += __shfl_down_sync(0xffffffffu, am, o);
            ad += __shfl_down_sync(0xffffffffu, ad, o);
        }
        if (lane == 0) {
            g_beta[bc * NH + h]  = sigmf(am);
            g_alpha[bc * NH + h] = 1.0f - sigmf(ad + bd[h]);
        }
    }
}

// ---------------- rmsnorm over DH=128 for K -> Hs ----------------
__global__ void rmshead_kernel(const float* __restrict__ memg) {
    int r = blockIdx.x;
    int d = threadIdx.x;
    float x = g_KVQ[(long)r * DH + d];          // K
    float ss = x * x;
    for (int o = 16; o; o >>= 1) ss += __shfl_down_sync(0xffffffffu, ss, o);
    __shared__ float sm[4];
    if ((d & 31) == 0) sm[d >> 5] = ss;
    __syncthreads();
    float tot = sm[0] + sm[1] + sm[2] + sm[3];
    float rs = rsqrtf(tot * (1.0f / DH) + 1e-6f);
    g_Hs[r * DH + d] = rndf(x * rs * memg[d]);
    if (d == 0) g_rsK[r] = rs;
}

// ---------------- rmsnorm for Q with per-chunk Gp -> Hq ----------------
__global__ void hq_kernel() {
    int r = blockIdx.x;
    int d = threadIdx.x;
    int bh = r / SEQN, n = r % SEQN, c = n / CH;
    float x = g_KVQ[2 * RWSDH + (long)r * DH + d];   // Q
    float ss = x * x;
    for (int o = 16; o; o >>= 1) ss += __shfl_down_sync(0xffffffffu, ss, o);
    __shared__ float sm[4];
    if ((d & 31) == 0) sm[d >> 5] = ss;
    __syncthreads();
    float tot = sm[0] + sm[1] + sm[2] + sm[3];
    float rs = rsqrtf(tot * (1.0f / DH) + 1e-6f);
    g_Hq[r * DH + d] = rndf(x * rs * g_Gp[(bh * NC + c) * DH + d]);
}

// --------- combined big scans over half tensors (8 halves per thread) ---------
__global__ void scanh_kernel(const __half* __restrict__ s1, const float* __restrict__ i1,
                             __half* __restrict__ o1,
                             const __half* __restrict__ s2, const float* __restrict__ i2,
                             __half* __restrict__ o2) {
    constexpr long SZ = (long)DH * DHID;       // 65536 halves
    const __half* s; const float* init; __half* wprev;
    if (blockIdx.z == 0) { s = s1; init = i1; wprev = o1; }
    else                 { s = s2; init = i2; wprev = o2; }
    int bh = blockIdx.y;
    long e8 = ((long)blockIdx.x * 256 + threadIdx.x) * 8;
    if (e8 >= SZ) return;
    int b = bh / NH, h = bh % NH;

    float m[8], w[8];
#pragma unroll
    for (int j = 0; j < 8; j++) { m[j] = 0.f; w[j] = init[e8 + j]; }

    auto store8 = [&](long off, const float* v) {
        __half2 hv[4];
#pragma unroll
        for (int j = 0; j < 4; j++)
            hv[j] = __floats2half2_rn(v[2 * j], v[2 * j + 1]);
        *(uint4*)(wprev + off) = *(const uint4*)hv;
    };
    auto load8 = [&](long off, float* v) {
        uint4 raw = *(const uint4*)(s + off);
        const __half2* h2 = (const __half2*)&raw;
#pragma unroll
        for (int j = 0; j < 4; j++) {
            float2 f = __half22float2(h2[j]);
            v[2 * j] = f.x; v[2 * j + 1] = f.y;
        }
    };

    store8((long)(bh * NC) * SZ + e8, w);
    float sv[8];
    load8((long)(bh * NC) * SZ + e8, sv);
    for (int t = 0; t < NC; t++) {
        float nx[8];
        if (t + 1 < NC) load8((long)(bh * NC + t + 1) * SZ + e8, nx);
        float beta  = g_beta[(b * NC + t) * NH + h];
        float alpha = g_alpha[(b * NC + t) * NH + h];
#pragma unroll
        for (int j = 0; j < 8; j++) {
            m[j] = beta * m[j] + sv[j];
            w[j] = alpha * w[j] + m[j];
        }
        if (t < NC - 1) {
            store8((long)(bh * NC + t + 1) * SZ + e8, w);
#pragma unroll
            for (int j = 0; j < 8; j++) sv[j] = nx[j];
        }
    }
}

// ---------------- small scan for s_g -> Gp ----------------
__global__ void scan_kernel(const float* __restrict__ s, const float* __restrict__ init,
                            float* __restrict__ wprev, int sz) {
    int bh = blockIdx.y;
    int e = blockIdx.x * 256 + threadIdx.x;
    if (e >= sz) return;
    int b = bh / NH, h = bh % NH;
    float m = 0.f, w = init[e];
    wprev[(long)(bh * NC) * sz + e] = rndf(w);
    for (int t = 0; t < NC; t++) {
        float beta  = g_beta[(b * NC + t) * NH + h];
        float alpha = g_alpha[(b * NC + t) * NH + h];
        m = beta * m + s[(long)(bh * NC + t) * sz + e];
        w = alpha * w + m;
        if (t < NC - 1) wprev[(long)(bh * NC + t + 1) * sz + e] = rndf(w);
    }
}

// ======= tf32 tensor-core GEMM, BMx128 tile, cp.async pipeline + ldmatrix =======
// EPI: 0 plain, 1 fused QKV, 2 store A1 + gelu, 3 pred->dY, 4 *gelu'(A1),
//      6 gelu only, 7 gated retrieval output, 8 negate -> HALF C (z-offset in halves),
//      9 fused dH->s_g column reduction (BM=64, block == chunk)
// TA: A^T @ B (A stored [K][M]) ;  HB: B operand stored as __half in global
template <int BM, int EPI, bool TA, bool HB>
__global__ void __launch_bounds__(256, 2) gmma(
    const float* __restrict__ A, const float* __restrict__ Bm, float* __restrict__ C,
    int K, int lda, int ldb, int ldc,
    long sA, long sB, long sC,
    const float* __restrict__ x0, const float* __restrict__ x1,
    const float* __restrict__ x2, float* __restrict__ x3) {
    constexpr int STG = 3;
    constexpr int WM  = BM / 2;
    constexpr int MA  = WM / 16;
    constexpr int AF  = BM / 64;
    constexpr int ASZ = TA ? 16 * 136 : BM * 20;     // floats
    constexpr int BSZH = 16 * 136;                   // elements per B stage

    int z = blockIdx.z;
    const __half* BmH = nullptr;
    __half* Ch = nullptr;
    if (EPI == 1) {
        if (z == 2) A = x0;
        Bm = (z == 0) ? Bm : (z == 1) ? x1 : x2;
        C += (long)z * RWSDH;
    } else {
        A += (long)z * sA;
        if (HB) BmH = (const __half*)Bm + (long)z * sB;
        else    Bm += (long)z * sB;
        if (EPI == 8) Ch = (__half*)C + (long)z * sC;   // offset in HALF units
        else          C += (long)z * sC;
    }

    extern __shared__ float smp[];
    float* Asm = smp;
    float*  BsmF = smp + STG * ASZ;
    __half* BsmH = (__half*)(smp + STG * ASZ);
    __shared__ float sgacc[128];

    int tid = threadIdx.x;
    int warp = tid >> 5, lane = tid & 31;
    int g = lane >> 2, tg = lane & 3;
    int wr = warp >> 2, wc = warp & 3;
    int m0 = blockIdx.y * BM, n0 = blockIdx.x * 128;

    int ldsmRow = wr * WM + (lane & 7) + ((lane >> 3) & 1) * 8;
    int ldsmK4  = (lane >> 4) * 4;

    float acc[MA][4][4];
#pragma unroll
    for (int i = 0; i < MA; i++)
#pragma unroll
        for (int j = 0; j < 4; j++)
#pragma unroll
            for (int l = 0; l < 4; l++) acc[i][j][l] = 0.f;

    auto issue = [&](int st, int kb) {
        float* as = Asm + st * ASZ;
        if (!TA) {
#pragma unroll
            for (int f = 0; f < AF; f++) {
                int cid = tid + f * 256;
                int m = cid >> 2, kq = (cid & 3) * 4;
                cpa16(&as[m * 20 + kq], A + (long)(m0 + m) * lda + kb + kq);
            }
        } else {
#pragma unroll
            for (int f = 0; f < 2; f++) {
                int cid = tid + f * 256;
                int k = cid >> 5, mq = (cid & 31) * 4;
                cpa16(&as[k * 136 + mq], A + (long)(kb + k) * lda + m0 + mq);
            }
        }
        if (HB) {
            __half* bs = BsmH + st * BSZH;
            int k = tid >> 4, nq = (tid & 15) * 8;
            cpa16(&bs[k * 136 + nq], BmH + (long)(kb + k) * ldb + n0 + nq);
        } else {
            float* bs = BsmF + st * BSZH;
#pragma unroll
            for (int f = 0; f < 2; f++) {
                int cid = tid + f * 256;
                int k = cid >> 5, nq = (cid & 31) * 4;
                cpa16(&bs[k * 136 + nq], Bm + (long)(kb + k) * ldb + n0 + nq);
            }
        }
    };

    if (EPI == 9) {
        if (tid < 128) sgacc[tid] = 0.f;
    }

    int nT = K >> 4;
#pragma unroll
    for (int s = 0; s < STG - 1; s++) {
        if (s < nT) issue(s, s << 4);
        CP_COMMIT();
    }

    for (int t = 0; t < nT; t++) {
        CP_WAIT1();
        __syncthreads();
        int nx = t + STG - 1;
        if (nx < nT) issue(nx % STG, nx << 4);
        CP_COMMIT();

        const float* as = Asm + (t % STG) * ASZ;
        const float*  bsF = BsmF + (t % STG) * BSZH;
        const __half* bsH = BsmH + (t % STG) * BSZH;
        unsigned asb = (unsigned)__cvta_generic_to_shared(as);
#pragma unroll
        for (int s = 0; s < 2; s++) {
            int k0 = s * 8 + tg;
            unsigned af[MA][4], bf[4][2];
            if (!TA) {
#pragma unroll
                for (int ma = 0; ma < MA; ma++) {
                    unsigned addr = asb + (unsigned)(((ldsmRow + ma * 16) * 20 + s * 8 + ldsmK4) * 4);
                    ldsm4(af[ma][0], af[ma][1], af[ma][2], af[ma][3], addr);
                }
            } else {
#pragma unroll
                for (int ma = 0; ma < MA; ma++) {
                    int rb = wr * WM + ma * 16 + g;
                    af[ma][0] = __float_as_uint(as[k0 * 136 + rb]);
                    af[ma][1] = __float_as_uint(as[k0 * 136 + rb + 8]);
                    af[ma][2] = __float_as_uint(as[(k0 + 4) * 136 + rb]);
                    af[ma][3] = __float_as_uint(as[(k0 + 4) * 136 + rb + 8]);
                }
            }
#pragma unroll
            for (int na = 0; na < 4; na++) {
                int nb = wc * 32 + na * 8 + g;
                if (HB) {
                    bf[na][0] = __float_as_uint(__half2float(bsH[k0 * 136 + nb]));
                    bf[na][1] = __float_as_uint(__half2float(bsH[(k0 + 4) * 136 + nb]));
                } else {
                    bf[na][0] = __float_as_uint(bsF[k0 * 136 + nb]);
                    bf[na][1] = __float_as_uint(bsF[(k0 + 4) * 136 + nb]);
                }
            }
#pragma unroll
            for (int na = 0; na < 4; na++)
#pragma unroll
                for (int ma = 0; ma < MA; ma++)
                    mma8(acc[ma][na], af[ma], bf[na][0], bf[na][1]);
        }
    }

    if (EPI == 9) {
        // dH = acc; s_g[chunk, c] = -sum_rows dH[r,c] * K[r,c] * rsK[r]
#pragma unroll
        for (int na = 0; na < 4; na++) {
#pragma unroll
            for (int half = 0; half < 2; half++) {
                int c = n0 + wc * 32 + na * 8 + tg * 2 + half;
                float csum = 0.f;
#pragma unroll
                for (int ma = 0; ma < MA; ma++)
#pragma unroll
                    for (int ih = 0; ih < 2; ih++) {
                        int i = ih * 2 + half;
                        int r = m0 + wr * WM + ma * 16 + g + ih * 8;
                        csum += acc[ma][na][i] * x0[(long)r * DH + c] * x1[r];
                    }
                for (int o = 16; o >= 4; o >>= 1)
                    csum += __shfl_down_sync(0xffffffffu, csum, o);
                if (g == 0) atomicAdd(&sgacc[wc * 32 + na * 8 + tg * 2 + half], csum);
            }
        }
        __syncthreads();
        if (tid < 128) C[(long)blockIdx.y * DH + tid] = -sgacc[tid];
        return;
    }

    // epilogue
#pragma unroll
    for (int ma = 0; ma < MA; ma++) {
#pragma unroll
        for (int na = 0; na < 4; na++) {
#pragma unroll
            for (int i = 0; i < 4; i++) {
                int r = m0 + wr * WM + ma * 16 + g + ((i >= 2) ? 8 : 0);
                int c = n0 + wc * 32 + na * 8 + tg * 2 + (i & 1);
                float v = acc[ma][na][i];
                if (EPI == 0) {
                    C[(long)r * ldc + c] = v;
                } else if (EPI == 8) {
                    Ch[(long)r * ldc + c] = __float2half(-v);
                } else if (EPI == 1) {
                    int b = r / SEQN, n = r % SEQN, h = c / DH, d = c % DH;
                    C[(long)(((b * NH + h) * SEQN) + n) * DH + d] = rndf(v);
                } else if (EPI == 2) {
                    x3[(long)r * ldc + c] = v;
                    C[(long)r * ldc + c]  = rndf(gelu_f(v));
                } else if (EPI == 3) {
                    float pred = v + x0[(long)r * DH + c];
                    int bh = r / SEQN, n = r % SEQN;
                    int b = bh / NH, h = bh % NH;
                    float lr = x2[(b * SEQN + n) * NH + h];
                    C[(long)r * DH + c] = rndf((2.0f / DH) * lr * (pred - x1[(long)r * DH + c]));
                } else if (EPI == 4) {
                    float a1 = x0[(long)r * ldc + c];
                    C[(long)r * ldc + c] = rndf(v * gelup_f(a1));
                } else if (EPI == 6) {
                    C[(long)r * ldc + c] = rndf(gelu_f(v));
                } else if (EPI == 7) {
                    float y = v + x0[(long)z * CH * DH + r * DH + c];
                    int bh = z / NC, cc = z % NC;
                    int n = cc * CH + r;
                    int b = bh / NH, h = bh % NH;
                    float gate = x1[(b * SEQN + n) * NH + h];
                    x3[(long)(b * SEQN + n) * DIM + h * DH + c] = rndf(y * gate);
                }
            }
        }
    }
}

constexpr int smem_bytes(int BM, bool TA, bool HB) {
    return 3 * ((TA ? 16 * 136 : BM * 20) * 4 + 16 * 136 * (HB ? 2 : 4));
}

// ---------------- launch ----------------
extern "C" void kernel_launch(void* const* d_in, const int* in_sizes, int n_in,
                              void* d_out, int out_size) {
    const float* seq   = (const float*)d_in[0];
    const float* gsto  = (const float*)d_in[1];
    const float* gret  = (const float*)d_in[2];
    const float* Wq    = (const float*)d_in[3];
    const float* Wk    = (const float*)d_in[4];
    const float* Wv    = (const float*)d_in[5];
    const float* Wa    = (const float*)d_in[6];
    const float* ba    = (const float*)d_in[7];
    const float* Wm    = (const float*)d_in[8];
    const float* Wd    = (const float*)d_in[9];
    const float* bd    = (const float*)d_in[10];
    const float* Wg    = (const float*)d_in[11];
    const float* Wc    = (const float*)d_in[12];
    const float* memg  = (const float*)d_in[13];
    const float* w1    = (const float*)d_in[14];
    const float* w2    = (const float*)d_in[15];
    float* out = (float*)d_out;

    float *p_xs, *p_xr, *p_KVQ, *p_lr, *p_gate, *p_Hs, *p_rsK, *p_A1, *p_GA,
          *p_dA1, *p_dY, *p_sg, *p_Gp, *p_Hq, *p_R, *p_w1T, *p_w2T,
          *p_Wr, *p_Wcr, *p_w1r, *p_w2r;
    __half *p_sw1h, *p_sw2h, *p_Wp1h, *p_Wp2h;
    cudaGetSymbolAddress((void**)&p_xs, g_xs);
    cudaGetSymbolAddress((void**)&p_xr, g_xr);
    cudaGetSymbolAddress((void**)&p_KVQ, g_KVQ);
    cudaGetSymbolAddress((void**)&p_lr, g_lr);
    cudaGetSymbolAddress((void**)&p_gate, g_gate);
    cudaGetSymbolAddress((void**)&p_Hs, g_Hs);
    cudaGetSymbolAddress((void**)&p_rsK, g_rsK);
    cudaGetSymbolAddress((void**)&p_A1, g_A1);
    cudaGetSymbolAddress((void**)&p_GA, g_GA);
    cudaGetSymbolAddress((void**)&p_dA1, g_dA1);
    cudaGetSymbolAddress((void**)&p_dY, g_dY);
    cudaGetSymbolAddress((void**)&p_sw1h, g_sw1h);
    cudaGetSymbolAddress((void**)&p_sw2h, g_sw2h);
    cudaGetSymbolAddress((void**)&p_sg, g_sg);
    cudaGetSymbolAddress((void**)&p_Wp1h, g_Wp1h);
    cudaGetSymbolAddress((void**)&p_Wp2h, g_Wp2h);
    cudaGetSymbolAddress((void**)&p_Gp, g_Gp);
    cudaGetSymbolAddress((void**)&p_Hq, g_Hq);
    cudaGetSymbolAddress((void**)&p_R, g_R);
    cudaGetSymbolAddress((void**)&p_w1T, g_w1T);
    cudaGetSymbolAddress((void**)&p_w2T, g_w2T);
    cudaGetSymbolAddress((void**)&p_Wr, g_Wr);
    cudaGetSymbolAddress((void**)&p_Wcr, g_Wcr);
    cudaGetSymbolAddress((void**)&p_w1r, g_w1r);
    cudaGetSymbolAddress((void**)&p_w2r, g_w2r);

    float* p_K = p_KVQ;
    float* p_V = p_KVQ + RWSDH;
    float* p_Q = p_KVQ + 2 * RWSDH;

    constexpr int S128  = smem_bytes(128, false, false);
    constexpr int S128T = smem_bytes(128, true,  false);
    constexpr int S64   = smem_bytes(64,  false, false);
    constexpr int S64H  = smem_bytes(64,  false, true);
    cudaFuncSetAttribute(gmma<128, 1, false, false>, cudaFuncAttributeMaxDynamicSharedMemorySize, S128);
    cudaFuncSetAttribute(gmma<128, 2, false, false>, cudaFuncAttributeMaxDynamicSharedMemorySize, S128);
    cudaFuncSetAttribute(gmma<64, 3, false, false>,  cudaFuncAttributeMaxDynamicSharedMemorySize, S64);
    cudaFuncSetAttribute(gmma<128, 4, false, false>, cudaFuncAttributeMaxDynamicSharedMemorySize, S128);
    cudaFuncSetAttribute(gmma<64, 9, false, false>,  cudaFuncAttributeMaxDynamicSharedMemorySize, S64);
    cudaFuncSetAttribute(gmma<64, 0, false, false>,  cudaFuncAttributeMaxDynamicSharedMemorySize, S64);
    cudaFuncSetAttribute(gmma<128, 8, true, false>,  cudaFuncAttributeMaxDynamicSharedMemorySize, S128T);
    cudaFuncSetAttribute(gmma<64, 6, false, true>,   cudaFuncAttributeMaxDynamicSharedMemorySize, S64H);
    cudaFuncSetAttribute(gmma<64, 7, false, true>,   cudaFuncAttributeMaxDynamicSharedMemorySize, S64H);

    // 0) rounded weight copies + rounded transposes (one launch)
    prep_kernel<<<dim3(1024, 8), 256>>>(Wk, Wv, Wq, Wc, w1, w2);

    // 1) rmsnorm of seq -> xs, xr (+ fused lr/gate)
    rmsseq_kernel<<<TOK, 256>>>(seq, gsto, gret, Wa, ba, Wg);

    // 2) fused QKV projections -> head-major K|V|Q
    gmma<128, 1, false, false><<<dim3(4, 32, 3), 256, S128>>>(p_xs, p_Wr, p_KVQ, DIM, DIM, DIM, 0,
        0, 0, 0, p_xr, p_Wr + DIM * DIM, p_Wr + 2 * DIM * DIM, nullptr);

    // 4) beta, alpha (two-stage pooling)
    pool1_kernel<<<dim3(Bb * NC, 8), 512>>>();
    pool2_kernel<<<Bb * NC, 512>>>(Wm, Wd, bd);

    // 5) Hs = rmsnorm(K, mem_g)
    rmshead_kernel<<<RWS, 128>>>(memg);

    // 7) A1 = Hs @ w1 ; GA = gelu(A1)
    gmma<128, 2, false, false><<<dim3(4, 128), 256, S128>>>(p_Hs, p_w1r, p_GA, DH, DH, DHID, DHID,
        0, 0, 0, nullptr, nullptr, nullptr, p_A1);
    // 8) pred = GA @ w2 + K -> dY
    gmma<64, 3, false, false><<<dim3(1, 256), 256, S64>>>(p_GA, p_w2r, p_dY, DHID, DHID, DH, DH,
        0, 0, 0, p_K, p_V, p_lr, nullptr);
    // 9) dA1 = (dY @ w2^T) * gelu'(A1)
    gmma<128, 4, false, false><<<dim3(4, 128), 256, S128>>>(p_dY, p_w2T, p_dA1, DH, DH, DHID, DHID,
        0, 0, 0, p_A1, nullptr, nullptr, nullptr);
    // 10+13) s_g = -colsum(dH * K * rsK) fused into dH GEMM (block == chunk)
    gmma<64, 9, false, false><<<dim3(1, 256), 256, S64>>>(p_dA1, p_w1T, p_sg, DHID, DHID, DH, DH,
        0, 0, 0, p_K, p_rsK, nullptr, nullptr);

    // 11) sW1[z] = -Hs_z^T @ dA1_z -> half
    gmma<128, 8, true, false><<<dim3(4, 1, NCHUNK), 256, S128T>>>(p_Hs, p_dA1, (float*)p_sw1h,
        CH, DH, DHID, DHID,
        (long)CH * DH, (long)CH * DHID, (long)DH * DHID, nullptr, nullptr, nullptr, nullptr);
    // 12) sW2[z] = -GA_z^T @ dY_z -> half
    gmma<128, 8, true, false><<<dim3(1, 4, NCHUNK), 256, S128T>>>(p_GA, p_dY, (float*)p_sw2h,
        CH, DHID, DH, DH,
        (long)CH * DHID, (long)CH * DH, (long)DHID * DH, nullptr, nullptr, nullptr, nullptr);

    // 14) half scans -> causal w_prev (half) + Gp
    scanh_kernel<<<dim3(32, BH, 2), 256>>>(p_sw1h, w1, p_Wp1h, p_sw2h, w2, p_Wp2h);
    scan_kernel<<<dim3(1, BH), 256>>>(p_sg, memg, p_Gp, DH);

    // 15) Hq = rmsnorm(Q, Gp[chunk])
    hq_kernel<<<RWS, 128>>>();

    // 16) retrieval GEMM1: GAq = gelu(Hq @ Wp1[z])  (B half)
    gmma<64, 6, false, true><<<dim3(4, 1, NCHUNK), 256, S64H>>>(p_Hq, (const float*)p_Wp1h, p_GA,
        DH, DH, DHID, DHID,
        (long)CH * DH, (long)DH * DHID, (long)CH * DHID, nullptr, nullptr, nullptr, nullptr);
    // 17) retrieval GEMM2: y = GAq @ Wp2[z] + q ; gated -> g_R  (B half)
    gmma<64, 7, false, true><<<dim3(1, 1, NCHUNK), 256, S64H>>>(p_GA, (const float*)p_Wp2h, p_R,
        DHID, DHID, DH, DH,
        (long)CH * DHID, (long)DHID * DH, 0, p_Q, p_gate, nullptr, p_R);
    // 18) out = R @ Wc  (BM=64 -> full wave)
    gmma<64, 0, false, false><<<dim3(4, 64), 256, S64>>>(p_R, p_Wcr, out, DIM, DIM, DIM, DIM,
        0, 0, 0, nullptr, nullptr, nullptr, nullptr);
}

// round 15
// speedup vs baseline: 3.1348x; 1.1447x over previous
#include <cuda_runtime.h>
#include <cuda_fp16.h>
#include <math.h>

// ---------------- problem constants ----------------
constexpr int Bb   = 2;
constexpr int SEQN = 2048;
constexpr int DIM  = 512;
constexpr int NH   = 4;
constexpr int DH   = 128;
constexpr int CH   = 64;
constexpr int NC   = 32;
constexpr int DHID = 512;
constexpr int BH   = 8;
constexpr int TOK  = Bb * SEQN;      // 4096
constexpr int RWS  = BH * SEQN;      // 16384
constexpr int NCHUNK = BH * NC;      // 256
constexpr long RWSDH = (long)RWS * DH;

// ---------------- device scratch ----------------
__device__ __half g_xsh[TOK * DIM];
__device__ __half g_xrh[TOK * DIM];
__device__ float g_KVQ[3 * RWS * DH];          // K | V | Q  (fp32)
__device__ float g_lr[TOK * NH];
__device__ float g_gate[TOK * NH];
__device__ float g_beta[Bb * NC * NH];
__device__ float g_alpha[Bb * NC * NH];
__device__ __half g_Hsh[RWS * DH];
__device__ float g_rsK[RWS];
__device__ float g_A1[RWS * DHID];             // fp32 (epilogue-only)
__device__ __half g_GAh[RWS * DHID];
__device__ __half g_dA1h[RWS * DHID];
__device__ __half g_dYh[RWS * DH];
__device__ __half g_sw1h[NCHUNK * DH * DHID];
__device__ __half g_sw2h[NCHUNK * DHID * DH];
__device__ float  g_sg[NCHUNK * DH];
__device__ __half g_Wp1h[NCHUNK * DH * DHID];
__device__ __half g_Wp2h[NCHUNK * DHID * DH];
__device__ float g_Gp[NCHUNK * DH];
__device__ __half g_Hqh[RWS * DH];
__device__ __half g_Rh[TOK * DIM];
__device__ __half g_w1Th[DHID * DH];
__device__ __half g_w2Th[DH * DHID];
__device__ float g_poolp[Bb * NC * 8 * DIM];
// fp16 weight copies
__device__ __half g_Wrh[3 * DIM * DIM];        // Wk | Wv | Wq
__device__ __half g_Wcrh[DIM * DIM];
__device__ __half g_w1rh[DH * DHID];
__device__ __half g_w2rh[DHID * DH];

// ---------------- math helpers ----------------
__device__ __forceinline__ float sigmf(float x) { return 1.0f / (1.0f + expf(-x)); }
__device__ __forceinline__ float gelu_f(float x) {
    return 0.5f * x * (1.0f + erff(x * 0.70710678118654752f));
}
__device__ __forceinline__ float gelup_f(float x) {
    return 0.5f * (1.0f + erff(x * 0.70710678118654752f))
         + x * 0.3989422804014327f * expf(-0.5f * x * x);
}
__device__ __forceinline__ float rndf(float x) {      // tf32 round (fp32 KVQ path)
    asm("cvt.rna.tf32.f32 %0, %1;" : "=f"(x) : "f"(x));
    return x;
}
__device__ __forceinline__ void mma16(float c[4], const unsigned a[4],
                                      unsigned b0, unsigned b1) {
    asm volatile(
        "mma.sync.aligned.m16n8k16.row.col.f32.f16.f16.f32 "
        "{%0,%1,%2,%3},{%4,%5,%6,%7},{%8,%9},{%0,%1,%2,%3};"
        : "+f"(c[0]), "+f"(c[1]), "+f"(c[2]), "+f"(c[3])
        : "r"(a[0]), "r"(a[1]), "r"(a[2]), "r"(a[3]), "r"(b0), "r"(b1));
}
__device__ __forceinline__ void ldsm4(unsigned& r0, unsigned& r1, unsigned& r2,
                                      unsigned& r3, unsigned addr) {
    asm volatile("ldmatrix.sync.aligned.m8n8.x4.shared.b16 {%0,%1,%2,%3}, [%4];"
                 : "=r"(r0), "=r"(r1), "=r"(r2), "=r"(r3) : "r"(addr));
}
__device__ __forceinline__ void ldsm4t(unsigned& r0, unsigned& r1, unsigned& r2,
                                       unsigned& r3, unsigned addr) {
    asm volatile("ldmatrix.sync.aligned.m8n8.x4.trans.shared.b16 {%0,%1,%2,%3}, [%4];"
                 : "=r"(r0), "=r"(r1), "=r"(r2), "=r"(r3) : "r"(addr));
}
__device__ __forceinline__ void cpa16(void* s, const void* g) {
    unsigned sa = (unsigned)__cvta_generic_to_shared(s);
    asm volatile("cp.async.cg.shared.global [%0], [%1], 16;\n" :: "r"(sa), "l"(g));
}
#define CP_COMMIT() asm volatile("cp.async.commit_group;\n" ::: "memory")
#define CP_WAIT1()  asm volatile("cp.async.wait_group 1;\n" ::: "memory")

// --------- prep: fp16 weight copies + fp16 weight transposes ---------
__global__ void prep_kernel(const float* __restrict__ Wk, const float* __restrict__ Wv,
                            const float* __restrict__ Wq, const float* __restrict__ Wc,
                            const float* __restrict__ w1, const float* __restrict__ w2) {
    int z = blockIdx.y;
    int idx = blockIdx.x * 256 + threadIdx.x;
    if (z < 3) {
        if (idx < DIM * DIM) g_Wrh[z * DIM * DIM + idx] =
            __float2half(z == 0 ? Wk[idx] : z == 1 ? Wv[idx] : Wq[idx]);
    } else if (z == 3) {
        if (idx < DIM * DIM) g_Wcrh[idx] = __float2half(Wc[idx]);
    } else if (z == 4) {
        if (idx < DH * DHID) g_w1rh[idx] = __float2half(w1[idx]);
    } else if (z == 5) {
        if (idx < DHID * DH) g_w2rh[idx] = __float2half(w2[idx]);
    } else if (z == 6) {
        if (idx < DH * DHID) {
            int r = idx / DHID, c = idx % DHID;
            g_w1Th[c * DH + r] = __float2half(w1[idx]);
        }
    } else {
        if (idx < DHID * DH) {
            int r = idx / DH, c = idx % DH;
            g_w2Th[c * DHID + r] = __float2half(w2[idx]);
        }
    }
}

// ------- rmsnorm over DIM=512 (xs, xr half) + fused lr/gate -------
__global__ void rmsseq_kernel(const float* __restrict__ seq,
                              const float* __restrict__ gs,
                              const float* __restrict__ gr,
                              const float* __restrict__ Wa,
                              const float* __restrict__ ba,
                              const float* __restrict__ Wg) {
    int t = blockIdx.x;
    int tid = threadIdx.x;
    int lane = tid & 31, warp = tid >> 5;
    float x0 = seq[t * DIM + tid];
    float x1 = seq[t * DIM + tid + 256];
    float ss = x0 * x0 + x1 * x1;
    for (int o = 16; o; o >>= 1) ss += __shfl_down_sync(0xffffffffu, ss, o);
    __shared__ float sm[8];
    __shared__ float sma[8][4], smg[8][4];
    if (lane == 0) sm[warp] = ss;
    __syncthreads();
    float tot = 0.f;
#pragma unroll
    for (int i = 0; i < 8; i++) tot += sm[i];
    float rs = rsqrtf(tot * (1.0f / DIM) + 1e-6f);
    float a0 = x0 * rs * gs[tid],       a1 = x1 * rs * gs[tid + 256];
    float r0 = x0 * rs * gr[tid],       r1 = x1 * rs * gr[tid + 256];
    g_xsh[t * DIM + tid]       = __float2half(a0);
    g_xsh[t * DIM + tid + 256] = __float2half(a1);
    g_xrh[t * DIM + tid]       = __float2half(r0);
    g_xrh[t * DIM + tid + 256] = __float2half(r1);
    float pa[4], pg[4];
#pragma unroll
    for (int h = 0; h < 4; h++) {
        pa[h] = a0 * Wa[tid * NH + h] + a1 * Wa[(tid + 256) * NH + h];
        pg[h] = r0 * Wg[tid * NH + h] + r1 * Wg[(tid + 256) * NH + h];
    }
#pragma unroll
    for (int o = 16; o; o >>= 1)
#pragma unroll
        for (int h = 0; h < 4; h++) {
            pa[h] += __shfl_down_sync(0xffffffffu, pa[h], o);
            pg[h] += __shfl_down_sync(0xffffffffu, pg[h], o);
        }
    if (lane == 0)
#pragma unroll
        for (int h = 0; h < 4; h++) { sma[warp][h] = pa[h]; smg[warp][h] = pg[h]; }
    __syncthreads();
    if (tid < 4) {
        float sa = 0.f, sg2 = 0.f;
#pragma unroll
        for (int i = 0; i < 8; i++) { sa += sma[i][tid]; sg2 += smg[i][tid]; }
        g_lr[t * NH + tid]   = sigmf(sa + ba[tid]);
        g_gate[t * NH + tid] = sigmf(sg2);
    }
}

// ---------------- pooled chunk stats: stage 1 ----------------
__global__ void pool1_kernel() {
    int bc = blockIdx.x, seg = blockIdx.y;
    int tid = threadIdx.x;
    int b = bc / NC, c = bc % NC;
    int t0 = b * SEQN + c * CH + seg * 8;
    float s = 0.f;
#pragma unroll
    for (int i = 0; i < 8; i++) s += __half2float(g_xsh[(t0 + i) * DIM + tid]);
    g_poolp[(bc * 8 + seg) * DIM + tid] = s;
}

// ---------------- pooled chunk stats: stage 2 ----------------
__global__ void pool2_kernel(const float* __restrict__ Wm, const float* __restrict__ Wd,
                             const float* __restrict__ bd) {
    int bc = blockIdx.x;
    int tid = threadIdx.x;
    __shared__ float pooled[DIM];
    float s = 0.f;
#pragma unroll
    for (int seg = 0; seg < 8; seg++) s += g_poolp[(bc * 8 + seg) * DIM + tid];
    pooled[tid] = s * (1.0f / CH);
    __syncthreads();
    if (tid < 128) {
        int lane = tid & 31, h = tid >> 5;
        float am = 0.f, ad = 0.f;
        for (int d = lane; d < DIM; d += 32) {
            am += pooled[d] * Wm[d * NH + h];
            ad += pooled[d] * Wd[d * NH + h];
        }
        for (int o = 16; o; o >>= 1) {
            am += __shfl_down_sync(0xffffffffu, am, o);
            ad += __shfl_down_sync(0xffffffffu, ad, o);
        }
        if (lane == 0) {
            g_beta[bc * NH + h]  = sigmf(am);
            g_alpha[bc * NH + h] = 1.0f - sigmf(ad + bd[h]);
        }
    }
}

// ---------------- rmsnorm over DH=128 for K -> Hs (half) ----------------
__global__ void rmshead_kernel(const float* __restrict__ memg) {
    int r = blockIdx.x;
    int d = threadIdx.x;
    float x = g_KVQ[(long)r * DH + d];          // K
    float ss = x * x;
    for (int o = 16; o; o >>= 1) ss += __shfl_down_sync(0xffffffffu, ss, o);
    __shared__ float sm[4];
    if ((d & 31) == 0) sm[d >> 5] = ss;
    __syncthreads();
    float tot = sm[0] + sm[1] + sm[2] + sm[3];
    float rs = rsqrtf(tot * (1.0f / DH) + 1e-6f);
    g_Hsh[r * DH + d] = __float2half(x * rs * memg[d]);
    if (d == 0) g_rsK[r] = rs;
}

// ---------------- rmsnorm for Q with per-chunk Gp -> Hq (half) ----------------
__global__ void hq_kernel() {
    int r = blockIdx.x;
    int d = threadIdx.x;
    int bh = r / SEQN, n = r % SEQN, c = n / CH;
    float x = g_KVQ[2 * RWSDH + (long)r * DH + d];   // Q
    float ss = x * x;
    for (int o = 16; o; o >>= 1) ss += __shfl_down_sync(0xffffffffu, ss, o);
    __shared__ float sm[4];
    if ((d & 31) == 0) sm[d >> 5] = ss;
    __syncthreads();
    float tot = sm[0] + sm[1] + sm[2] + sm[3];
    float rs = rsqrtf(tot * (1.0f / DH) + 1e-6f);
    g_Hqh[r * DH + d] = __float2half(x * rs * g_Gp[(bh * NC + c) * DH + d]);
}

// --------- combined big scans over half tensors ---------
__global__ void scanh_kernel(const __half* __restrict__ s1, const float* __restrict__ i1,
                             __half* __restrict__ o1,
                             const __half* __restrict__ s2, const float* __restrict__ i2,
                             __half* __restrict__ o2) {
    constexpr long SZ = (long)DH * DHID;       // 65536 halves
    const __half* s; const float* init; __half* wprev;
    if (blockIdx.z == 0) { s = s1; init = i1; wprev = o1; }
    else                 { s = s2; init = i2; wprev = o2; }
    int bh = blockIdx.y;
    long e8 = ((long)blockIdx.x * 256 + threadIdx.x) * 8;
    if (e8 >= SZ) return;
    int b = bh / NH, h = bh % NH;

    float m[8], w[8];
#pragma unroll
    for (int j = 0; j < 8; j++) { m[j] = 0.f; w[j] = init[e8 + j]; }

    auto store8 = [&](long off, const float* v) {
        __half2 hv[4];
#pragma unroll
        for (int j = 0; j < 4; j++)
            hv[j] = __floats2half2_rn(v[2 * j], v[2 * j + 1]);
        *(uint4*)(wprev + off) = *(const uint4*)hv;
    };
    auto load8 = [&](long off, float* v) {
        uint4 raw = *(const uint4*)(s + off);
        const __half2* h2 = (const __half2*)&raw;
#pragma unroll
        for (int j = 0; j < 4; j++) {
            float2 f = __half22float2(h2[j]);
            v[2 * j] = f.x; v[2 * j + 1] = f.y;
        }
    };

    store8((long)(bh * NC) * SZ + e8, w);
    float sv[8];
    load8((long)(bh * NC) * SZ + e8, sv);
    for (int t = 0; t < NC; t++) {
        float nx[8];
        if (t + 1 < NC) load8((long)(bh * NC + t + 1) * SZ + e8, nx);
        float beta  = g_beta[(b * NC + t) * NH + h];
        float alpha = g_alpha[(b * NC + t) * NH + h];
#pragma unroll
        for (int j = 0; j < 8; j++) {
            m[j] = beta * m[j] + sv[j];
            w[j] = alpha * w[j] + m[j];
        }
        if (t < NC - 1) {
            store8((long)(bh * NC + t + 1) * SZ + e8, w);
#pragma unroll
            for (int j = 0; j < 8; j++) sv[j] = nx[j];
        }
    }
}

// ---------------- small scan for s_g -> Gp ----------------
__global__ void scan_kernel(const float* __restrict__ s, const float* __restrict__ init,
                            float* __restrict__ wprev, int sz) {
    int bh = blockIdx.y;
    int e = blockIdx.x * 256 + threadIdx.x;
    if (e >= sz) return;
    int b = bh / NH, h = bh % NH;
    float m = 0.f, w = init[e];
    wprev[(long)(bh * NC) * sz + e] = rndf(w);
    for (int t = 0; t < NC; t++) {
        float beta  = g_beta[(b * NC + t) * NH + h];
        float alpha = g_alpha[(b * NC + t) * NH + h];
        m = beta * m + s[(long)(bh * NC + t) * sz + e];
        w = alpha * w + m;
        if (t < NC - 1) wprev[(long)(bh * NC + t + 1) * sz + e] = rndf(w);
    }
}

// ======= fp16 tensor-core GEMM (m16n8k16), BMx128 tile, cp.async + ldmatrix =======
// EPI: 0 plain fp32 C, 1 fused QKV -> fp32 KVQ, 2 A1(fp32)+gelu->half, 3 pred->dY half,
//      4 *gelu'(A1)->half, 6 gelu->half, 7 gated retrieval ->half x3, 8 negate->half C,
//      9 fused dH->s_g reduction (fp32 C)
// TA: C = op(A^T B), A stored [K][M] half
template <int BM, int EPI, bool TA>
__global__ void __launch_bounds__(256, 2) gmma(
    const __half* __restrict__ A, const __half* __restrict__ Bm, void* __restrict__ Cv,
    int K, int lda, int ldb, int ldc,
    long sA, long sB, long sC,
    const float* __restrict__ f0, const float* __restrict__ f1,
    const float* __restrict__ f2, void* __restrict__ x3,
    const __half* __restrict__ h0) {
    constexpr int STG = 3;
    constexpr int WM  = BM / 2;
    constexpr int MA  = WM / 16;
    constexpr int ASZ = TA ? 16 * 136 : BM * 24;     // halves
    constexpr int BSZ = 16 * 136;                    // halves

    int z = blockIdx.z;
    float* C = (float*)Cv;
    __half* Ch = (__half*)Cv;
    if (EPI == 1) {
        if (z == 2) A = h0;
        Bm += (long)z * DIM * DIM;
        C += (long)z * RWSDH;
    } else {
        A += (long)z * sA;
        Bm += (long)z * sB;
        if (EPI == 8) Ch += (long)z * sC;
        else if (EPI == 0 || EPI == 9) C += (long)z * sC;
        else Ch += (long)z * sC;
    }

    extern __shared__ char smraw[];
    __half* Asm = (__half*)smraw;
    __half* Bsm = Asm + STG * ASZ;
    __shared__ float sgacc[128];

    int tid = threadIdx.x;
    int warp = tid >> 5, lane = tid & 31;
    int g = lane >> 2, tg = lane & 3;
    int wr = warp >> 2, wc = warp & 3;
    int m0 = blockIdx.y * BM, n0 = blockIdx.x * 128;

    float acc[MA][4][4];
#pragma unroll
    for (int i = 0; i < MA; i++)
#pragma unroll
        for (int j = 0; j < 4; j++)
#pragma unroll
            for (int l = 0; l < 4; l++) acc[i][j][l] = 0.f;

    auto issue = [&](int st, int kb) {
        __half* as = Asm + st * ASZ;
        __half* bs = Bsm + st * BSZ;
        if (!TA) {
            if (BM == 128 || tid < 128) {
                int m = tid >> 1, kh = (tid & 1) * 8;
                cpa16(&as[m * 24 + kh], A + (long)(m0 + m) * lda + kb + kh);
            }
        } else {
            int k = tid >> 4, m8 = (tid & 15) * 8;
            cpa16(&as[k * 136 + m8], A + (long)(kb + k) * lda + m0 + m8);
        }
        {
            int k = tid >> 4, n8 = (tid & 15) * 8;
            cpa16(&bs[k * 136 + n8], Bm + (long)(kb + k) * ldb + n0 + n8);
        }
    };

    if (EPI == 9) {
        if (tid < 128) sgacc[tid] = 0.f;
    }

    int nT = K >> 4;
#pragma unroll
    for (int s = 0; s < STG - 1; s++) {
        if (s < nT) issue(s, s << 4);
        CP_COMMIT();
    }

    for (int t = 0; t < nT; t++) {
        CP_WAIT1();
        __syncthreads();
        int nx = t + STG - 1;
        if (nx < nT) issue(nx % STG, nx << 4);
        CP_COMMIT();

        const __half* as = Asm + (t % STG) * ASZ;
        const __half* bs = Bsm + (t % STG) * BSZ;
        unsigned asb = (unsigned)__cvta_generic_to_shared(as);
        unsigned bsb = (unsigned)__cvta_generic_to_shared(bs);

        unsigned af[MA][4], bf[4][2];
        if (!TA) {
            // A row-major [BM][24]h: lanes 0-15 rows, lanes 16-31 khalf+8
            int arow = lane & 15, ak = (lane >> 4) * 8;
#pragma unroll
            for (int ma = 0; ma < MA; ma++) {
                unsigned addr = asb + 2u * (unsigned)((wr * WM + ma * 16 + arow) * 24 + ak);
                ldsm4(af[ma][0], af[ma][1], af[ma][2], af[ma][3], addr);
            }
        } else {
            // A stored [16 k][M]h: trans load -> A^T fragments
            int krow = (lane & 7) + (lane >> 4) * 8;
            int moff = ((lane >> 3) & 1) * 8;
#pragma unroll
            for (int ma = 0; ma < MA; ma++) {
                int R = wr * WM + ma * 16;
                unsigned addr = asb + 2u * (unsigned)(krow * 136 + R + moff);
                ldsm4t(af[ma][0], af[ma][1], af[ma][2], af[ma][3], addr);
            }
        }
        {
            // B stored [16 k][128 n]h: trans load, two x4 per warp (n0..15, n16..31)
            int krow = lane & 15;
            int nhi = (lane >> 4) * 8;
#pragma unroll
            for (int h = 0; h < 2; h++) {
                unsigned r0, r1, r2, r3;
                unsigned addr = bsb + 2u * (unsigned)(krow * 136 + wc * 32 + h * 16 + nhi);
                ldsm4t(r0, r1, r2, r3, addr);
                bf[2 * h][0] = r0; bf[2 * h][1] = r1;
                bf[2 * h + 1][0] = r2; bf[2 * h + 1][1] = r3;
            }
        }
#pragma unroll
        for (int na = 0; na < 4; na++)
#pragma unroll
            for (int ma = 0; ma < MA; ma++)
                mma16(acc[ma][na], af[ma], bf[na][0], bf[na][1]);
    }

    if (EPI == 9) {
        // dH = acc; s_g[chunk, c] = -sum_rows dH[r,c] * K[r,c] * rsK[r]
#pragma unroll
        for (int na = 0; na < 4; na++) {
#pragma unroll
            for (int hf = 0; hf < 2; hf++) {
                int c = n0 + wc * 32 + na * 8 + tg * 2 + hf;
                float csum = 0.f;
#pragma unroll
                for (int ma = 0; ma < MA; ma++)
#pragma unroll
                    for (int ih = 0; ih < 2; ih++) {
                        int i = ih * 2 + hf;
                        int r = m0 + wr * WM + ma * 16 + g + ih * 8;
                        csum += acc[ma][na][i] * f0[(long)r * DH + c] * f1[r];
                    }
                for (int o = 16; o >= 4; o >>= 1)
                    csum += __shfl_down_sync(0xffffffffu, csum, o);
                if (g == 0) atomicAdd(&sgacc[wc * 32 + na * 8 + tg * 2 + hf], csum);
            }
        }
        __syncthreads();
        if (tid < 128) C[(long)blockIdx.y * DH + tid] = -sgacc[tid];
        return;
    }

    // epilogue
#pragma unroll
    for (int ma = 0; ma < MA; ma++) {
#pragma unroll
        for (int na = 0; na < 4; na++) {
#pragma unroll
            for (int i = 0; i < 4; i++) {
                int r = m0 + wr * WM + ma * 16 + g + ((i >= 2) ? 8 : 0);
                int c = n0 + wc * 32 + na * 8 + tg * 2 + (i & 1);
                float v = acc[ma][na][i];
                if (EPI == 0) {
                    C[(long)r * ldc + c] = v;
                } else if (EPI == 8) {
                    Ch[(long)r * ldc + c] = __float2half(-v);
                } else if (EPI == 1) {
                    int b = r / SEQN, n = r % SEQN, h = c / DH, d = c % DH;
                    C[(long)(((b * NH + h) * SEQN) + n) * DH + d] = rndf(v);
                } else if (EPI == 2) {
                    ((float*)x3)[(long)r * ldc + c] = v;
                    Ch[(long)r * ldc + c] = __float2half(gelu_f(v));
                } else if (EPI == 3) {
                    float pred = v + f0[(long)r * DH + c];
                    int bh = r / SEQN, n = r % SEQN;
                    int b = bh / NH, h = bh % NH;
                    float lr = f2[(b * SEQN + n) * NH + h];
                    Ch[(long)r * DH + c] =
                        __float2half((2.0f / DH) * lr * (pred - f1[(long)r * DH + c]));
                } else if (EPI == 4) {
                    float a1 = f0[(long)r * ldc + c];
                    Ch[(long)r * ldc + c] = __float2half(v * gelup_f(a1));
                } else if (EPI == 6) {
                    Ch[(long)r * ldc + c] = __float2half(gelu_f(v));
                } else if (EPI == 7) {
                    float y = v + f0[(long)z * CH * DH + r * DH + c];
                    int bh = z / NC, cc = z % NC;
                    int n = cc * CH + r;
                    int b = bh / NH, h = bh % NH;
                    float gate = f1[(b * SEQN + n) * NH + h];
                    ((__half*)x3)[(long)(b * SEQN + n) * DIM + h * DH + c] =
                        __float2half(y * gate);
                }
            }
        }
    }
}

constexpr int smem_bytes(int BM, bool TA) {
    return 3 * ((TA ? 16 * 136 : BM * 24) + 16 * 136) * 2;
}

// ---------------- launch ----------------
extern "C" void kernel_launch(void* const* d_in, const int* in_sizes, int n_in,
                              void* d_out, int out_size) {
    const float* seq   = (const float*)d_in[0];
    const float* gsto  = (const float*)d_in[1];
    const float* gret  = (const float*)d_in[2];
    const float* Wq    = (const float*)d_in[3];
    const float* Wk    = (const float*)d_in[4];
    const float* Wv    = (const float*)d_in[5];
    const float* Wa    = (const float*)d_in[6];
    const float* ba    = (const float*)d_in[7];
    const float* Wm    = (const float*)d_in[8];
    const float* Wd    = (const float*)d_in[9];
    const float* bd    = (const float*)d_in[10];
    const float* Wg    = (const float*)d_in[11];
    const float* Wc    = (const float*)d_in[12];
    const float* memg  = (const float*)d_in[13];
    const float* w1    = (const float*)d_in[14];
    const float* w2    = (const float*)d_in[15];
    float* out = (float*)d_out;

    float *p_KVQ, *p_lr, *p_gate, *p_rsK, *p_A1, *p_sg, *p_Gp;
    __half *p_xsh, *p_xrh, *p_Hsh, *p_GAh, *p_dA1h, *p_dYh, *p_Hqh, *p_Rh,
           *p_sw1h, *p_sw2h, *p_Wp1h, *p_Wp2h, *p_w1Th, *p_w2Th,
           *p_Wrh, *p_Wcrh, *p_w1rh, *p_w2rh;
    cudaGetSymbolAddress((void**)&p_xsh, g_xsh);
    cudaGetSymbolAddress((void**)&p_xrh, g_xrh);
    cudaGetSymbolAddress((void**)&p_KVQ, g_KVQ);
    cudaGetSymbolAddress((void**)&p_lr, g_lr);
    cudaGetSymbolAddress((void**)&p_gate, g_gate);
    cudaGetSymbolAddress((void**)&p_Hsh, g_Hsh);
    cudaGetSymbolAddress((void**)&p_rsK, g_rsK);
    cudaGetSymbolAddress((void**)&p_A1, g_A1);
    cudaGetSymbolAddress((void**)&p_GAh, g_GAh);
    cudaGetSymbolAddress((void**)&p_dA1h, g_dA1h);
    cudaGetSymbolAddress((void**)&p_dYh, g_dYh);
    cudaGetSymbolAddress((void**)&p_sw1h, g_sw1h);
    cudaGetSymbolAddress((void**)&p_sw2h, g_sw2h);
    cudaGetSymbolAddress((void**)&p_sg, g_sg);
    cudaGetSymbolAddress((void**)&p_Wp1h, g_Wp1h);
    cudaGetSymbolAddress((void**)&p_Wp2h, g_Wp2h);
    cudaGetSymbolAddress((void**)&p_Gp, g_Gp);
    cudaGetSymbolAddress((void**)&p_Hqh, g_Hqh);
    cudaGetSymbolAddress((void**)&p_Rh, g_Rh);
    cudaGetSymbolAddress((void**)&p_w1Th, g_w1Th);
    cudaGetSymbolAddress((void**)&p_w2Th, g_w2Th);
    cudaGetSymbolAddress((void**)&p_Wrh, g_Wrh);
    cudaGetSymbolAddress((void**)&p_Wcrh, g_Wcrh);
    cudaGetSymbolAddress((void**)&p_w1rh, g_w1rh);
    cudaGetSymbolAddress((void**)&p_w2rh, g_w2rh);

    float* p_K = p_KVQ;
    float* p_V = p_KVQ + RWSDH;
    float* p_Q = p_KVQ + 2 * RWSDH;

    constexpr int S128  = smem_bytes(128, false);
    constexpr int S128T = smem_bytes(128, true);
    constexpr int S64   = smem_bytes(64, false);
    cudaFuncSetAttribute(gmma<128, 1, false>, cudaFuncAttributeMaxDynamicSharedMemorySize, S128);
    cudaFuncSetAttribute(gmma<128, 2, false>, cudaFuncAttributeMaxDynamicSharedMemorySize, S128);
    cudaFuncSetAttribute(gmma<64, 3, false>,  cudaFuncAttributeMaxDynamicSharedMemorySize, S64);
    cudaFuncSetAttribute(gmma<128, 4, false>, cudaFuncAttributeMaxDynamicSharedMemorySize, S128);
    cudaFuncSetAttribute(gmma<64, 9, false>,  cudaFuncAttributeMaxDynamicSharedMemorySize, S64);
    cudaFuncSetAttribute(gmma<64, 0, false>,  cudaFuncAttributeMaxDynamicSharedMemorySize, S64);
    cudaFuncSetAttribute(gmma<128, 8, true>,  cudaFuncAttributeMaxDynamicSharedMemorySize, S128T);
    cudaFuncSetAttribute(gmma<64, 6, false>,  cudaFuncAttributeMaxDynamicSharedMemorySize, S64);
    cudaFuncSetAttribute(gmma<64, 7, false>,  cudaFuncAttributeMaxDynamicSharedMemorySize, S64);

    // 0) fp16 weight copies + transposes
    prep_kernel<<<dim3(1024, 8), 256>>>(Wk, Wv, Wq, Wc, w1, w2);

    // 1) rmsnorm of seq -> xs, xr (half) + fused lr/gate
    rmsseq_kernel<<<TOK, 256>>>(seq, gsto, gret, Wa, ba, Wg);

    // 2) fused QKV projections -> head-major K|V|Q (fp32)
    gmma<128, 1, false><<<dim3(4, 32, 3), 256, S128>>>(p_xsh, p_Wrh, p_KVQ,
        DIM, DIM, DIM, 0, 0, 0, 0, nullptr, nullptr, nullptr, nullptr, p_xrh);

    // 4) beta, alpha
    pool1_kernel<<<dim3(Bb * NC, 8), 512>>>();
    pool2_kernel<<<Bb * NC, 512>>>(Wm, Wd, bd);

    // 5) Hs = rmsnorm(K, mem_g) (half)
    rmshead_kernel<<<RWS, 128>>>(memg);

    // 7) A1(fp32) = Hs @ w1 ; GA = gelu(A1) (half)
    gmma<128, 2, false><<<dim3(4, 128), 256, S128>>>(p_Hsh, p_w1rh, p_GAh,
        DH, DH, DHID, DHID, 0, 0, 0, nullptr, nullptr, nullptr, p_A1, nullptr);
    // 8) pred = GA @ w2 + K -> dY (half)
    gmma<64, 3, false><<<dim3(1, 256), 256, S64>>>(p_GAh, p_w2rh, p_dYh,
        DHID, DHID, DH, DH, 0, 0, 0, p_K, p_V, p_lr, nullptr, nullptr);
    // 9) dA1 = (dY @ w2^T) * gelu'(A1) (half)
    gmma<128, 4, false><<<dim3(4, 128), 256, S128>>>(p_dYh, p_w2Th, p_dA1h,
        DH, DH, DHID, DHID, 0, 0, 0, p_A1, nullptr, nullptr, nullptr, nullptr);
    // 10+13) s_g = -colsum(dH * K * rsK) fused into dH GEMM
    gmma<64, 9, false><<<dim3(1, 256), 256, S64>>>(p_dA1h, p_w1Th, p_sg,
        DHID, DHID, DH, DH, 0, 0, 0, p_K, p_rsK, nullptr, nullptr, nullptr);

    // 11) sW1[z] = -Hs_z^T @ dA1_z (half)
    gmma<128, 8, true><<<dim3(4, 1, NCHUNK), 256, S128T>>>(p_Hsh, p_dA1h, p_sw1h,
        CH, DH, DHID, DHID,
        (long)CH * DH, (long)CH * DHID, (long)DH * DHID, nullptr, nullptr, nullptr, nullptr, nullptr);
    // 12) sW2[z] = -GA_z^T @ dY_z (half)
    gmma<128, 8, true><<<dim3(1, 4, NCHUNK), 256, S128T>>>(p_GAh, p_dYh, p_sw2h,
        CH, DHID, DH, DH,
        (long)CH * DHID, (long)CH * DH, (long)DHID * DH, nullptr, nullptr, nullptr, nullptr, nullptr);

    // 14) scans -> causal w_prev (half) + Gp
    scanh_kernel<<<dim3(32, BH, 2), 256>>>(p_sw1h, w1, p_Wp1h, p_sw2h, w2, p_Wp2h);
    scan_kernel<<<dim3(1, BH), 256>>>(p_sg, memg, p_Gp, DH);

    // 15) Hq = rmsnorm(Q, Gp[chunk]) (half)
    hq_kernel<<<RWS, 128>>>();

    // 16) retrieval GEMM1: GAq = gelu(Hq @ Wp1[z]) (half)
    gmma<64, 6, false><<<dim3(4, 1, NCHUNK), 256, S64>>>(p_Hqh, p_Wp1h, p_GAh,
        DH, DH, DHID, DHID,
        (long)CH * DH, (long)DH * DHID, (long)CH * DHID, nullptr, nullptr, nullptr, nullptr, nullptr);
    // 17) retrieval GEMM2: y = GAq @ Wp2[z] + q ; gated -> R (half)
    gmma<64, 7, false><<<dim3(1, 1, NCHUNK), 256, S64>>>(p_GAh, p_Wp2h, nullptr,
        DHID, DHID, DH, DH,
        (long)CH * DHID, (long)DHID * DH, 0, p_Q, p_gate, nullptr, p_Rh, nullptr);
    // 18) out = R @ Wc (fp32 out)
    gmma<64, 0, false><<<dim3(4, 64), 256, S64>>>(p_Rh, p_Wcrh, out,
        DIM, DIM, DIM, DIM, 0, 0, 0, nullptr, nullptr, nullptr, nullptr, nullptr);
}

// round 16
// speedup vs baseline: 4.1480x; 1.3232x over previous
#include <cuda_runtime.h>
#include <cuda_fp16.h>
#include <math.h>

// ---------------- problem constants ----------------
constexpr int Bb   = 2;
constexpr int SEQN = 2048;
constexpr int DIM  = 512;
constexpr int NH   = 4;
constexpr int DH   = 128;
constexpr int CH   = 64;
constexpr int NC   = 32;
constexpr int DHID = 512;
constexpr int BH   = 8;
constexpr int TOK  = Bb * SEQN;      // 4096
constexpr int RWS  = BH * SEQN;      // 16384
constexpr int NCHUNK = BH * NC;      // 256
constexpr long RWSDH = (long)RWS * DH;

// ---------------- device scratch ----------------
__device__ __half g_xsh[TOK * DIM];
__device__ __half g_xrh[TOK * DIM];
__device__ __half g_KVQh[3 * RWS * DH];        // K | V | Q  (fp16)
__device__ float g_lr[TOK * NH];
__device__ float g_gate[TOK * NH];
__device__ float g_beta[Bb * NC * NH];
__device__ float g_alpha[Bb * NC * NH];
__device__ __half g_Hsh[RWS * DH];
__device__ float g_rsK[RWS];
__device__ __half g_A1h[RWS * DHID];           // fp16 pre-activation
__device__ __half g_GAh[RWS * DHID];
__device__ __half g_dA1h[RWS * DHID];
__device__ __half g_dYh[RWS * DH];
__device__ __half g_sw1h[NCHUNK * DH * DHID];
__device__ __half g_sw2h[NCHUNK * DHID * DH];
__device__ float  g_sg[NCHUNK * DH];
__device__ __half g_Wp1h[NCHUNK * DH * DHID];
__device__ __half g_Wp2h[NCHUNK * DHID * DH];
__device__ float g_Gp[NCHUNK * DH];
__device__ __half g_Hqh[RWS * DH];
__device__ __half g_Rh[TOK * DIM];
__device__ __half g_w1Th[DHID * DH];
__device__ __half g_w2Th[DH * DHID];
__device__ float g_poolp[Bb * NC * 8 * DIM];
// fp16 weight copies
__device__ __half g_Wrh[3 * DIM * DIM];        // Wk | Wv | Wq
__device__ __half g_Wcrh[DIM * DIM];
__device__ __half g_w1rh[DH * DHID];
__device__ __half g_w2rh[DHID * DH];

// ---------------- math helpers ----------------
__device__ __forceinline__ float sigmf(float x) { return 1.0f / (1.0f + expf(-x)); }
__device__ __forceinline__ float gelu_f(float x) {
    return 0.5f * x * (1.0f + erff(x * 0.70710678118654752f));
}
__device__ __forceinline__ float gelup_f(float x) {
    return 0.5f * (1.0f + erff(x * 0.70710678118654752f))
         + x * 0.3989422804014327f * expf(-0.5f * x * x);
}
__device__ __forceinline__ float rndf(float x) {
    asm("cvt.rna.tf32.f32 %0, %1;" : "=f"(x) : "f"(x));
    return x;
}
__device__ __forceinline__ void mma16(float c[4], const unsigned a[4],
                                      unsigned b0, unsigned b1) {
    asm volatile(
        "mma.sync.aligned.m16n8k16.row.col.f32.f16.f16.f32 "
        "{%0,%1,%2,%3},{%4,%5,%6,%7},{%8,%9},{%0,%1,%2,%3};"
        : "+f"(c[0]), "+f"(c[1]), "+f"(c[2]), "+f"(c[3])
        : "r"(a[0]), "r"(a[1]), "r"(a[2]), "r"(a[3]), "r"(b0), "r"(b1));
}
__device__ __forceinline__ void ldsm4(unsigned& r0, unsigned& r1, unsigned& r2,
                                      unsigned& r3, unsigned addr) {
    asm volatile("ldmatrix.sync.aligned.m8n8.x4.shared.b16 {%0,%1,%2,%3}, [%4];"
                 : "=r"(r0), "=r"(r1), "=r"(r2), "=r"(r3) : "r"(addr));
}
__device__ __forceinline__ void ldsm4t(unsigned& r0, unsigned& r1, unsigned& r2,
                                       unsigned& r3, unsigned addr) {
    asm volatile("ldmatrix.sync.aligned.m8n8.x4.trans.shared.b16 {%0,%1,%2,%3}, [%4];"
                 : "=r"(r0), "=r"(r1), "=r"(r2), "=r"(r3) : "r"(addr));
}
__device__ __forceinline__ void cpa16(void* s, const void* g) {
    unsigned sa = (unsigned)__cvta_generic_to_shared(s);
    asm volatile("cp.async.cg.shared.global [%0], [%1], 16;\n" :: "r"(sa), "l"(g));
}
#define CP_COMMIT() asm volatile("cp.async.commit_group;\n" ::: "memory")
#define CP_WAIT1()  asm volatile("cp.async.wait_group 1;\n" ::: "memory")

// --------- prep: fp16 weight copies + transposes ---------
__global__ void prep_kernel(const float* __restrict__ Wk, const float* __restrict__ Wv,
                            const float* __restrict__ Wq, const float* __restrict__ Wc,
                            const float* __restrict__ w1, const float* __restrict__ w2) {
    int z = blockIdx.y;
    int idx = blockIdx.x * 256 + threadIdx.x;
    if (z < 3) {
        if (idx < DIM * DIM) g_Wrh[z * DIM * DIM + idx] =
            __float2half(z == 0 ? Wk[idx] : z == 1 ? Wv[idx] : Wq[idx]);
    } else if (z == 3) {
        if (idx < DIM * DIM) g_Wcrh[idx] = __float2half(Wc[idx]);
    } else if (z == 4) {
        if (idx < DH * DHID) g_w1rh[idx] = __float2half(w1[idx]);
    } else if (z == 5) {
        if (idx < DHID * DH) g_w2rh[idx] = __float2half(w2[idx]);
    } else if (z == 6) {
        if (idx < DH * DHID) {
            int r = idx / DHID, c = idx % DHID;
            g_w1Th[c * DH + r] = __float2half(w1[idx]);
        }
    } else {
        if (idx < DHID * DH) {
            int r = idx / DH, c = idx % DH;
            g_w2Th[c * DHID + r] = __float2half(w2[idx]);
        }
    }
}

// ------- rmsnorm over DIM=512 (xs, xr half) + fused lr/gate -------
__global__ void rmsseq_kernel(const float* __restrict__ seq,
                              const float* __restrict__ gs,
                              const float* __restrict__ gr,
                              const float* __restrict__ Wa,
                              const float* __restrict__ ba,
                              const float* __restrict__ Wg) {
    int t = blockIdx.x;
    int tid = threadIdx.x;
    int lane = tid & 31, warp = tid >> 5;
    float x0 = seq[t * DIM + tid];
    float x1 = seq[t * DIM + tid + 256];
    float ss = x0 * x0 + x1 * x1;
    for (int o = 16; o; o >>= 1) ss += __shfl_down_sync(0xffffffffu, ss, o);
    __shared__ float sm[8];
    __shared__ float sma[8][4], smg[8][4];
    if (lane == 0) sm[warp] = ss;
    __syncthreads();
    float tot = 0.f;
#pragma unroll
    for (int i = 0; i < 8; i++) tot += sm[i];
    float rs = rsqrtf(tot * (1.0f / DIM) + 1e-6f);
    float a0 = x0 * rs * gs[tid],       a1 = x1 * rs * gs[tid + 256];
    float r0 = x0 * rs * gr[tid],       r1 = x1 * rs * gr[tid + 256];
    g_xsh[t * DIM + tid]       = __float2half(a0);
    g_xsh[t * DIM + tid + 256] = __float2half(a1);
    g_xrh[t * DIM + tid]       = __float2half(r0);
    g_xrh[t * DIM + tid + 256] = __float2half(r1);
    float pa[4], pg[4];
#pragma unroll
    for (int h = 0; h < 4; h++) {
        pa[h] = a0 * Wa[tid * NH + h] + a1 * Wa[(tid + 256) * NH + h];
        pg[h] = r0 * Wg[tid * NH + h] + r1 * Wg[(tid + 256) * NH + h];
    }
#pragma unroll
    for (int o = 16; o; o >>= 1)
#pragma unroll
        for (int h = 0; h < 4; h++) {
            pa[h] += __shfl_down_sync(0xffffffffu, pa[h], o);
            pg[h] += __shfl_down_sync(0xffffffffu, pg[h], o);
        }
    if (lane == 0)
#pragma unroll
        for (int h = 0; h < 4; h++) { sma[warp][h] = pa[h]; smg[warp][h] = pg[h]; }
    __syncthreads();
    if (tid < 4) {
        float sa = 0.f, sg2 = 0.f;
#pragma unroll
        for (int i = 0; i < 8; i++) { sa += sma[i][tid]; sg2 += smg[i][tid]; }
        g_lr[t * NH + tid]   = sigmf(sa + ba[tid]);
        g_gate[t * NH + tid] = sigmf(sg2);
    }
}

// ---------------- pooled chunk stats: stage 1 ----------------
__global__ void pool1_kernel() {
    int bc = blockIdx.x, seg = blockIdx.y;
    int tid = threadIdx.x;
    int b = bc / NC, c = bc % NC;
    int t0 = b * SEQN + c * CH + seg * 8;
    float s = 0.f;
#pragma unroll
    for (int i = 0; i < 8; i++) s += __half2float(g_xsh[(t0 + i) * DIM + tid]);
    g_poolp[(bc * 8 + seg) * DIM + tid] = s;
}

// ---------------- pooled chunk stats: stage 2 ----------------
__global__ void pool2_kernel(const float* __restrict__ Wm, const float* __restrict__ Wd,
                             const float* __restrict__ bd) {
    int bc = blockIdx.x;
    int tid = threadIdx.x;
    __shared__ float pooled[DIM];
    float s = 0.f;
#pragma unroll
    for (int seg = 0; seg < 8; seg++) s += g_poolp[(bc * 8 + seg) * DIM + tid];
    pooled[tid] = s * (1.0f / CH);
    __syncthreads();
    if (tid < 128) {
        int lane = tid & 31, h = tid >> 5;
        float am = 0.f, ad = 0.f;
        for (int d = lane; d < DIM; d += 32) {
            am += pooled[d] * Wm[d * NH + h];
            ad += pooled[d] * Wd[d * NH + h];
        }
        for (int o = 16; o; o >>= 1) {
            am += __shfl_down_sync(0xffffffffu, am, o);
            ad += __shfl_down_sync(0xffffffffu, ad, o);
        }
        if (lane == 0) {
            g_beta[bc * NH + h]  = sigmf(am);
            g_alpha[bc * NH + h] = 1.0f - sigmf(ad + bd[h]);
        }
    }
}

// ---------------- rmsnorm over DH=128 for K -> Hs (half) ----------------
__global__ void rmshead_kernel(const float* __restrict__ memg) {
    int r = blockIdx.x;
    int d = threadIdx.x;
    float x = __half2float(g_KVQh[(long)r * DH + d]);    // K
    float ss = x * x;
    for (int o = 16; o; o >>= 1) ss += __shfl_down_sync(0xffffffffu, ss, o);
    __shared__ float sm[4];
    if ((d & 31) == 0) sm[d >> 5] = ss;
    __syncthreads();
    float tot = sm[0] + sm[1] + sm[2] + sm[3];
    float rs = rsqrtf(tot * (1.0f / DH) + 1e-6f);
    g_Hsh[r * DH + d] = __float2half(x * rs * memg[d]);
    if (d == 0) g_rsK[r] = rs;
}

// ---------------- rmsnorm for Q with per-chunk Gp -> Hq (half) ----------------
__global__ void hq_kernel() {
    int r = blockIdx.x;
    int d = threadIdx.x;
    int bh = r / SEQN, n = r % SEQN, c = n / CH;
    float x = __half2float(g_KVQh[2 * RWSDH + (long)r * DH + d]);   // Q
    float ss = x * x;
    for (int o = 16; o; o >>= 1) ss += __shfl_down_sync(0xffffffffu, ss, o);
    __shared__ float sm[4];
    if ((d & 31) == 0) sm[d >> 5] = ss;
    __syncthreads();
    float tot = sm[0] + sm[1] + sm[2] + sm[3];
    float rs = rsqrtf(tot * (1.0f / DH) + 1e-6f);
    g_Hqh[r * DH + d] = __float2half(x * rs * g_Gp[(bh * NC + c) * DH + d]);
}

// --------- combined big scans over half tensors ---------
__global__ void scanh_kernel(const __half* __restrict__ s1, const float* __restrict__ i1,
                             __half* __restrict__ o1,
                             const __half* __restrict__ s2, const float* __restrict__ i2,
                             __half* __restrict__ o2) {
    constexpr long SZ = (long)DH * DHID;
    const __half* s; const float* init; __half* wprev;
    if (blockIdx.z == 0) { s = s1; init = i1; wprev = o1; }
    else                 { s = s2; init = i2; wprev = o2; }
    int bh = blockIdx.y;
    long e8 = ((long)blockIdx.x * 256 + threadIdx.x) * 8;
    if (e8 >= SZ) return;
    int b = bh / NH, h = bh % NH;

    float m[8], w[8];
#pragma unroll
    for (int j = 0; j < 8; j++) { m[j] = 0.f; w[j] = init[e8 + j]; }

    auto store8 = [&](long off, const float* v) {
        __half2 hv[4];
#pragma unroll
        for (int j = 0; j < 4; j++)
            hv[j] = __floats2half2_rn(v[2 * j], v[2 * j + 1]);
        *(uint4*)(wprev + off) = *(const uint4*)hv;
    };
    auto load8 = [&](long off, float* v) {
        uint4 raw = *(const uint4*)(s + off);
        const __half2* h2 = (const __half2*)&raw;
#pragma unroll
        for (int j = 0; j < 4; j++) {
            float2 f = __half22float2(h2[j]);
            v[2 * j] = f.x; v[2 * j + 1] = f.y;
        }
    };

    store8((long)(bh * NC) * SZ + e8, w);
    float sv[8];
    load8((long)(bh * NC) * SZ + e8, sv);
    for (int t = 0; t < NC; t++) {
        float nx[8];
        if (t + 1 < NC) load8((long)(bh * NC + t + 1) * SZ + e8, nx);
        float beta  = g_beta[(b * NC + t) * NH + h];
        float alpha = g_alpha[(b * NC + t) * NH + h];
#pragma unroll
        for (int j = 0; j < 8; j++) {
            m[j] = beta * m[j] + sv[j];
            w[j] = alpha * w[j] + m[j];
        }
        if (t < NC - 1) {
            store8((long)(bh * NC + t + 1) * SZ + e8, w);
#pragma unroll
            for (int j = 0; j < 8; j++) sv[j] = nx[j];
        }
    }
}

// ---------------- small scan for s_g -> Gp ----------------
__global__ void scan_kernel(const float* __restrict__ s, const float* __restrict__ init,
                            float* __restrict__ wprev, int sz) {
    int bh = blockIdx.y;
    int e = blockIdx.x * 256 + threadIdx.x;
    if (e >= sz) return;
    int b = bh / NH, h = bh % NH;
    float m = 0.f, w = init[e];
    wprev[(long)(bh * NC) * sz + e] = rndf(w);
    for (int t = 0; t < NC; t++) {
        float beta  = g_beta[(b * NC + t) * NH + h];
        float alpha = g_alpha[(b * NC + t) * NH + h];
        m = beta * m + s[(long)(bh * NC + t) * sz + e];
        w = alpha * w + m;
        if (t < NC - 1) wprev[(long)(bh * NC + t + 1) * sz + e] = rndf(w);
    }
}

// ======= fp16 tensor-core GEMM (m16n8k16), BMx128 tile, cp.async + ldmatrix =======
// EPI: 0 plain fp32 C, 1 fused QKV -> half KVQ, 2 A1(half)+gelu->half, 3 pred->dY half,
//      4 *gelu'(A1 half)->half, 6 gelu->half, 7 gated retrieval ->half x3,
//      8 negate->half C, 9 fused dH->s_g reduction (fp32 C)
// TA: C = op(A^T B), A stored [K][M] half
// h0: aux half pointer (EPI1: xr; EPI3/7/9: KVQ base; EPI4: A1)
template <int BM, int EPI, bool TA>
__global__ void __launch_bounds__(256, 2) gmma(
    const __half* __restrict__ A, const __half* __restrict__ Bm, void* __restrict__ Cv,
    int K, int lda, int ldb, int ldc,
    long sA, long sB, long sC,
    const float* __restrict__ f1, const float* __restrict__ f2,
    void* __restrict__ x3, const __half* __restrict__ h0) {
    constexpr int STG = 3;
    constexpr int WM  = BM / 2;
    constexpr int MA  = WM / 16;
    constexpr int ASZ = TA ? 16 * 136 : BM * 24;
    constexpr int BSZ = 16 * 136;

    int z = blockIdx.z;
    float* C = (float*)Cv;
    __half* Ch = (__half*)Cv;
    if (EPI == 1) {
        if (z == 2) A = h0;
        Bm += (long)z * DIM * DIM;
        Ch += (long)z * RWSDH;
    } else {
        A += (long)z * sA;
        Bm += (long)z * sB;
        if (EPI == 0 || EPI == 9) C += (long)z * sC;
        else Ch += (long)z * sC;
    }

    extern __shared__ char smraw[];
    __half* Asm = (__half*)smraw;
    __half* Bsm = Asm + STG * ASZ;
    __shared__ float sgacc[128];

    int tid = threadIdx.x;
    int warp = tid >> 5, lane = tid & 31;
    int g = lane >> 2, tg = lane & 3;
    int wr = warp >> 2, wc = warp & 3;
    int m0 = blockIdx.y * BM, n0 = blockIdx.x * 128;

    float acc[MA][4][4];
#pragma unroll
    for (int i = 0; i < MA; i++)
#pragma unroll
        for (int j = 0; j < 4; j++)
#pragma unroll
            for (int l = 0; l < 4; l++) acc[i][j][l] = 0.f;

    auto issue = [&](int st, int kb) {
        __half* as = Asm + st * ASZ;
        __half* bs = Bsm + st * BSZ;
        if (!TA) {
            if (BM == 128 || tid < 128) {
                int m = tid >> 1, kh = (tid & 1) * 8;
                cpa16(&as[m * 24 + kh], A + (long)(m0 + m) * lda + kb + kh);
            }
        } else {
            int k = tid >> 4, m8 = (tid & 15) * 8;
            cpa16(&as[k * 136 + m8], A + (long)(kb + k) * lda + m0 + m8);
        }
        {
            int k = tid >> 4, n8 = (tid & 15) * 8;
            cpa16(&bs[k * 136 + n8], Bm + (long)(kb + k) * ldb + n0 + n8);
        }
    };

    if (EPI == 9) {
        if (tid < 128) sgacc[tid] = 0.f;
    }

    int nT = K >> 4;
#pragma unroll
    for (int s = 0; s < STG - 1; s++) {
        if (s < nT) issue(s, s << 4);
        CP_COMMIT();
    }

    for (int t = 0; t < nT; t++) {
        CP_WAIT1();
        __syncthreads();
        int nx = t + STG - 1;
        if (nx < nT) issue(nx % STG, nx << 4);
        CP_COMMIT();

        const __half* as = Asm + (t % STG) * ASZ;
        const __half* bs = Bsm + (t % STG) * BSZ;
        unsigned asb = (unsigned)__cvta_generic_to_shared(as);
        unsigned bsb = (unsigned)__cvta_generic_to_shared(bs);

        unsigned af[MA][4], bf[4][2];
        if (!TA) {
            int arow = lane & 15, ak = (lane >> 4) * 8;
#pragma unroll
            for (int ma = 0; ma < MA; ma++) {
                unsigned addr = asb + 2u * (unsigned)((wr * WM + ma * 16 + arow) * 24 + ak);
                ldsm4(af[ma][0], af[ma][1], af[ma][2], af[ma][3], addr);
            }
        } else {
            int krow = (lane & 7) + (lane >> 4) * 8;
            int moff = ((lane >> 3) & 1) * 8;
#pragma unroll
            for (int ma = 0; ma < MA; ma++) {
                int R = wr * WM + ma * 16;
                unsigned addr = asb + 2u * (unsigned)(krow * 136 + R + moff);
                ldsm4t(af[ma][0], af[ma][1], af[ma][2], af[ma][3], addr);
            }
        }
        {
            int krow = lane & 15;
            int nhi = (lane >> 4) * 8;
#pragma unroll
            for (int h = 0; h < 2; h++) {
                unsigned r0, r1, r2, r3;
                unsigned addr = bsb + 2u * (unsigned)(krow * 136 + wc * 32 + h * 16 + nhi);
                ldsm4t(r0, r1, r2, r3, addr);
                bf[2 * h][0] = r0; bf[2 * h][1] = r1;
                bf[2 * h + 1][0] = r2; bf[2 * h + 1][1] = r3;
            }
        }
#pragma unroll
        for (int na = 0; na < 4; na++)
#pragma unroll
            for (int ma = 0; ma < MA; ma++)
                mma16(acc[ma][na], af[ma], bf[na][0], bf[na][1]);
    }

    if (EPI == 9) {
        // dH = acc; s_g[chunk, c] = -sum_rows dH[r,c] * K[r,c] * rsK[r]
#pragma unroll
        for (int na = 0; na < 4; na++) {
#pragma unroll
            for (int hf = 0; hf < 2; hf++) {
                int c = n0 + wc * 32 + na * 8 + tg * 2 + hf;
                float csum = 0.f;
#pragma unroll
                for (int ma = 0; ma < MA; ma++)
#pragma unroll
                    for (int ih = 0; ih < 2; ih++) {
                        int i = ih * 2 + hf;
                        int r = m0 + wr * WM + ma * 16 + g + ih * 8;
                        csum += acc[ma][na][i] * __half2float(h0[(long)r * DH + c]) * f1[r];
                    }
                for (int o = 16; o >= 4; o >>= 1)
                    csum += __shfl_down_sync(0xffffffffu, csum, o);
                if (g == 0) atomicAdd(&sgacc[wc * 32 + na * 8 + tg * 2 + hf], csum);
            }
        }
        __syncthreads();
        if (tid < 128) C[(long)blockIdx.y * DH + tid] = -sgacc[tid];
        return;
    }

    // vectorized epilogue: pairs (i=0,1)@row r and (i=2,3)@row r+8, c..c+1
#pragma unroll
    for (int ma = 0; ma < MA; ma++) {
#pragma unroll
        for (int na = 0; na < 4; na++) {
#pragma unroll
            for (int p = 0; p < 2; p++) {
                int r = m0 + wr * WM + ma * 16 + g + p * 8;
                int c = n0 + wc * 32 + na * 8 + tg * 2;
                float v0 = acc[ma][na][p * 2 + 0];
                float v1 = acc[ma][na][p * 2 + 1];
                if (EPI == 0) {
                    *(float2*)&C[(long)r * ldc + c] = make_float2(v0, v1);
                } else if (EPI == 8) {
                    *(__half2*)&Ch[(long)r * ldc + c] = __floats2half2_rn(-v0, -v1);
                } else if (EPI == 1) {
                    int b = r / SEQN, n = r % SEQN, h = c / DH, d = c % DH;
                    *(__half2*)&Ch[(long)(((b * NH + h) * SEQN) + n) * DH + d] =
                        __floats2half2_rn(v0, v1);
                } else if (EPI == 2) {
                    *(__half2*)&((__half*)x3)[(long)r * ldc + c] = __floats2half2_rn(v0, v1);
                    *(__half2*)&Ch[(long)r * ldc + c] =
                        __floats2half2_rn(gelu_f(v0), gelu_f(v1));
                } else if (EPI == 3) {
                    float2 kk = __half22float2(*(const __half2*)&h0[(long)r * DH + c]);
                    float2 vv = __half22float2(*(const __half2*)&h0[RWSDH + (long)r * DH + c]);
                    int bh = r / SEQN, n = r % SEQN;
                    int b = bh / NH, h = bh % NH;
                    float lr = f2[(b * SEQN + n) * NH + h];
                    float s = (2.0f / DH) * lr;
                    *(__half2*)&Ch[(long)r * DH + c] =
                        __floats2half2_rn(s * (v0 + kk.x - vv.x), s * (v1 + kk.y - vv.y));
                } else if (EPI == 4) {
                    float2 a1 = __half22float2(*(const __half2*)&h0[(long)r * ldc + c]);
                    *(__half2*)&Ch[(long)r * ldc + c] =
                        __floats2half2_rn(v0 * gelup_f(a1.x), v1 * gelup_f(a1.y));
                } else if (EPI == 6) {
                    *(__half2*)&Ch[(long)r * ldc + c] =
                        __floats2half2_rn(gelu_f(v0), gelu_f(v1));
                } else if (EPI == 7) {
                    float2 qq = __half22float2(
                        *(const __half2*)&h0[2 * RWSDH + (long)z * CH * DH + (long)r * DH + c]);
                    int bh = z / NC, cc = z % NC;
                    int n = cc * CH + r;
                    int b = bh / NH, h = bh % NH;
                    float gate = f1[(b * SEQN + n) * NH + h];
                    *(__half2*)&((__half*)x3)[(long)(b * SEQN + n) * DIM + h * DH + c] =
                        __floats2half2_rn((v0 + qq.x) * gate, (v1 + qq.y) * gate);
                }
            }
        }
    }
}

constexpr int smem_bytes(int BM, bool TA) {
    return 3 * ((TA ? 16 * 136 : BM * 24) + 16 * 136) * 2;
}

// ---------------- launch ----------------
extern "C" void kernel_launch(void* const* d_in, const int* in_sizes, int n_in,
                              void* d_out, int out_size) {
    const float* seq   = (const float*)d_in[0];
    const float* gsto  = (const float*)d_in[1];
    const float* gret  = (const float*)d_in[2];
    const float* Wq    = (const float*)d_in[3];
    const float* Wk    = (const float*)d_in[4];
    const float* Wv    = (const float*)d_in[5];
    const float* Wa    = (const float*)d_in[6];
    const float* ba    = (const float*)d_in[7];
    const float* Wm    = (const float*)d_in[8];
    const float* Wd    = (const float*)d_in[9];
    const float* bd    = (const float*)d_in[10];
    const float* Wg    = (const float*)d_in[11];
    const float* Wc    = (const float*)d_in[12];
    const float* memg  = (const float*)d_in[13];
    const float* w1    = (const float*)d_in[14];
    const float* w2    = (const float*)d_in[15];
    float* out = (float*)d_out;

    float *p_lr, *p_gate, *p_rsK, *p_sg, *p_Gp;
    __half *p_xsh, *p_xrh, *p_KVQh, *p_Hsh, *p_A1h, *p_GAh, *p_dA1h, *p_dYh,
           *p_Hqh, *p_Rh, *p_sw1h, *p_sw2h, *p_Wp1h, *p_Wp2h, *p_w1Th, *p_w2Th,
           *p_Wrh, *p_Wcrh, *p_w1rh, *p_w2rh;
    cudaGetSymbolAddress((void**)&p_xsh, g_xsh);
    cudaGetSymbolAddress((void**)&p_xrh, g_xrh);
    cudaGetSymbolAddress((void**)&p_KVQh, g_KVQh);
    cudaGetSymbolAddress((void**)&p_lr, g_lr);
    cudaGetSymbolAddress((void**)&p_gate, g_gate);
    cudaGetSymbolAddress((void**)&p_Hsh, g_Hsh);
    cudaGetSymbolAddress((void**)&p_rsK, g_rsK);
    cudaGetSymbolAddress((void**)&p_A1h, g_A1h);
    cudaGetSymbolAddress((void**)&p_GAh, g_GAh);
    cudaGetSymbolAddress((void**)&p_dA1h, g_dA1h);
    cudaGetSymbolAddress((void**)&p_dYh, g_dYh);
    cudaGetSymbolAddress((void**)&p_sw1h, g_sw1h);
    cudaGetSymbolAddress((void**)&p_sw2h, g_sw2h);
    cudaGetSymbolAddress((void**)&p_sg, g_sg);
    cudaGetSymbolAddress((void**)&p_Wp1h, g_Wp1h);
    cudaGetSymbolAddress((void**)&p_Wp2h, g_Wp2h);
    cudaGetSymbolAddress((void**)&p_Gp, g_Gp);
    cudaGetSymbolAddress((void**)&p_Hqh, g_Hqh);
    cudaGetSymbolAddress((void**)&p_Rh, g_Rh);
    cudaGetSymbolAddress((void**)&p_w1Th, g_w1Th);
    cudaGetSymbolAddress((void**)&p_w2Th, g_w2Th);
    cudaGetSymbolAddress((void**)&p_Wrh, g_Wrh);
    cudaGetSymbolAddress((void**)&p_Wcrh, g_Wcrh);
    cudaGetSymbolAddress((void**)&p_w1rh, g_w1rh);
    cudaGetSymbolAddress((void**)&p_w2rh, g_w2rh);

    constexpr int S128  = smem_bytes(128, false);
    constexpr int S128T = smem_bytes(128, true);
    constexpr int S64   = smem_bytes(64, false);
    cudaFuncSetAttribute(gmma<128, 1, false>, cudaFuncAttributeMaxDynamicSharedMemorySize, S128);
    cudaFuncSetAttribute(gmma<128, 2, false>, cudaFuncAttributeMaxDynamicSharedMemorySize, S128);
    cudaFuncSetAttribute(gmma<64, 3, false>,  cudaFuncAttributeMaxDynamicSharedMemorySize, S64);
    cudaFuncSetAttribute(gmma<128, 4, false>, cudaFuncAttributeMaxDynamicSharedMemorySize, S128);
    cudaFuncSetAttribute(gmma<64, 9, false>,  cudaFuncAttributeMaxDynamicSharedMemorySize, S64);
    cudaFuncSetAttribute(gmma<64, 0, false>,  cudaFuncAttributeMaxDynamicSharedMemorySize, S64);
    cudaFuncSetAttribute(gmma<128, 8, true>,  cudaFuncAttributeMaxDynamicSharedMemorySize, S128T);
    cudaFuncSetAttribute(gmma<64, 6, false>,  cudaFuncAttributeMaxDynamicSharedMemorySize, S64);
    cudaFuncSetAttribute(gmma<64, 7, false>,  cudaFuncAttributeMaxDynamicSharedMemorySize, S64);

    // 0) fp16 weight copies + transposes
    prep_kernel<<<dim3(1024, 8), 256>>>(Wk, Wv, Wq, Wc, w1, w2);

    // 1) rmsnorm of seq -> xs, xr (half) + fused lr/gate
    rmsseq_kernel<<<TOK, 256>>>(seq, gsto, gret, Wa, ba, Wg);

    // 2) fused QKV projections -> head-major K|V|Q (half)
    gmma<128, 1, false><<<dim3(4, 32, 3), 256, S128>>>(p_xsh, p_Wrh, p_KVQh,
        DIM, DIM, DIM, 0, 0, 0, 0, nullptr, nullptr, nullptr, p_xrh);

    // 4) beta, alpha
    pool1_kernel<<<dim3(Bb * NC, 8), 512>>>();
    pool2_kernel<<<Bb * NC, 512>>>(Wm, Wd, bd);

    // 5) Hs = rmsnorm(K, mem_g) (half)
    rmshead_kernel<<<RWS, 128>>>(memg);

    // 7) A1(half) = Hs @ w1 ; GA = gelu(A1) (half)
    gmma<128, 2, false><<<dim3(4, 128), 256, S128>>>(p_Hsh, p_w1rh, p_GAh,
        DH, DH, DHID, DHID, 0, 0, 0, nullptr, nullptr, p_A1h, nullptr);
    // 8) pred = GA @ w2 + K -> dY (half)
    gmma<64, 3, false><<<dim3(1, 256), 256, S64>>>(p_GAh, p_w2rh, p_dYh,
        DHID, DHID, DH, DH, 0, 0, 0, nullptr, p_lr, nullptr, p_KVQh);
    // 9) dA1 = (dY @ w2^T) * gelu'(A1) (half)
    gmma<128, 4, false><<<dim3(4, 128), 256, S128>>>(p_dYh, p_w2Th, p_dA1h,
        DH, DH, DHID, DHID, 0, 0, 0, nullptr, nullptr, nullptr, p_A1h);
    // 10+13) s_g = -colsum(dH * K * rsK) fused into dH GEMM
    gmma<64, 9, false><<<dim3(1, 256), 256, S64>>>(p_dA1h, p_w1Th, p_sg,
        DHID, DHID, DH, DH, 0, 0, 0, p_rsK, nullptr, nullptr, p_KVQh);

    // 11) sW1[z] = -Hs_z^T @ dA1_z (half)
    gmma<128, 8, true><<<dim3(4, 1, NCHUNK), 256, S128T>>>(p_Hsh, p_dA1h, p_sw1h,
        CH, DH, DHID, DHID,
        (long)CH * DH, (long)CH * DHID, (long)DH * DHID, nullptr, nullptr, nullptr, nullptr);
    // 12) sW2[z] = -GA_z^T @ dY_z (half)
    gmma<128, 8, true><<<dim3(1, 4, NCHUNK), 256, S128T>>>(p_GAh, p_dYh, p_sw2h,
        CH, DHID, DH, DH,
        (long)CH * DHID, (long)CH * DH, (long)DHID * DH, nullptr, nullptr, nullptr, nullptr);

    // 14) scans -> causal w_prev (half) + Gp
    scanh_kernel<<<dim3(32, BH, 2), 256>>>(p_sw1h, w1, p_Wp1h, p_sw2h, w2, p_Wp2h);
    scan_kernel<<<dim3(1, BH), 256>>>(p_sg, memg, p_Gp, DH);

    // 15) Hq = rmsnorm(Q, Gp[chunk]) (half)
    hq_kernel<<<RWS, 128>>>();

    // 16) retrieval GEMM1: GAq = gelu(Hq @ Wp1[z]) (half)
    gmma<64, 6, false><<<dim3(4, 1, NCHUNK), 256, S64>>>(p_Hqh, p_Wp1h, p_GAh,
        DH, DH, DHID, DHID,
        (long)CH * DH, (long)DH * DHID, (long)CH * DHID, nullptr, nullptr, nullptr, nullptr);
    // 17) retrieval GEMM2: y = (GAq @ Wp2[z] + q) * gate -> R (half)
    gmma<64, 7, false><<<dim3(1, 1, NCHUNK), 256, S64>>>(p_GAh, p_Wp2h, nullptr,
        DHID, DHID, DH, DH,
        (long)CH * DHID, (long)DHID * DH, 0, p_gate, nullptr, p_Rh, p_KVQh);
    // 18) out = R @ Wc (fp32 out)
    gmma<64, 0, false><<<dim3(4, 64), 256, S64>>>(p_Rh, p_Wcrh, out,
        DIM, DIM, DIM, DIM, 0, 0, 0, nullptr, nullptr, nullptr, nullptr);
}

// round 17
// speedup vs baseline: 4.2727x; 1.0301x over previous
#include <cuda_runtime.h>
#include <cuda_fp16.h>
#include <math.h>

// ---------------- problem constants ----------------
constexpr int Bb   = 2;
constexpr int SEQN = 2048;
constexpr int DIM  = 512;
constexpr int NH   = 4;
constexpr int DH   = 128;
constexpr int CH   = 64;
constexpr int NC   = 32;
constexpr int DHID = 512;
constexpr int BH   = 8;
constexpr int TOK  = Bb * SEQN;      // 4096
constexpr int RWS  = BH * SEQN;      // 16384
constexpr int NCHUNK = BH * NC;      // 256
constexpr long RWSDH = (long)RWS * DH;

// ---------------- device scratch ----------------
__device__ __half g_xsh[TOK * DIM];
__device__ __half g_xrh[TOK * DIM];
__device__ __half g_KVQh[3 * RWS * DH];        // K | V | Q  (fp16)
__device__ float g_lr[TOK * NH];
__device__ float g_gate[TOK * NH];
__device__ float g_beta[Bb * NC * NH];
__device__ float g_alpha[Bb * NC * NH];
__device__ __half g_Hsh[RWS * DH];
__device__ float g_rsK[RWS];
__device__ __half g_A1h[RWS * DHID];
__device__ __half g_GAh[RWS * DHID];
__device__ __half g_dA1h[RWS * DHID];
__device__ __half g_dYh[RWS * DH];
__device__ __half g_sw1h[NCHUNK * DH * DHID];
__device__ __half g_sw2h[NCHUNK * DHID * DH];
__device__ float  g_sg[NCHUNK * DH];
__device__ __half g_Wp1h[NCHUNK * DH * DHID];
__device__ __half g_Wp2h[NCHUNK * DHID * DH];
__device__ float g_Gp[NCHUNK * DH];
__device__ __half g_Hqh[RWS * DH];
__device__ __half g_Rh[TOK * DIM];
__device__ __half g_w1Th[DHID * DH];
__device__ __half g_w2Th[DH * DHID];
__device__ float g_poolp[Bb * NC * 8 * DIM];
// fp16 weight copies
__device__ __half g_Wrh[3 * DIM * DIM];        // Wk | Wv | Wq
__device__ __half g_Wcrh[DIM * DIM];
__device__ __half g_w1rh[DH * DHID];
__device__ __half g_w2rh[DHID * DH];

// ---------------- math helpers ----------------
__device__ __forceinline__ float sigmf(float x) { return 1.0f / (1.0f + expf(-x)); }
__device__ __forceinline__ float gelu_f(float x) {
    return 0.5f * x * (1.0f + erff(x * 0.70710678118654752f));
}
__device__ __forceinline__ float gelup_f(float x) {
    return 0.5f * (1.0f + erff(x * 0.70710678118654752f))
         + x * 0.3989422804014327f * expf(-0.5f * x * x);
}
__device__ __forceinline__ float rndf(float x) {
    asm("cvt.rna.tf32.f32 %0, %1;" : "=f"(x) : "f"(x));
    return x;
}
__device__ __forceinline__ void mma16(float c[4], const unsigned a[4],
                                      unsigned b0, unsigned b1) {
    asm volatile(
        "mma.sync.aligned.m16n8k16.row.col.f32.f16.f16.f32 "
        "{%0,%1,%2,%3},{%4,%5,%6,%7},{%8,%9},{%0,%1,%2,%3};"
        : "+f"(c[0]), "+f"(c[1]), "+f"(c[2]), "+f"(c[3])
        : "r"(a[0]), "r"(a[1]), "r"(a[2]), "r"(a[3]), "r"(b0), "r"(b1));
}
__device__ __forceinline__ void ldsm4(unsigned& r0, unsigned& r1, unsigned& r2,
                                      unsigned& r3, unsigned addr) {
    asm volatile("ldmatrix.sync.aligned.m8n8.x4.shared.b16 {%0,%1,%2,%3}, [%4];"
                 : "=r"(r0), "=r"(r1), "=r"(r2), "=r"(r3) : "r"(addr));
}
__device__ __forceinline__ void ldsm4t(unsigned& r0, unsigned& r1, unsigned& r2,
                                       unsigned& r3, unsigned addr) {
    asm volatile("ldmatrix.sync.aligned.m8n8.x4.trans.shared.b16 {%0,%1,%2,%3}, [%4];"
                 : "=r"(r0), "=r"(r1), "=r"(r2), "=r"(r3) : "r"(addr));
}
__device__ __forceinline__ void cpa16(void* s, const void* g) {
    unsigned sa = (unsigned)__cvta_generic_to_shared(s);
    asm volatile("cp.async.cg.shared.global [%0], [%1], 16;\n" :: "r"(sa), "l"(g));
}
#define CP_COMMIT() asm volatile("cp.async.commit_group;\n" ::: "memory")
#define CP_WAIT1()  asm volatile("cp.async.wait_group 1;\n" ::: "memory")

// --------- prep: fp16 weight copies + transposes ---------
__global__ void prep_kernel(const float* __restrict__ Wk, const float* __restrict__ Wv,
                            const float* __restrict__ Wq, const float* __restrict__ Wc,
                            const float* __restrict__ w1, const float* __restrict__ w2) {
    int z = blockIdx.y;
    int idx = blockIdx.x * 256 + threadIdx.x;
    if (z < 3) {
        if (idx < DIM * DIM) g_Wrh[z * DIM * DIM + idx] =
            __float2half(z == 0 ? Wk[idx] : z == 1 ? Wv[idx] : Wq[idx]);
    } else if (z == 3) {
        if (idx < DIM * DIM) g_Wcrh[idx] = __float2half(Wc[idx]);
    } else if (z == 4) {
        if (idx < DH * DHID) g_w1rh[idx] = __float2half(w1[idx]);
    } else if (z == 5) {
        if (idx < DHID * DH) g_w2rh[idx] = __float2half(w2[idx]);
    } else if (z == 6) {
        if (idx < DH * DHID) {
            int r = idx / DHID, c = idx % DHID;
            g_w1Th[c * DH + r] = __float2half(w1[idx]);
        }
    } else {
        if (idx < DHID * DH) {
            int r = idx / DH, c = idx % DH;
            g_w2Th[c * DHID + r] = __float2half(w2[idx]);
        }
    }
}

// ------- rmsnorm over DIM=512 (xs, xr half) + fused lr/gate -------
__global__ void rmsseq_kernel(const float* __restrict__ seq,
                              const float* __restrict__ gs,
                              const float* __restrict__ gr,
                              const float* __restrict__ Wa,
                              const float* __restrict__ ba,
                              const float* __restrict__ Wg) {
    int t = blockIdx.x;
    int tid = threadIdx.x;
    int lane = tid & 31, warp = tid >> 5;
    float x0 = seq[t * DIM + tid];
    float x1 = seq[t * DIM + tid + 256];
    float ss = x0 * x0 + x1 * x1;
    for (int o = 16; o; o >>= 1) ss += __shfl_down_sync(0xffffffffu, ss, o);
    __shared__ float sm[8];
    __shared__ float sma[8][4], smg[8][4];
    if (lane == 0) sm[warp] = ss;
    __syncthreads();
    float tot = 0.f;
#pragma unroll
    for (int i = 0; i < 8; i++) tot += sm[i];
    float rs = rsqrtf(tot * (1.0f / DIM) + 1e-6f);
    float a0 = x0 * rs * gs[tid],       a1 = x1 * rs * gs[tid + 256];
    float r0 = x0 * rs * gr[tid],       r1 = x1 * rs * gr[tid + 256];
    g_xsh[t * DIM + tid]       = __float2half(a0);
    g_xsh[t * DIM + tid + 256] = __float2half(a1);
    g_xrh[t * DIM + tid]       = __float2half(r0);
    g_xrh[t * DIM + tid + 256] = __float2half(r1);
    float pa[4], pg[4];
#pragma unroll
    for (int h = 0; h < 4; h++) {
        pa[h] = a0 * Wa[tid * NH + h] + a1 * Wa[(tid + 256) * NH + h];
        pg[h] = r0 * Wg[tid * NH + h] + r1 * Wg[(tid + 256) * NH + h];
    }
#pragma unroll
    for (int o = 16; o; o >>= 1)
#pragma unroll
        for (int h = 0; h < 4; h++) {
            pa[h] += __shfl_down_sync(0xffffffffu, pa[h], o);
            pg[h] += __shfl_down_sync(0xffffffffu, pg[h], o);
        }
    if (lane == 0)
#pragma unroll
        for (int h = 0; h < 4; h++) { sma[warp][h] = pa[h]; smg[warp][h] = pg[h]; }
    __syncthreads();
    if (tid < 4) {
        float sa = 0.f, sg2 = 0.f;
#pragma unroll
        for (int i = 0; i < 8; i++) { sa += sma[i][tid]; sg2 += smg[i][tid]; }
        g_lr[t * NH + tid]   = sigmf(sa + ba[tid]);
        g_gate[t * NH + tid] = sigmf(sg2);
    }
}

// ---------------- pooled chunk stats: stage 1 ----------------
__global__ void pool1_kernel() {
    int bc = blockIdx.x, seg = blockIdx.y;
    int tid = threadIdx.x;
    int b = bc / NC, c = bc % NC;
    int t0 = b * SEQN + c * CH + seg * 8;
    float s = 0.f;
#pragma unroll
    for (int i = 0; i < 8; i++) s += __half2float(g_xsh[(t0 + i) * DIM + tid]);
    g_poolp[(bc * 8 + seg) * DIM + tid] = s;
}

// ---------------- pooled chunk stats: stage 2 ----------------
__global__ void pool2_kernel(const float* __restrict__ Wm, const float* __restrict__ Wd,
                             const float* __restrict__ bd) {
    int bc = blockIdx.x;
    int tid = threadIdx.x;
    __shared__ float pooled[DIM];
    float s = 0.f;
#pragma unroll
    for (int seg = 0; seg < 8; seg++) s += g_poolp[(bc * 8 + seg) * DIM + tid];
    pooled[tid] = s * (1.0f / CH);
    __syncthreads();
    if (tid < 128) {
        int lane = tid & 31, h = tid >> 5;
        float am = 0.f, ad = 0.f;
        for (int d = lane; d < DIM; d += 32) {
            am += pooled[d] * Wm[d * NH + h];
            ad += pooled[d] * Wd[d * NH + h];
        }
        for (int o = 16; o; o >>= 1) {
            am += __shfl_down_sync(0xffffffffu, am, o);
            ad += __shfl_down_sync(0xffffffffu, ad, o);
        }
        if (lane == 0) {
            g_beta[bc * NH + h]  = sigmf(am);
            g_alpha[bc * NH + h] = 1.0f - sigmf(ad + bd[h]);
        }
    }
}

// ---------------- rmsnorm for Q with per-chunk Gp -> Hq (half), 4 rows/block ----------------
__global__ void hq_kernel() {
    int tid = threadIdx.x;                 // 512 threads
    int rloc = tid >> 7, d = tid & 127;
    int r = blockIdx.x * 4 + rloc;
    int bh = r / SEQN, n = r % SEQN, c = n / CH;
    float x = __half2float(g_KVQh[2 * RWSDH + (long)r * DH + d]);
    float ss = x * x;
    for (int o = 16; o; o >>= 1) ss += __shfl_down_sync(0xffffffffu, ss, o);
    __shared__ float sm[16];
    if ((tid & 31) == 0) sm[tid >> 5] = ss;
    __syncthreads();
    int w0 = rloc * 4;
    float tot = sm[w0] + sm[w0 + 1] + sm[w0 + 2] + sm[w0 + 3];
    float rs = rsqrtf(tot * (1.0f / DH) + 1e-6f);
    g_Hqh[(long)r * DH + d] = __float2half(x * rs * g_Gp[(bh * NC + c) * DH + d]);
}

// --------- combined big scans over half tensors ---------
__global__ void scanh_kernel(const __half* __restrict__ s1, const float* __restrict__ i1,
                             __half* __restrict__ o1,
                             const __half* __restrict__ s2, const float* __restrict__ i2,
                             __half* __restrict__ o2) {
    constexpr long SZ = (long)DH * DHID;
    const __half* s; const float* init; __half* wprev;
    if (blockIdx.z == 0) { s = s1; init = i1; wprev = o1; }
    else                 { s = s2; init = i2; wprev = o2; }
    int bh = blockIdx.y;
    long e8 = ((long)blockIdx.x * 256 + threadIdx.x) * 8;
    if (e8 >= SZ) return;
    int b = bh / NH, h = bh % NH;

    float m[8], w[8];
#pragma unroll
    for (int j = 0; j < 8; j++) { m[j] = 0.f; w[j] = init[e8 + j]; }

    auto store8 = [&](long off, const float* v) {
        __half2 hv[4];
#pragma unroll
        for (int j = 0; j < 4; j++)
            hv[j] = __floats2half2_rn(v[2 * j], v[2 * j + 1]);
        *(uint4*)(wprev + off) = *(const uint4*)hv;
    };
    auto load8 = [&](long off, float* v) {
        uint4 raw = *(const uint4*)(s + off);
        const __half2* h2 = (const __half2*)&raw;
#pragma unroll
        for (int j = 0; j < 4; j++) {
            float2 f = __half22float2(h2[j]);
            v[2 * j] = f.x; v[2 * j + 1] = f.y;
        }
    };

    store8((long)(bh * NC) * SZ + e8, w);
    float sv[8];
    load8((long)(bh * NC) * SZ + e8, sv);
    for (int t = 0; t < NC; t++) {
        float nx[8];
        if (t + 1 < NC) load8((long)(bh * NC + t + 1) * SZ + e8, nx);
        float beta  = g_beta[(b * NC + t) * NH + h];
        float alpha = g_alpha[(b * NC + t) * NH + h];
#pragma unroll
        for (int j = 0; j < 8; j++) {
            m[j] = beta * m[j] + sv[j];
            w[j] = alpha * w[j] + m[j];
        }
        if (t < NC - 1) {
            store8((long)(bh * NC + t + 1) * SZ + e8, w);
#pragma unroll
            for (int j = 0; j < 8; j++) sv[j] = nx[j];
        }
    }
}

// ---------------- small scan for s_g -> Gp ----------------
__global__ void scan_kernel(const float* __restrict__ s, const float* __restrict__ init,
                            float* __restrict__ wprev, int sz) {
    int bh = blockIdx.y;
    int e = blockIdx.x * 256 + threadIdx.x;
    if (e >= sz) return;
    int b = bh / NH, h = bh % NH;
    float m = 0.f, w = init[e];
    wprev[(long)(bh * NC) * sz + e] = rndf(w);
    for (int t = 0; t < NC; t++) {
        float beta  = g_beta[(b * NC + t) * NH + h];
        float alpha = g_alpha[(b * NC + t) * NH + h];
        m = beta * m + s[(long)(bh * NC + t) * sz + e];
        w = alpha * w + m;
        if (t < NC - 1) wprev[(long)(bh * NC + t + 1) * sz + e] = rndf(w);
    }
}

// ======= fp16 tensor-core GEMM (m16n8k16), BMx128 tile, cp.async + ldmatrix =======
// EPI: 0 plain fp32 C, 1 fused QKV -> half KVQ (z=0 also K-rmsnorm -> Hs, rsK),
//      2 A1(half)+gelu->half, 3 pred->dY half, 4 *gelu'(A1 half)->half, 6 gelu->half,
//      7 gated retrieval ->half x3, 8 negate->half C, 9 fused dH->s_g reduction (fp32 C)
// TA: C = op(A^T B), A stored [K][M] half
// h0: aux half (EPI1: xr; EPI3/7/9: KVQ base; EPI4: A1); f1: EPI1 memg
// f2: EPI1 rsK (cast), EPI3 lr;  x3: EPI1 Hs, EPI2 A1, EPI7 R
template <int BM, int EPI, bool TA>
__global__ void __launch_bounds__(256, 2) gmma(
    const __half* __restrict__ A, const __half* __restrict__ Bm, void* __restrict__ Cv,
    int K, int lda, int ldb, int ldc,
    long sA, long sB, long sC,
    const float* __restrict__ f1, const float* __restrict__ f2,
    void* __restrict__ x3, const __half* __restrict__ h0) {
    constexpr int STG = 3;
    constexpr int WM  = BM / 2;
    constexpr int MA  = WM / 16;
    constexpr int ASZ = TA ? 16 * 136 : BM * 24;
    constexpr int BSZ = 16 * 136;

    int z = blockIdx.z;
    float* C = (float*)Cv;
    __half* Ch = (__half*)Cv;
    if (EPI == 1) {
        if (z == 2) A = h0;
        Bm += (long)z * DIM * DIM;
        Ch += (long)z * RWSDH;
    } else {
        A += (long)z * sA;
        Bm += (long)z * sB;
        if (EPI == 0 || EPI == 9) C += (long)z * sC;
        else Ch += (long)z * sC;
    }

    extern __shared__ char smraw[];
    __half* Asm = (__half*)smraw;
    __half* Bsm = Asm + STG * ASZ;
    __shared__ float sgacc[128];

    int tid = threadIdx.x;
    int warp = tid >> 5, lane = tid & 31;
    int g = lane >> 2, tg = lane & 3;
    int wr = warp >> 2, wc = warp & 3;
    int m0 = blockIdx.y * BM, n0 = blockIdx.x * 128;

    float acc[MA][4][4];
#pragma unroll
    for (int i = 0; i < MA; i++)
#pragma unroll
        for (int j = 0; j < 4; j++)
#pragma unroll
            for (int l = 0; l < 4; l++) acc[i][j][l] = 0.f;

    auto issue = [&](int st, int kb) {
        __half* as = Asm + st * ASZ;
        __half* bs = Bsm + st * BSZ;
        if (!TA) {
            if (BM == 128 || tid < 128) {
                int m = tid >> 1, kh = (tid & 1) * 8;
                cpa16(&as[m * 24 + kh], A + (long)(m0 + m) * lda + kb + kh);
            }
        } else {
            int k = tid >> 4, m8 = (tid & 15) * 8;
            cpa16(&as[k * 136 + m8], A + (long)(kb + k) * lda + m0 + m8);
        }
        {
            int k = tid >> 4, n8 = (tid & 15) * 8;
            cpa16(&bs[k * 136 + n8], Bm + (long)(kb + k) * ldb + n0 + n8);
        }
    };

    if (EPI == 9 || (EPI == 1 && z == 0)) {
        if (tid < 128) sgacc[tid] = 0.f;
    }

    int nT = K >> 4;
#pragma unroll
    for (int s = 0; s < STG - 1; s++) {
        if (s < nT) issue(s, s << 4);
        CP_COMMIT();
    }

    for (int t = 0; t < nT; t++) {
        CP_WAIT1();
        __syncthreads();
        int nx = t + STG - 1;
        if (nx < nT) issue(nx % STG, nx << 4);
        CP_COMMIT();

        const __half* as = Asm + (t % STG) * ASZ;
        const __half* bs = Bsm + (t % STG) * BSZ;
        unsigned asb = (unsigned)__cvta_generic_to_shared(as);
        unsigned bsb = (unsigned)__cvta_generic_to_shared(bs);

        unsigned af[MA][4], bf[4][2];
        if (!TA) {
            int arow = lane & 15, ak = (lane >> 4) * 8;
#pragma unroll
            for (int ma = 0; ma < MA; ma++) {
                unsigned addr = asb + 2u * (unsigned)((wr * WM + ma * 16 + arow) * 24 + ak);
                ldsm4(af[ma][0], af[ma][1], af[ma][2], af[ma][3], addr);
            }
        } else {
            int krow = (lane & 7) + (lane >> 4) * 8;
            int moff = ((lane >> 3) & 1) * 8;
#pragma unroll
            for (int ma = 0; ma < MA; ma++) {
                int R = wr * WM + ma * 16;
                unsigned addr = asb + 2u * (unsigned)(krow * 136 + R + moff);
                ldsm4t(af[ma][0], af[ma][1], af[ma][2], af[ma][3], addr);
            }
        }
        {
            int krow = lane & 15;
            int nhi = (lane >> 4) * 8;
#pragma unroll
            for (int h = 0; h < 2; h++) {
                unsigned r0, r1, r2, r3;
                unsigned addr = bsb + 2u * (unsigned)(krow * 136 + wc * 32 + h * 16 + nhi);
                ldsm4t(r0, r1, r2, r3, addr);
                bf[2 * h][0] = r0; bf[2 * h][1] = r1;
                bf[2 * h + 1][0] = r2; bf[2 * h + 1][1] = r3;
            }
        }
#pragma unroll
        for (int na = 0; na < 4; na++)
#pragma unroll
            for (int ma = 0; ma < MA; ma++)
                mma16(acc[ma][na], af[ma], bf[na][0], bf[na][1]);
    }

    if (EPI == 9) {
#pragma unroll
        for (int na = 0; na < 4; na++) {
#pragma unroll
            for (int hf = 0; hf < 2; hf++) {
                int c = n0 + wc * 32 + na * 8 + tg * 2 + hf;
                float csum = 0.f;
#pragma unroll
                for (int ma = 0; ma < MA; ma++)
#pragma unroll
                    for (int ih = 0; ih < 2; ih++) {
                        int i = ih * 2 + hf;
                        int r = m0 + wr * WM + ma * 16 + g + ih * 8;
                        csum += acc[ma][na][i] * __half2float(h0[(long)r * DH + c]) * f1[r];
                    }
                for (int o = 16; o >= 4; o >>= 1)
                    csum += __shfl_down_sync(0xffffffffu, csum, o);
                if (g == 0) atomicAdd(&sgacc[wc * 32 + na * 8 + tg * 2 + hf], csum);
            }
        }
        __syncthreads();
        if (tid < 128) C[(long)blockIdx.y * DH + tid] = -sgacc[tid];
        return;
    }

    if (EPI == 1 && z == 0) {
        // K projection + fused per-(token,head) rmsnorm: this block's 128 columns
        // are exactly one head's DH dims; each tile row is one rmsnorm group.
        __syncthreads();   // sgacc zeros visible
#pragma unroll
        for (int ma = 0; ma < MA; ma++)
#pragma unroll
            for (int p = 0; p < 2; p++) {
                float ss = 0.f;
#pragma unroll
                for (int na = 0; na < 4; na++) {
                    float v0 = acc[ma][na][p * 2 + 0];
                    float v1 = acc[ma][na][p * 2 + 1];
                    ss += v0 * v0 + v1 * v1;
                }
                ss += __shfl_xor_sync(0xffffffffu, ss, 1);
                ss += __shfl_xor_sync(0xffffffffu, ss, 2);
                if (tg == 0) atomicAdd(&sgacc[wr * WM + ma * 16 + g + p * 8], ss);
            }
        __syncthreads();
        float* rsKp = (float*)f2;
#pragma unroll
        for (int ma = 0; ma < MA; ma++)
#pragma unroll
            for (int p = 0; p < 2; p++) {
                int rloc = wr * WM + ma * 16 + g + p * 8;
                float rs = rsqrtf(sgacc[rloc] * (1.0f / DH) + 1e-6f);
                int t = m0 + rloc;
                int b = t / SEQN, n = t % SEQN, h = n0 >> 7;
                long base = ((long)(b * NH + h) * SEQN + n) * DH;
                if (wc == 0 && tg == 0) rsKp[(long)(b * NH + h) * SEQN + n] = rs;
#pragma unroll
                for (int na = 0; na < 4; na++) {
                    int c = wc * 32 + na * 8 + tg * 2;    // d within head
                    float v0 = acc[ma][na][p * 2 + 0];
                    float v1 = acc[ma][na][p * 2 + 1];
                    *(__half2*)&Ch[base + c] = __floats2half2_rn(v0, v1);
                    *(__half2*)&((__half*)x3)[base + c] =
                        __floats2half2_rn(v0 * rs * f1[c], v1 * rs * f1[c + 1]);
                }
            }
        return;
    }

    // vectorized epilogue: pairs (i=0,1)@row r and (i=2,3)@row r+8, c..c+1
#pragma unroll
    for (int ma = 0; ma < MA; ma++) {
#pragma unroll
        for (int na = 0; na < 4; na++) {
#pragma unroll
            for (int p = 0; p < 2; p++) {
                int r = m0 + wr * WM + ma * 16 + g + p * 8;
                int c = n0 + wc * 32 + na * 8 + tg * 2;
                float v0 = acc[ma][na][p * 2 + 0];
                float v1 = acc[ma][na][p * 2 + 1];
                if (EPI == 0) {
                    *(float2*)&C[(long)r * ldc + c] = make_float2(v0, v1);
                } else if (EPI == 8) {
                    *(__half2*)&Ch[(long)r * ldc + c] = __floats2half2_rn(-v0, -v1);
                } else if (EPI == 1) {
                    int b = r / SEQN, n = r % SEQN, h = c / DH, d = c % DH;
                    *(__half2*)&Ch[(long)(((b * NH + h) * SEQN) + n) * DH + d] =
                        __floats2half2_rn(v0, v1);
                } else if (EPI == 2) {
                    *(__half2*)&((__half*)x3)[(long)r * ldc + c] = __floats2half2_rn(v0, v1);
                    *(__half2*)&Ch[(long)r * ldc + c] =
                        __floats2half2_rn(gelu_f(v0), gelu_f(v1));
                } else if (EPI == 3) {
                    float2 kk = __half22float2(*(const __half2*)&h0[(long)r * DH + c]);
                    float2 vv = __half22float2(*(const __half2*)&h0[RWSDH + (long)r * DH + c]);
                    int bh = r / SEQN, n = r % SEQN;
                    int b = bh / NH, h = bh % NH;
                    float lr = f2[(b * SEQN + n) * NH + h];
                    float s = (2.0f / DH) * lr;
                    *(__half2*)&Ch[(long)r * DH + c] =
                        __floats2half2_rn(s * (v0 + kk.x - vv.x), s * (v1 + kk.y - vv.y));
                } else if (EPI == 4) {
                    float2 a1 = __half22float2(*(const __half2*)&h0[(long)r * ldc + c]);
                    *(__half2*)&Ch[(long)r * ldc + c] =
                        __floats2half2_rn(v0 * gelup_f(a1.x), v1 * gelup_f(a1.y));
                } else if (EPI == 6) {
                    *(__half2*)&Ch[(long)r * ldc + c] =
                        __floats2half2_rn(gelu_f(v0), gelu_f(v1));
                } else if (EPI == 7) {
                    float2 qq = __half22float2(
                        *(const __half2*)&h0[2 * RWSDH + (long)z * CH * DH + (long)r * DH + c]);
                    int bh = z / NC, cc = z % NC;
                    int n = cc * CH + r;
                    int b = bh / NH, h = bh % NH;
                    float gate = f1[(b * SEQN + n) * NH + h];
                    *(__half2*)&((__half*)x3)[(long)(b * SEQN + n) * DIM + h * DH + c] =
                        __floats2half2_rn((v0 + qq.x) * gate, (v1 + qq.y) * gate);
                }
            }
        }
    }
}

constexpr int smem_bytes(int BM, bool TA) {
    return 3 * ((TA ? 16 * 136 : BM * 24) + 16 * 136) * 2;
}

// ---------------- launch ----------------
extern "C" void kernel_launch(void* const* d_in, const int* in_sizes, int n_in,
                              void* d_out, int out_size) {
    const float* seq   = (const float*)d_in[0];
    const float* gsto  = (const float*)d_in[1];
    const float* gret  = (const float*)d_in[2];
    const float* Wq    = (const float*)d_in[3];
    const float* Wk    = (const float*)d_in[4];
    const float* Wv    = (const float*)d_in[5];
    const float* Wa    = (const float*)d_in[6];
    const float* ba    = (const float*)d_in[7];
    const float* Wm    = (const float*)d_in[8];
    const float* Wd    = (const float*)d_in[9];
    const float* bd    = (const float*)d_in[10];
    const float* Wg    = (const float*)d_in[11];
    const float* Wc    = (const float*)d_in[12];
    const float* memg  = (const float*)d_in[13];
    const float* w1    = (const float*)d_in[14];
    const float* w2    = (const float*)d_in[15];
    float* out = (float*)d_out;

    float *p_lr, *p_gate, *p_rsK, *p_sg, *p_Gp;
    __half *p_xsh, *p_xrh, *p_KVQh, *p_Hsh, *p_A1h, *p_GAh, *p_dA1h, *p_dYh,
           *p_Hqh, *p_Rh, *p_sw1h, *p_sw2h, *p_Wp1h, *p_Wp2h, *p_w1Th, *p_w2Th,
           *p_Wrh, *p_Wcrh, *p_w1rh, *p_w2rh;
    cudaGetSymbolAddress((void**)&p_xsh, g_xsh);
    cudaGetSymbolAddress((void**)&p_xrh, g_xrh);
    cudaGetSymbolAddress((void**)&p_KVQh, g_KVQh);
    cudaGetSymbolAddress((void**)&p_lr, g_lr);
    cudaGetSymbolAddress((void**)&p_gate, g_gate);
    cudaGetSymbolAddress((void**)&p_Hsh, g_Hsh);
    cudaGetSymbolAddress((void**)&p_rsK, g_rsK);
    cudaGetSymbolAddress((void**)&p_A1h, g_A1h);
    cudaGetSymbolAddress((void**)&p_GAh, g_GAh);
    cudaGetSymbolAddress((void**)&p_dA1h, g_dA1h);
    cudaGetSymbolAddress((void**)&p_dYh, g_dYh);
    cudaGetSymbolAddress((void**)&p_sw1h, g_sw1h);
    cudaGetSymbolAddress((void**)&p_sw2h, g_sw2h);
    cudaGetSymbolAddress((void**)&p_sg, g_sg);
    cudaGetSymbolAddress((void**)&p_Wp1h, g_Wp1h);
    cudaGetSymbolAddress((void**)&p_Wp2h, g_Wp2h);
    cudaGetSymbolAddress((void**)&p_Gp, g_Gp);
    cudaGetSymbolAddress((void**)&p_Hqh, g_Hqh);
    cudaGetSymbolAddress((void**)&p_Rh, g_Rh);
    cudaGetSymbolAddress((void**)&p_w1Th, g_w1Th);
    cudaGetSymbolAddress((void**)&p_w2Th, g_w2Th);
    cudaGetSymbolAddress((void**)&p_Wrh, g_Wrh);
    cudaGetSymbolAddress((void**)&p_Wcrh, g_Wcrh);
    cudaGetSymbolAddress((void**)&p_w1rh, g_w1rh);
    cudaGetSymbolAddress((void**)&p_w2rh, g_w2rh);

    constexpr int S128  = smem_bytes(128, false);
    constexpr int S128T = smem_bytes(128, true);
    constexpr int S64   = smem_bytes(64, false);
    cudaFuncSetAttribute(gmma<128, 1, false>, cudaFuncAttributeMaxDynamicSharedMemorySize, S128);
    cudaFuncSetAttribute(gmma<128, 2, false>, cudaFuncAttributeMaxDynamicSharedMemorySize, S128);
    cudaFuncSetAttribute(gmma<64, 3, false>,  cudaFuncAttributeMaxDynamicSharedMemorySize, S64);
    cudaFuncSetAttribute(gmma<128, 4, false>, cudaFuncAttributeMaxDynamicSharedMemorySize, S128);
    cudaFuncSetAttribute(gmma<64, 9, false>,  cudaFuncAttributeMaxDynamicSharedMemorySize, S64);
    cudaFuncSetAttribute(gmma<64, 0, false>,  cudaFuncAttributeMaxDynamicSharedMemorySize, S64);
    cudaFuncSetAttribute(gmma<128, 8, true>,  cudaFuncAttributeMaxDynamicSharedMemorySize, S128T);
    cudaFuncSetAttribute(gmma<64, 6, false>,  cudaFuncAttributeMaxDynamicSharedMemorySize, S64);
    cudaFuncSetAttribute(gmma<64, 7, false>,  cudaFuncAttributeMaxDynamicSharedMemorySize, S64);

    // 0) fp16 weight copies + transposes
    prep_kernel<<<dim3(1024, 8), 256>>>(Wk, Wv, Wq, Wc, w1, w2);

    // 1) rmsnorm of seq -> xs, xr (half) + fused lr/gate
    rmsseq_kernel<<<TOK, 256>>>(seq, gsto, gret, Wa, ba, Wg);

    // 2) fused QKV projections -> head-major K|V|Q (half); z=0 also Hs + rsK
    gmma<128, 1, false><<<dim3(4, 32, 3), 256, S128>>>(p_xsh, p_Wrh, p_KVQh,
        DIM, DIM, DIM, 0, 0, 0, 0, memg, p_rsK, p_Hsh, p_xrh);

    // 4) beta, alpha
    pool1_kernel<<<dim3(Bb * NC, 8), 512>>>();
    pool2_kernel<<<Bb * NC, 512>>>(Wm, Wd, bd);

    // 7) A1(half) = Hs @ w1 ; GA = gelu(A1) (half)
    gmma<128, 2, false><<<dim3(4, 128), 256, S128>>>(p_Hsh, p_w1rh, p_GAh,
        DH, DH, DHID, DHID, 0, 0, 0, nullptr, nullptr, p_A1h, nullptr);
    // 8) pred = GA @ w2 + K -> dY (half)
    gmma<64, 3, false><<<dim3(1, 256), 256, S64>>>(p_GAh, p_w2rh, p_dYh,
        DHID, DHID, DH, DH, 0, 0, 0, nullptr, p_lr, nullptr, p_KVQh);
    // 9) dA1 = (dY @ w2^T) * gelu'(A1) (half)
    gmma<128, 4, false><<<dim3(4, 128), 256, S128>>>(p_dYh, p_w2Th, p_dA1h,
        DH, DH, DHID, DHID, 0, 0, 0, nullptr, nullptr, nullptr, p_A1h);
    // 10+13) s_g = -colsum(dH * K * rsK) fused into dH GEMM
    gmma<64, 9, false><<<dim3(1, 256), 256, S64>>>(p_dA1h, p_w1Th, p_sg,
        DHID, DHID, DH, DH, 0, 0, 0, p_rsK, nullptr, nullptr, p_KVQh);

    // 11) sW1[z] = -Hs_z^T @ dA1_z (half)
    gmma<128, 8, true><<<dim3(4, 1, NCHUNK), 256, S128T>>>(p_Hsh, p_dA1h, p_sw1h,
        CH, DH, DHID, DHID,
        (long)CH * DH, (long)CH * DHID, (long)DH * DHID, nullptr, nullptr, nullptr, nullptr);
    // 12) sW2[z] = -GA_z^T @ dY_z (half)
    gmma<128, 8, true><<<dim3(1, 4, NCHUNK), 256, S128T>>>(p_GAh, p_dYh, p_sw2h,
        CH, DHID, DH, DH,
        (long)CH * DHID, (long)CH * DH, (long)DHID * DH, nullptr, nullptr, nullptr, nullptr);

    // 14) scans -> causal w_prev (half) + Gp
    scanh_kernel<<<dim3(32, BH, 2), 256>>>(p_sw1h, w1, p_Wp1h, p_sw2h, w2, p_Wp2h);
    scan_kernel<<<dim3(1, BH), 256>>>(p_sg, memg, p_Gp, DH);

    // 15) Hq = rmsnorm(Q, Gp[chunk]) (half), 4 rows/block
    hq_kernel<<<RWS / 4, 512>>>();

    // 16) retrieval GEMM1: GAq = gelu(Hq @ Wp1[z]) (half)
    gmma<64, 6, false><<<dim3(4, 1, NCHUNK), 256, S64>>>(p_Hqh, p_Wp1h, p_GAh,
        DH, DH, DHID, DHID,
        (long)CH * DH, (long)DH * DHID, (long)CH * DHID, nullptr, nullptr, nullptr, nullptr);
    // 17) retrieval GEMM2: y = (GAq @ Wp2[z] + q) * gate -> R (half)
    gmma<64, 7, false><<<dim3(1, 1, NCHUNK), 256, S64>>>(p_GAh, p_Wp2h, nullptr,
        DHID, DHID, DH, DH,
        (long)CH * DHID, (long)DHID * DH, 0, p_gate, nullptr, p_Rh, p_KVQh);
    // 18) out = R @ Wc (fp32 out)
    gmma<64, 0, false><<<dim3(4, 64), 256, S64>>>(p_Rh, p_Wcrh, out,
        DIM, DIM, DIM, DIM, 0, 0, 0, nullptr, nullptr, nullptr, nullptr);
}